// round 1
// baseline (speedup 1.0000x reference)
#include <cuda_runtime.h>
#include <math.h>

#define N_NODES 100000
#define E_EDGES 1600000
#define NFEAT   512
#define NHID    256
#define NCLASS  40
#define NLAYERS 10
#define ALPHA   0.1f

// Scratch (static device globals — allocation-free rule)
__device__ float g_h [N_NODES * NHID];    // 102.4 MB  relu(x@W1+b1)
__device__ float g_h2[N_NODES * NCLASS];  // 16 MB     h@W2+b2  (also z_0)
__device__ float g_za[N_NODES * NCLASS];  // 16 MB     ping
__device__ float g_zb[N_NODES * NCLASS];  // 16 MB     pong

// ---------------------------------------------------------------------------
// GEMM1: h = relu(x @ W1 + b1)   [100000,512] x [512,256]
// 128x128 tile, BK=16, 256 threads, 8x8 microtile
// ---------------------------------------------------------------------------
#define BM 128
#define BN 128
#define BK 16
#define TM 8
#define TN 8

__global__ void __launch_bounds__(256) gemm1_relu_kernel(
    const float* __restrict__ A,   // x [N,512]
    const float* __restrict__ B,   // W1 [512,256]
    const float* __restrict__ bias,
    float* __restrict__ C)         // g_h [N,256]
{
    __shared__ float As[BK][BM];
    __shared__ float Bs[BK][BN];

    const int tid = threadIdx.x;
    const int rowBase = blockIdx.x * BM;
    const int colBase = blockIdx.y * BN;

    const int tr = tid / 16;       // 0..15
    const int tc = tid % 16;       // 0..15

    float acc[TM][TN];
    #pragma unroll
    for (int i = 0; i < TM; i++)
        #pragma unroll
        for (int j = 0; j < TN; j++) acc[i][j] = 0.f;

    const int aRow0 = tid / 4;           // 0..63
    const int aCol  = (tid % 4) * 4;     // 0,4,8,12
    const int bRow0 = tid / 32;          // 0..7
    const int bCol  = (tid % 32) * 4;    // 0..124

    const float bval = bias[0];

    for (int k0 = 0; k0 < NFEAT; k0 += BK) {
        // A tile -> As[k][m]  (transposed store)
        #pragma unroll
        for (int s = 0; s < 2; s++) {
            int r = aRow0 + s * 64;
            int gr = rowBase + r;
            float4 v = make_float4(0.f, 0.f, 0.f, 0.f);
            if (gr < N_NODES)
                v = *(const float4*)(A + (size_t)gr * NFEAT + k0 + aCol);
            As[aCol + 0][r] = v.x;
            As[aCol + 1][r] = v.y;
            As[aCol + 2][r] = v.z;
            As[aCol + 3][r] = v.w;
        }
        // B tile -> Bs[k][n]
        #pragma unroll
        for (int s = 0; s < 2; s++) {
            int r = bRow0 + s * 8;
            float4 v = *(const float4*)(B + (size_t)(k0 + r) * NHID + colBase + bCol);
            *(float4*)&Bs[r][bCol] = v;
        }
        __syncthreads();

        #pragma unroll
        for (int k = 0; k < BK; k++) {
            float rm[TM], rn[TN];
            #pragma unroll
            for (int i = 0; i < TM; i++) rm[i] = As[k][tr * TM + i];
            #pragma unroll
            for (int j = 0; j < TN; j++) rn[j] = Bs[k][tc * TN + j];
            #pragma unroll
            for (int i = 0; i < TM; i++)
                #pragma unroll
                for (int j = 0; j < TN; j++)
                    acc[i][j] += rm[i] * rn[j];
        }
        __syncthreads();
    }

    #pragma unroll
    for (int i = 0; i < TM; i++) {
        int gr = rowBase + tr * TM + i;
        if (gr >= N_NODES) continue;
        #pragma unroll
        for (int j = 0; j < TN; j += 4) {
            float4 v;
            v.x = fmaxf(acc[i][j + 0] + bval, 0.f);
            v.y = fmaxf(acc[i][j + 1] + bval, 0.f);
            v.z = fmaxf(acc[i][j + 2] + bval, 0.f);
            v.w = fmaxf(acc[i][j + 3] + bval, 0.f);
            *(float4*)(C + (size_t)gr * NHID + colBase + tc * TN + j) = v;
        }
    }
}

// ---------------------------------------------------------------------------
// GEMM2: h2 = h @ W2 + b2   [100000,256] x [256,40]
// 128-row tile, full 40 cols, BK=32, 256 threads, 4x5 microtile
// ---------------------------------------------------------------------------
__global__ void __launch_bounds__(256) gemm2_kernel(
    const float* __restrict__ A,   // g_h [N,256]
    const float* __restrict__ B,   // W2 [256,40]
    const float* __restrict__ bias,
    float* __restrict__ C)         // g_h2 [N,40]
{
    __shared__ float As[32][128];  // [k][row]
    __shared__ float Bs[32][40];

    const int tid = threadIdx.x;
    const int rowBase = blockIdx.x * 128;
    const int rg = tid / 8;    // 0..31 -> rows rg*4 .. rg*4+3
    const int cg = tid % 8;    // 0..7  -> cols cg*5 .. cg*5+4

    float acc[4][5];
    #pragma unroll
    for (int i = 0; i < 4; i++)
        #pragma unroll
        for (int j = 0; j < 5; j++) acc[i][j] = 0.f;

    const float bval = bias[0];

    for (int k0 = 0; k0 < NHID; k0 += 32) {
        // A tile: 128x32 = 1024 float4, 4 per thread (transposed store)
        #pragma unroll
        for (int s = 0; s < 4; s++) {
            int idx = tid + s * 256;
            int r = idx / 8;
            int c4 = (idx % 8) * 4;
            int gr = rowBase + r;
            float4 v = make_float4(0.f, 0.f, 0.f, 0.f);
            if (gr < N_NODES)
                v = *(const float4*)(A + (size_t)gr * NHID + k0 + c4);
            As[c4 + 0][r] = v.x;
            As[c4 + 1][r] = v.y;
            As[c4 + 2][r] = v.z;
            As[c4 + 3][r] = v.w;
        }
        // B tile: 32x40 = 1280 floats, 5 per thread
        #pragma unroll
        for (int s = 0; s < 5; s++) {
            int idx = tid + s * 256;
            int r = idx / 40, c = idx % 40;
            Bs[r][c] = B[(size_t)(k0 + r) * NCLASS + c];
        }
        __syncthreads();

        #pragma unroll
        for (int k = 0; k < 32; k++) {
            float rm[4], rn[5];
            #pragma unroll
            for (int i = 0; i < 4; i++) rm[i] = As[k][rg * 4 + i];
            #pragma unroll
            for (int j = 0; j < 5; j++) rn[j] = Bs[k][cg * 5 + j];
            #pragma unroll
            for (int i = 0; i < 4; i++)
                #pragma unroll
                for (int j = 0; j < 5; j++)
                    acc[i][j] += rm[i] * rn[j];
        }
        __syncthreads();
    }

    #pragma unroll
    for (int i = 0; i < 4; i++) {
        int gr = rowBase + rg * 4 + i;
        if (gr >= N_NODES) continue;
        #pragma unroll
        for (int j = 0; j < 5; j++)
            C[(size_t)gr * NCLASS + cg * 5 + j] = acc[i][j] + bval;
    }
}

// ---------------------------------------------------------------------------
// znew = ALPHA * h2  (per-iteration init)
// ---------------------------------------------------------------------------
__global__ void scale_init_kernel(const float* __restrict__ h2,
                                  float* __restrict__ znew, int n4)
{
    int i = blockIdx.x * blockDim.x + threadIdx.x;
    if (i < n4) {
        float4 v = ((const float4*)h2)[i];
        v.x *= ALPHA; v.y *= ALPHA; v.z *= ALPHA; v.w *= ALPHA;
        ((float4*)znew)[i] = v;
    }
}

// ---------------------------------------------------------------------------
// Edge scatter: znew[row] += 0.9 * vals * z[col]   (one thread per edge,
// 10x float4 vector reductions per edge)
// ---------------------------------------------------------------------------
__global__ void __launch_bounds__(256) spmm_edges_kernel(
    const int* __restrict__ row, const int* __restrict__ col,
    const float* __restrict__ vals,
    const float* __restrict__ z, float* __restrict__ znew)
{
    int e = blockIdx.x * blockDim.x + threadIdx.x;
    if (e >= E_EDGES) return;
    int r = row[e];
    int c = col[e];
    float v = (1.0f - ALPHA) * vals[e];

    const float4* zp = (const float4*)(z + (size_t)c * NCLASS);
    float4* op = (float4*)(znew + (size_t)r * NCLASS);

    #pragma unroll
    for (int t = 0; t < NCLASS / 4; t++) {
        float4 a = zp[t];
        a.x *= v; a.y *= v; a.z *= v; a.w *= v;
        asm volatile("red.global.add.v4.f32 [%0], {%1,%2,%3,%4};"
                     :: "l"(op + t), "f"(a.x), "f"(a.y), "f"(a.z), "f"(a.w)
                     : "memory");
    }
}

// ---------------------------------------------------------------------------
// Row-wise log_softmax over 40 classes: one warp per row
// ---------------------------------------------------------------------------
__global__ void logsoftmax_kernel(const float* __restrict__ z,
                                  float* __restrict__ out)
{
    int gtid = blockIdx.x * blockDim.x + threadIdx.x;
    int warp = gtid / 32;
    int lane = gtid % 32;
    if (warp >= N_NODES) return;

    const float* zr = z + (size_t)warp * NCLASS;
    float v0 = zr[lane];                                  // lane 0..31 < 40
    float v1 = (lane < NCLASS - 32) ? zr[lane + 32] : -INFINITY;

    float m = fmaxf(v0, v1);
    #pragma unroll
    for (int o = 16; o > 0; o >>= 1)
        m = fmaxf(m, __shfl_xor_sync(0xFFFFFFFFu, m, o));

    float s = expf(v0 - m) + ((lane < NCLASS - 32) ? expf(v1 - m) : 0.f);
    #pragma unroll
    for (int o = 16; o > 0; o >>= 1)
        s += __shfl_xor_sync(0xFFFFFFFFu, s, o);

    float L = m + logf(s);
    out[(size_t)warp * NCLASS + lane] = v0 - L;
    if (lane < NCLASS - 32)
        out[(size_t)warp * NCLASS + lane + 32] = v1 - L;
}

// ---------------------------------------------------------------------------
extern "C" void kernel_launch(void* const* d_in, const int* in_sizes, int n_in,
                              void* d_out, int out_size)
{
    const float* x    = (const float*)d_in[0];
    const int*   row  = (const int*)  d_in[1];
    const int*   col  = (const int*)  d_in[2];
    const float* vals = (const float*)d_in[3];
    const float* W1   = (const float*)d_in[4];
    const float* b1   = (const float*)d_in[5];
    const float* W2   = (const float*)d_in[6];
    const float* b2   = (const float*)d_in[7];
    float* out = (float*)d_out;

    float *h, *h2, *za, *zb;
    cudaGetSymbolAddress((void**)&h,  g_h);
    cudaGetSymbolAddress((void**)&h2, g_h2);
    cudaGetSymbolAddress((void**)&za, g_za);
    cudaGetSymbolAddress((void**)&zb, g_zb);

    // MLP
    dim3 g1((N_NODES + BM - 1) / BM, NHID / BN);
    gemm1_relu_kernel<<<g1, 256>>>(x, W1, b1, h);
    gemm2_kernel<<<(N_NODES + 127) / 128, 256>>>(h, W2, b2, h2);

    // APPNP propagation: z <- 0.9 * A z + 0.1 * h2, z_0 = h2
    const int n4 = N_NODES * NCLASS / 4;
    const float* zin = h2;
    float* bufs[2] = { za, zb };
    for (int it = 0; it < NLAYERS; it++) {
        float* zout = bufs[it & 1];
        scale_init_kernel<<<(n4 + 255) / 256, 256>>>(h2, zout, n4);
        spmm_edges_kernel<<<(E_EDGES + 255) / 256, 256>>>(row, col, vals, zin, zout);
        zin = zout;
    }

    // log_softmax -> output
    logsoftmax_kernel<<<(N_NODES * 32 + 255) / 256, 256>>>(zin, out);
}

// round 2
// speedup vs baseline: 1.2889x; 1.2889x over previous
#include <cuda_runtime.h>
#include <math.h>

#define N_NODES 100000
#define E_EDGES 1600000
#define NFEAT   512
#define NHID    256
#define NCLASS  40
#define NLAYERS 10
#define ALPHA   0.1f

#define SCAN_BLK 1024
#define NUM_SCAN_BLKS ((N_NODES + SCAN_BLK - 1) / SCAN_BLK)   // 98

// Scratch (static device globals — allocation-free rule)
__device__ float g_h [N_NODES * NHID];    // relu(x@W1+b1)
__device__ float g_h2[N_NODES * NCLASS];  // h@W2+b2  (z_0)
__device__ float g_za[N_NODES * NCLASS];
__device__ float g_zb[N_NODES * NCLASS];

// CSR build scratch
__device__ int  g_cnt   [N_NODES];
__device__ int  g_offl  [N_NODES];        // within-block exclusive scan
__device__ int  g_start [N_NODES + 1];
__device__ int  g_cursor[N_NODES];
__device__ int  g_blk   [NUM_SCAN_BLKS];
__device__ int  g_blkoff[NUM_SCAN_BLKS];
__device__ int2 g_edges [E_EDGES];        // .x = col, .y = bits of 0.9*val

// ---------------------------------------------------------------------------
// GEMM1: h = relu(x @ W1 + b1)   [100000,512] x [512,256]
// ---------------------------------------------------------------------------
#define BM 128
#define BN 128
#define BK 16
#define TM 8
#define TN 8

__global__ void __launch_bounds__(256) gemm1_relu_kernel(
    const float* __restrict__ A,
    const float* __restrict__ B,
    const float* __restrict__ bias,
    float* __restrict__ C)
{
    __shared__ float As[BK][BM];
    __shared__ float Bs[BK][BN];

    const int tid = threadIdx.x;
    const int rowBase = blockIdx.x * BM;
    const int colBase = blockIdx.y * BN;
    const int tr = tid / 16;
    const int tc = tid % 16;

    float acc[TM][TN];
    #pragma unroll
    for (int i = 0; i < TM; i++)
        #pragma unroll
        for (int j = 0; j < TN; j++) acc[i][j] = 0.f;

    const int aRow0 = tid / 4;
    const int aCol  = (tid % 4) * 4;
    const int bRow0 = tid / 32;
    const int bCol  = (tid % 32) * 4;
    const float bval = bias[0];

    for (int k0 = 0; k0 < NFEAT; k0 += BK) {
        #pragma unroll
        for (int s = 0; s < 2; s++) {
            int r = aRow0 + s * 64;
            int gr = rowBase + r;
            float4 v = make_float4(0.f, 0.f, 0.f, 0.f);
            if (gr < N_NODES)
                v = *(const float4*)(A + (size_t)gr * NFEAT + k0 + aCol);
            As[aCol + 0][r] = v.x;
            As[aCol + 1][r] = v.y;
            As[aCol + 2][r] = v.z;
            As[aCol + 3][r] = v.w;
        }
        #pragma unroll
        for (int s = 0; s < 2; s++) {
            int r = bRow0 + s * 8;
            float4 v = *(const float4*)(B + (size_t)(k0 + r) * NHID + colBase + bCol);
            *(float4*)&Bs[r][bCol] = v;
        }
        __syncthreads();

        #pragma unroll
        for (int k = 0; k < BK; k++) {
            float rm[TM], rn[TN];
            #pragma unroll
            for (int i = 0; i < TM; i++) rm[i] = As[k][tr * TM + i];
            #pragma unroll
            for (int j = 0; j < TN; j++) rn[j] = Bs[k][tc * TN + j];
            #pragma unroll
            for (int i = 0; i < TM; i++)
                #pragma unroll
                for (int j = 0; j < TN; j++)
                    acc[i][j] += rm[i] * rn[j];
        }
        __syncthreads();
    }

    #pragma unroll
    for (int i = 0; i < TM; i++) {
        int gr = rowBase + tr * TM + i;
        if (gr >= N_NODES) continue;
        #pragma unroll
        for (int j = 0; j < TN; j += 4) {
            float4 v;
            v.x = fmaxf(acc[i][j + 0] + bval, 0.f);
            v.y = fmaxf(acc[i][j + 1] + bval, 0.f);
            v.z = fmaxf(acc[i][j + 2] + bval, 0.f);
            v.w = fmaxf(acc[i][j + 3] + bval, 0.f);
            *(float4*)(C + (size_t)gr * NHID + colBase + tc * TN + j) = v;
        }
    }
}

// ---------------------------------------------------------------------------
// GEMM2: h2 = h @ W2 + b2   [100000,256] x [256,40]
// ---------------------------------------------------------------------------
__global__ void __launch_bounds__(256) gemm2_kernel(
    const float* __restrict__ A,
    const float* __restrict__ B,
    const float* __restrict__ bias,
    float* __restrict__ C)
{
    __shared__ float As[32][128];
    __shared__ float Bs[32][40];

    const int tid = threadIdx.x;
    const int rowBase = blockIdx.x * 128;
    const int rg = tid / 8;
    const int cg = tid % 8;

    float acc[4][5];
    #pragma unroll
    for (int i = 0; i < 4; i++)
        #pragma unroll
        for (int j = 0; j < 5; j++) acc[i][j] = 0.f;

    const float bval = bias[0];

    for (int k0 = 0; k0 < NHID; k0 += 32) {
        #pragma unroll
        for (int s = 0; s < 4; s++) {
            int idx = tid + s * 256;
            int r = idx / 8;
            int c4 = (idx % 8) * 4;
            int gr = rowBase + r;
            float4 v = make_float4(0.f, 0.f, 0.f, 0.f);
            if (gr < N_NODES)
                v = *(const float4*)(A + (size_t)gr * NHID + k0 + c4);
            As[c4 + 0][r] = v.x;
            As[c4 + 1][r] = v.y;
            As[c4 + 2][r] = v.z;
            As[c4 + 3][r] = v.w;
        }
        #pragma unroll
        for (int s = 0; s < 5; s++) {
            int idx = tid + s * 256;
            int r = idx / 40, c = idx % 40;
            Bs[r][c] = B[(size_t)(k0 + r) * NCLASS + c];
        }
        __syncthreads();

        #pragma unroll
        for (int k = 0; k < 32; k++) {
            float rm[4], rn[5];
            #pragma unroll
            for (int i = 0; i < 4; i++) rm[i] = As[k][rg * 4 + i];
            #pragma unroll
            for (int j = 0; j < 5; j++) rn[j] = Bs[k][cg * 5 + j];
            #pragma unroll
            for (int i = 0; i < 4; i++)
                #pragma unroll
                for (int j = 0; j < 5; j++)
                    acc[i][j] += rm[i] * rn[j];
        }
        __syncthreads();
    }

    #pragma unroll
    for (int i = 0; i < 4; i++) {
        int gr = rowBase + rg * 4 + i;
        if (gr >= N_NODES) continue;
        #pragma unroll
        for (int j = 0; j < 5; j++)
            C[(size_t)gr * NCLASS + cg * 5 + j] = acc[i][j] + bval;
    }
}

// ---------------------------------------------------------------------------
// CSR build: histogram -> 2-level exclusive scan -> scatter
// ---------------------------------------------------------------------------
__global__ void zero_counts_kernel()
{
    int i = blockIdx.x * blockDim.x + threadIdx.x;
    if (i < N_NODES) g_cnt[i] = 0;
}

__global__ void histogram_kernel(const int* __restrict__ row)
{
    int e = blockIdx.x * blockDim.x + threadIdx.x;
    if (e < E_EDGES) atomicAdd(&g_cnt[row[e]], 1);
}

__global__ void __launch_bounds__(SCAN_BLK) scan1_kernel()
{
    __shared__ int s[SCAN_BLK];
    int gid = blockIdx.x * SCAN_BLK + threadIdx.x;
    int x = (gid < N_NODES) ? g_cnt[gid] : 0;
    s[threadIdx.x] = x;
    __syncthreads();
    #pragma unroll
    for (int d = 1; d < SCAN_BLK; d <<= 1) {
        int t = (threadIdx.x >= d) ? s[threadIdx.x - d] : 0;
        __syncthreads();
        s[threadIdx.x] += t;
        __syncthreads();
    }
    if (gid < N_NODES) g_offl[gid] = s[threadIdx.x] - x;
    if (threadIdx.x == SCAN_BLK - 1) g_blk[blockIdx.x] = s[SCAN_BLK - 1];
}

__global__ void scan2_kernel()
{
    __shared__ int s[128];
    int tid = threadIdx.x;
    int x = (tid < NUM_SCAN_BLKS) ? g_blk[tid] : 0;
    s[tid] = x;
    __syncthreads();
    #pragma unroll
    for (int d = 1; d < 128; d <<= 1) {
        int t = (tid >= d) ? s[tid - d] : 0;
        __syncthreads();
        s[tid] += t;
        __syncthreads();
    }
    if (tid < NUM_SCAN_BLKS) g_blkoff[tid] = s[tid] - x;
}

__global__ void scan3_kernel()
{
    int i = blockIdx.x * blockDim.x + threadIdx.x;
    if (i < N_NODES) {
        int st = g_offl[i] + g_blkoff[i / SCAN_BLK];
        g_start[i]  = st;
        g_cursor[i] = st;
    }
    if (i == 0) g_start[N_NODES] = E_EDGES;
}

__global__ void scatter_kernel(const int* __restrict__ row,
                               const int* __restrict__ col,
                               const float* __restrict__ vals)
{
    int e = blockIdx.x * blockDim.x + threadIdx.x;
    if (e >= E_EDGES) return;
    int r = row[e];
    int pos = atomicAdd(&g_cursor[r], 1);
    int2 ev;
    ev.x = col[e];
    ev.y = __float_as_int((1.0f - ALPHA) * vals[e]);
    g_edges[pos] = ev;
}

// ---------------------------------------------------------------------------
// Pull-mode SpMM + alpha blend: znew[r] = sum_e v*z[col] + ALPHA*h2[r]
// One thread per row; 40 fp32 accumulators; no atomics.
// ---------------------------------------------------------------------------
__global__ void __launch_bounds__(256) spmm_csr_kernel(
    const float* __restrict__ z,
    const float* __restrict__ h2,
    float* __restrict__ znew)
{
    int r = blockIdx.x * blockDim.x + threadIdx.x;
    if (r >= N_NODES) return;

    int e0 = g_start[r];
    int e1 = g_start[r + 1];

    float4 acc[NCLASS / 4];
    #pragma unroll
    for (int t = 0; t < NCLASS / 4; t++)
        acc[t] = make_float4(0.f, 0.f, 0.f, 0.f);

    for (int e = e0; e < e1; e++) {
        int2 ev = g_edges[e];
        int c = ev.x;
        float v = __int_as_float(ev.y);
        const float4* zp = (const float4*)(z + (size_t)c * NCLASS);
        #pragma unroll
        for (int t = 0; t < NCLASS / 4; t++) {
            float4 a = zp[t];
            acc[t].x += v * a.x;
            acc[t].y += v * a.y;
            acc[t].z += v * a.z;
            acc[t].w += v * a.w;
        }
    }

    const float4* hp = (const float4*)(h2 + (size_t)r * NCLASS);
    float4* op = (float4*)(znew + (size_t)r * NCLASS);
    #pragma unroll
    for (int t = 0; t < NCLASS / 4; t++) {
        float4 hv = hp[t];
        float4 o;
        o.x = acc[t].x + ALPHA * hv.x;
        o.y = acc[t].y + ALPHA * hv.y;
        o.z = acc[t].z + ALPHA * hv.z;
        o.w = acc[t].w + ALPHA * hv.w;
        op[t] = o;
    }
}

// ---------------------------------------------------------------------------
// Row-wise log_softmax over 40 classes: one warp per row
// ---------------------------------------------------------------------------
__global__ void logsoftmax_kernel(const float* __restrict__ z,
                                  float* __restrict__ out)
{
    int gtid = blockIdx.x * blockDim.x + threadIdx.x;
    int warp = gtid / 32;
    int lane = gtid % 32;
    if (warp >= N_NODES) return;

    const float* zr = z + (size_t)warp * NCLASS;
    float v0 = zr[lane];
    float v1 = (lane < NCLASS - 32) ? zr[lane + 32] : -INFINITY;

    float m = fmaxf(v0, v1);
    #pragma unroll
    for (int o = 16; o > 0; o >>= 1)
        m = fmaxf(m, __shfl_xor_sync(0xFFFFFFFFu, m, o));

    float s = expf(v0 - m) + ((lane < NCLASS - 32) ? expf(v1 - m) : 0.f);
    #pragma unroll
    for (int o = 16; o > 0; o >>= 1)
        s += __shfl_xor_sync(0xFFFFFFFFu, s, o);

    float L = m + logf(s);
    out[(size_t)warp * NCLASS + lane] = v0 - L;
    if (lane < NCLASS - 32)
        out[(size_t)warp * NCLASS + lane + 32] = v1 - L;
}

// ---------------------------------------------------------------------------
extern "C" void kernel_launch(void* const* d_in, const int* in_sizes, int n_in,
                              void* d_out, int out_size)
{
    const float* x    = (const float*)d_in[0];
    const int*   row  = (const int*)  d_in[1];
    const int*   col  = (const int*)  d_in[2];
    const float* vals = (const float*)d_in[3];
    const float* W1   = (const float*)d_in[4];
    const float* b1   = (const float*)d_in[5];
    const float* W2   = (const float*)d_in[6];
    const float* b2   = (const float*)d_in[7];
    float* out = (float*)d_out;

    float *h, *h2, *za, *zb;
    cudaGetSymbolAddress((void**)&h,  g_h);
    cudaGetSymbolAddress((void**)&h2, g_h2);
    cudaGetSymbolAddress((void**)&za, g_za);
    cudaGetSymbolAddress((void**)&zb, g_zb);

    // CSR build (atomic-free propagation afterwards)
    zero_counts_kernel<<<(N_NODES + 255) / 256, 256>>>();
    histogram_kernel<<<(E_EDGES + 255) / 256, 256>>>(row);
    scan1_kernel<<<NUM_SCAN_BLKS, SCAN_BLK>>>();
    scan2_kernel<<<1, 128>>>();
    scan3_kernel<<<(N_NODES + 255) / 256, 256>>>();
    scatter_kernel<<<(E_EDGES + 255) / 256, 256>>>(row, col, vals);

    // MLP
    dim3 g1((N_NODES + BM - 1) / BM, NHID / BN);
    gemm1_relu_kernel<<<g1, 256>>>(x, W1, b1, h);
    gemm2_kernel<<<(N_NODES + 127) / 128, 256>>>(h, W2, b2, h2);

    // APPNP propagation
    const float* zin = h2;
    float* bufs[2] = { za, zb };
    for (int it = 0; it < NLAYERS; it++) {
        float* zout = bufs[it & 1];
        spmm_csr_kernel<<<(N_NODES + 255) / 256, 256>>>(zin, h2, zout);
        zin = zout;
    }

    logsoftmax_kernel<<<(N_NODES * 32 + 255) / 256, 256>>>(zin, out);
}

// round 4
// speedup vs baseline: 1.6835x; 1.3061x over previous
#include <cuda_runtime.h>
#include <cuda_bf16.h>
#include <math.h>
#include <stdint.h>

#define N_NODES 100000
#define E_EDGES 1600000
#define NFEAT   512
#define NHID    256
#define NCLASS  40
#define NLAYERS 10
#define ALPHA   0.1f

#define SCAN_BLK 1024
#define NUM_SCAN_BLKS ((N_NODES + SCAN_BLK - 1) / SCAN_BLK)   // 98

// Scratch (static device globals — allocation-free rule)
__device__ float g_h [N_NODES * NHID];    // relu(x@W1+b1)
__device__ float g_h2[N_NODES * NCLASS];  // h@W2+b2  (z_0)
__device__ float g_za[N_NODES * NCLASS];
__device__ float g_zb[N_NODES * NCLASS];

// W1 transposed + bf16-split: [NHID][NFEAT]
__device__ __nv_bfloat16 g_w1t_hi[NHID * NFEAT];
__device__ __nv_bfloat16 g_w1t_lo[NHID * NFEAT];

// CSR build scratch
__device__ int  g_cnt   [N_NODES];
__device__ int  g_offl  [N_NODES];
__device__ int  g_start [N_NODES + 1];
__device__ int  g_cursor[N_NODES];
__device__ int  g_blk   [NUM_SCAN_BLKS];
__device__ int  g_blkoff[NUM_SCAN_BLKS];
__device__ int2 g_edges [E_EDGES];

// ===========================================================================
// helpers (baseline PTX only: ldmatrix / mma.sync / cp.async)
// ===========================================================================
__device__ __forceinline__ uint32_t smem_u32(const void* p) {
    uint32_t a;
    asm("{ .reg .u64 t; cvta.to.shared.u64 t, %1; cvt.u32.u64 %0, t; }"
        : "=r"(a) : "l"(p));
    return a;
}

__device__ __forceinline__ void ldsm4(uint32_t addr, uint32_t* r) {
    asm volatile("ldmatrix.sync.aligned.m8n8.x4.shared.b16 {%0,%1,%2,%3}, [%4];"
        : "=r"(r[0]), "=r"(r[1]), "=r"(r[2]), "=r"(r[3]) : "r"(addr));
}

__device__ __forceinline__ void mma16816(float* c, const uint32_t* a,
                                         uint32_t b0, uint32_t b1) {
    asm volatile(
        "mma.sync.aligned.m16n8k16.row.col.f32.bf16.bf16.f32 "
        "{%0,%1,%2,%3}, {%4,%5,%6,%7}, {%8,%9}, {%0,%1,%2,%3};"
        : "+f"(c[0]), "+f"(c[1]), "+f"(c[2]), "+f"(c[3])
        : "r"(a[0]), "r"(a[1]), "r"(a[2]), "r"(a[3]), "r"(b0), "r"(b1));
}

__device__ __forceinline__ void cpasync16(uint32_t saddr, const void* gptr) {
    asm volatile("cp.async.cg.shared.global [%0], [%1], 16;"
                 :: "r"(saddr), "l"(gptr) : "memory");
}
#define CP_COMMIT() asm volatile("cp.async.commit_group;" ::: "memory")
#define CP_WAIT0()  asm volatile("cp.async.wait_group 0;" ::: "memory")

__device__ __forceinline__ uint32_t sw128(uint32_t off) {
    return off ^ ((off >> 3) & 0x70);
}

// ===========================================================================
// Prep: W1T bf16 split  (w1t[n][k] = W1[k][n] split into hi/lo)
// ===========================================================================
__global__ void prep_w1t_kernel(const float* __restrict__ W1)
{
    int i = blockIdx.x * blockDim.x + threadIdx.x;
    if (i >= NHID * NFEAT) return;
    int n = i / NFEAT, k = i % NFEAT;
    float v = W1[(size_t)k * NHID + n];
    __nv_bfloat16 h = __float2bfloat16(v);
    g_w1t_hi[i] = h;
    g_w1t_lo[i] = __float2bfloat16(v - __bfloat162float(h));
}

// ===========================================================================
// GEMM1 (mma.sync HMMA): h = relu(x @ W1 + b1), bf16 2-split, fp32 acc
// CTA 128x128, 8 warps (4m x 2n), warp tile 32x64. K staged at 32, dbl buf.
// SMEM stage: A 128 rows x 128B [hi k32 | lo k32] = 16KB, B same = 16KB.
// ===========================================================================
#define G1_BM 128
#define G1_BN 128
#define G1_BK 32
#define G1_STAGES (NFEAT / G1_BK)      // 16
#define G1_A_OFF 0
#define G1_B_OFF 16384
#define G1_STAGE_BYTES 32768
#define G1_SMEM (2 * G1_STAGE_BYTES)   // 65536

__device__ __forceinline__ void split2p(float a, float b, uint32_t& hi, uint32_t& lo) {
    __nv_bfloat16 ah = __float2bfloat16(a);
    __nv_bfloat16 bh = __float2bfloat16(b);
    __nv_bfloat16 al = __float2bfloat16(a - __bfloat162float(ah));
    __nv_bfloat16 bl = __float2bfloat16(b - __bfloat162float(bh));
    hi = (uint32_t)__bfloat16_as_ushort(ah) | ((uint32_t)__bfloat16_as_ushort(bh) << 16);
    lo = (uint32_t)__bfloat16_as_ushort(al) | ((uint32_t)__bfloat16_as_ushort(bl) << 16);
}

__global__ void __launch_bounds__(256, 1) gemm1_mma_kernel(
    const float* __restrict__ A,
    const float* __restrict__ bias,
    float* __restrict__ C)
{
    extern __shared__ char smem[];
    const uint32_t sbase = smem_u32(smem);
    const int tid  = threadIdx.x;
    const int wid  = tid >> 5;
    const int lane = tid & 31;
    const int rowBase = blockIdx.x * G1_BM;
    const int colBase = blockIdx.y * G1_BN;

    const int warp_m = wid & 3;        // 0..3
    const int warp_n = wid >> 2;       // 0..1
    const int m0 = warp_m * 32;
    const int n0 = warp_n * 64;

    float acc[2][8][4];
    #pragma unroll
    for (int i = 0; i < 2; i++)
        #pragma unroll
        for (int j = 0; j < 8; j++)
            #pragma unroll
            for (int q = 0; q < 4; q++) acc[i][j][q] = 0.f;

    // per-thread global-load coords (A: 2 groups of 8 floats)
    const int agr[2] = { tid >> 2, (tid + 256) >> 2 };           // row 0..127
    const int akq    = tid & 3;                                   // k-octet
    // B: 2 groups (row n, k-octet), via cp.async
    const int bn[2]  = { tid >> 2, (tid + 256) >> 2 };
    const int bkq    = tid & 3;

    float a_st[16];

    // ---- stage loader pieces ----
    auto ldgA = [&](int k0) {
        #pragma unroll
        for (int it = 0; it < 2; it++) {
            int gr = rowBase + agr[it];
            if (gr < N_NODES) {
                const float* p = A + (size_t)gr * NFEAT + k0 + akq * 8;
                float4 v0 = *(const float4*)p;
                float4 v1 = *(const float4*)(p + 4);
                a_st[it*8+0]=v0.x; a_st[it*8+1]=v0.y; a_st[it*8+2]=v0.z; a_st[it*8+3]=v0.w;
                a_st[it*8+4]=v1.x; a_st[it*8+5]=v1.y; a_st[it*8+6]=v1.z; a_st[it*8+7]=v1.w;
            } else {
                #pragma unroll
                for (int q = 0; q < 8; q++) a_st[it*8+q] = 0.f;
            }
        }
    };
    auto cpB = [&](int k0, int stage) {
        uint32_t bb = sbase + stage * G1_STAGE_BYTES + G1_B_OFF;
        #pragma unroll
        for (int it = 0; it < 2; it++) {
            size_t gi = (size_t)(colBase + bn[it]) * NFEAT + k0 + bkq * 8;
            uint32_t offh = bn[it] * 128 + bkq * 16;
            cpasync16(bb + sw128(offh),      g_w1t_hi + gi);
            cpasync16(bb + sw128(offh + 64), g_w1t_lo + gi);
        }
        CP_COMMIT();
    };
    auto stsA = [&](int stage) {
        uint32_t ab = sbase + stage * G1_STAGE_BYTES + G1_A_OFF;
        #pragma unroll
        for (int it = 0; it < 2; it++) {
            uint4 hq, lq;
            split2p(a_st[it*8+0], a_st[it*8+1], hq.x, lq.x);
            split2p(a_st[it*8+2], a_st[it*8+3], hq.y, lq.y);
            split2p(a_st[it*8+4], a_st[it*8+5], hq.z, lq.z);
            split2p(a_st[it*8+6], a_st[it*8+7], hq.w, lq.w);
            uint32_t offh = agr[it] * 128 + akq * 16;
            *(uint4*)(smem + stage * G1_STAGE_BYTES + G1_A_OFF + sw128(offh))      = hq;
            *(uint4*)(smem + stage * G1_STAGE_BYTES + G1_A_OFF + sw128(offh + 64)) = lq;
        }
    };

    // ---- compute one k32 stage ----
    auto compute = [&](int stage) {
        uint32_t ab = sbase + stage * G1_STAGE_BYTES + G1_A_OFF;
        uint32_t bb = sbase + stage * G1_STAGE_BYTES + G1_B_OFF;
        const int q  = lane >> 3;       // 0..3
        const int rr = lane & 7;        // 0..7
        #pragma unroll
        for (int k16 = 0; k16 < 2; k16++) {
            int cb = k16 * 2;           // hi chunk base; lo = cb+4
            uint32_t ah[2][4], al[2][4], bh[4][4], bl[4][4];
            #pragma unroll
            for (int mi = 0; mi < 2; mi++) {
                int row = m0 + mi * 16 + (q & 1) * 8 + rr;
                uint32_t offh = row * 128 + (cb + (q >> 1)) * 16;
                ldsm4(ab + sw128(offh), ah[mi]);
                ldsm4(ab + sw128(offh + 64), al[mi]);
            }
            #pragma unroll
            for (int nj = 0; nj < 4; nj++) {
                int row = n0 + nj * 16 + (q & 1) * 8 + rr;
                uint32_t offh = row * 128 + (cb + (q >> 1)) * 16;
                ldsm4(bb + sw128(offh), bh[nj]);
                ldsm4(bb + sw128(offh + 64), bl[nj]);
            }
            #pragma unroll
            for (int mi = 0; mi < 2; mi++)
                #pragma unroll
                for (int nt = 0; nt < 8; nt++) {
                    int nj = nt >> 1, hh = nt & 1;
                    mma16816(acc[mi][nt], ah[mi], bh[nj][hh], bh[nj][2 + hh]);
                    mma16816(acc[mi][nt], ah[mi], bl[nj][hh], bl[nj][2 + hh]);
                    mma16816(acc[mi][nt], al[mi], bh[nj][hh], bh[nj][2 + hh]);
                }
        }
    };

    // ---- pipeline ----
    ldgA(0); cpB(0, 0); stsA(0);
    CP_WAIT0();
    __syncthreads();

    for (int s = 0; s < G1_STAGES; s++) {
        if (s + 1 < G1_STAGES) {
            ldgA((s + 1) * G1_BK);
            cpB((s + 1) * G1_BK, (s + 1) & 1);
        }
        compute(s & 1);
        if (s + 1 < G1_STAGES) {
            stsA((s + 1) & 1);
            CP_WAIT0();
            __syncthreads();
        }
    }

    // ---- epilogue: bias + relu ----
    const float bval = bias[0];
    const int g  = lane >> 2;
    const int tq = lane & 3;
    #pragma unroll
    for (int mi = 0; mi < 2; mi++)
        #pragma unroll
        for (int nt = 0; nt < 8; nt++) {
            int row = m0 + mi * 16 + g;
            int col = colBase + n0 + nt * 8 + tq * 2;
            int gr0 = rowBase + row;
            int gr1 = gr0 + 8;
            float* cc = acc[mi][nt];
            if (gr0 < N_NODES) {
                float2 o;
                o.x = fmaxf(cc[0] + bval, 0.f);
                o.y = fmaxf(cc[1] + bval, 0.f);
                *(float2*)(C + (size_t)gr0 * NHID + col) = o;
            }
            if (gr1 < N_NODES) {
                float2 o;
                o.x = fmaxf(cc[2] + bval, 0.f);
                o.y = fmaxf(cc[3] + bval, 0.f);
                *(float2*)(C + (size_t)gr1 * NHID + col) = o;
            }
        }
}

// ---------------------------------------------------------------------------
// GEMM2: h2 = h @ W2 + b2   [100000,256] x [256,40]  (SIMT fp32)
// ---------------------------------------------------------------------------
__global__ void __launch_bounds__(256) gemm2_kernel(
    const float* __restrict__ A,
    const float* __restrict__ B,
    const float* __restrict__ bias,
    float* __restrict__ C)
{
    __shared__ float As[32][128];
    __shared__ float Bs[32][40];

    const int tid = threadIdx.x;
    const int rowBase = blockIdx.x * 128;
    const int rg = tid / 8;
    const int cg = tid % 8;

    float acc[4][5];
    #pragma unroll
    for (int i = 0; i < 4; i++)
        #pragma unroll
        for (int j = 0; j < 5; j++) acc[i][j] = 0.f;

    const float bval = bias[0];

    for (int k0 = 0; k0 < NHID; k0 += 32) {
        #pragma unroll
        for (int s = 0; s < 4; s++) {
            int idx = tid + s * 256;
            int r = idx / 8;
            int c4 = (idx % 8) * 4;
            int gr = rowBase + r;
            float4 v = make_float4(0.f, 0.f, 0.f, 0.f);
            if (gr < N_NODES)
                v = *(const float4*)(A + (size_t)gr * NHID + k0 + c4);
            As[c4 + 0][r] = v.x;
            As[c4 + 1][r] = v.y;
            As[c4 + 2][r] = v.z;
            As[c4 + 3][r] = v.w;
        }
        #pragma unroll
        for (int s = 0; s < 5; s++) {
            int idx = tid + s * 256;
            int r = idx / 40, c = idx % 40;
            Bs[r][c] = B[(size_t)(k0 + r) * NCLASS + c];
        }
        __syncthreads();

        #pragma unroll
        for (int k = 0; k < 32; k++) {
            float rm[4], rn[5];
            #pragma unroll
            for (int i = 0; i < 4; i++) rm[i] = As[k][rg * 4 + i];
            #pragma unroll
            for (int j = 0; j < 5; j++) rn[j] = Bs[k][cg * 5 + j];
            #pragma unroll
            for (int i = 0; i < 4; i++)
                #pragma unroll
                for (int j = 0; j < 5; j++)
                    acc[i][j] += rm[i] * rn[j];
        }
        __syncthreads();
    }

    #pragma unroll
    for (int i = 0; i < 4; i++) {
        int gr = rowBase + rg * 4 + i;
        if (gr >= N_NODES) continue;
        #pragma unroll
        for (int j = 0; j < 5; j++)
            C[(size_t)gr * NCLASS + cg * 5 + j] = acc[i][j] + bval;
    }
}

// ---------------------------------------------------------------------------
// CSR build: histogram -> 2-level exclusive scan -> scatter
// ---------------------------------------------------------------------------
__global__ void zero_counts_kernel()
{
    int i = blockIdx.x * blockDim.x + threadIdx.x;
    if (i < N_NODES) g_cnt[i] = 0;
}

__global__ void histogram_kernel(const int* __restrict__ row)
{
    int e = blockIdx.x * blockDim.x + threadIdx.x;
    if (e < E_EDGES) atomicAdd(&g_cnt[row[e]], 1);
}

__global__ void __launch_bounds__(SCAN_BLK) scan1_kernel()
{
    __shared__ int s[SCAN_BLK];
    int gid = blockIdx.x * SCAN_BLK + threadIdx.x;
    int x = (gid < N_NODES) ? g_cnt[gid] : 0;
    s[threadIdx.x] = x;
    __syncthreads();
    #pragma unroll
    for (int d = 1; d < SCAN_BLK; d <<= 1) {
        int t = (threadIdx.x >= d) ? s[threadIdx.x - d] : 0;
        __syncthreads();
        s[threadIdx.x] += t;
        __syncthreads();
    }
    if (gid < N_NODES) g_offl[gid] = s[threadIdx.x] - x;
    if (threadIdx.x == SCAN_BLK - 1) g_blk[blockIdx.x] = s[SCAN_BLK - 1];
}

__global__ void scan2_kernel()
{
    __shared__ int s[128];
    int tid = threadIdx.x;
    int x = (tid < NUM_SCAN_BLKS) ? g_blk[tid] : 0;
    s[tid] = x;
    __syncthreads();
    #pragma unroll
    for (int d = 1; d < 128; d <<= 1) {
        int t = (tid >= d) ? s[tid - d] : 0;
        __syncthreads();
        s[tid] += t;
        __syncthreads();
    }
    if (tid < NUM_SCAN_BLKS) g_blkoff[tid] = s[tid] - x;
}

__global__ void scan3_kernel()
{
    int i = blockIdx.x * blockDim.x + threadIdx.x;
    if (i < N_NODES) {
        int st = g_offl[i] + g_blkoff[i / SCAN_BLK];
        g_start[i]  = st;
        g_cursor[i] = st;
    }
    if (i == 0) g_start[N_NODES] = E_EDGES;
}

__global__ void scatter_kernel(const int* __restrict__ row,
                               const int* __restrict__ col,
                               const float* __restrict__ vals)
{
    int e = blockIdx.x * blockDim.x + threadIdx.x;
    if (e >= E_EDGES) return;
    int r = row[e];
    int pos = atomicAdd(&g_cursor[r], 1);
    int2 ev;
    ev.x = col[e];
    ev.y = __float_as_int((1.0f - ALPHA) * vals[e]);
    g_edges[pos] = ev;
}

// ---------------------------------------------------------------------------
// Pull-mode SpMM + alpha blend (atomic-free)
// ---------------------------------------------------------------------------
__global__ void __launch_bounds__(256) spmm_csr_kernel(
    const float* __restrict__ z,
    const float* __restrict__ h2,
    float* __restrict__ znew)
{
    int r = blockIdx.x * blockDim.x + threadIdx.x;
    if (r >= N_NODES) return;

    int e0 = g_start[r];
    int e1 = g_start[r + 1];

    float4 acc[NCLASS / 4];
    #pragma unroll
    for (int t = 0; t < NCLASS / 4; t++)
        acc[t] = make_float4(0.f, 0.f, 0.f, 0.f);

    for (int e = e0; e < e1; e++) {
        int2 ev = g_edges[e];
        int c = ev.x;
        float v = __int_as_float(ev.y);
        const float4* zp = (const float4*)(z + (size_t)c * NCLASS);
        #pragma unroll
        for (int t = 0; t < NCLASS / 4; t++) {
            float4 a = zp[t];
            acc[t].x += v * a.x;
            acc[t].y += v * a.y;
            acc[t].z += v * a.z;
            acc[t].w += v * a.w;
        }
    }

    const float4* hp = (const float4*)(h2 + (size_t)r * NCLASS);
    float4* op = (float4*)(znew + (size_t)r * NCLASS);
    #pragma unroll
    for (int t = 0; t < NCLASS / 4; t++) {
        float4 hv = hp[t];
        float4 o;
        o.x = acc[t].x + ALPHA * hv.x;
        o.y = acc[t].y + ALPHA * hv.y;
        o.z = acc[t].z + ALPHA * hv.z;
        o.w = acc[t].w + ALPHA * hv.w;
        op[t] = o;
    }
}

// ---------------------------------------------------------------------------
// Row-wise log_softmax over 40 classes: one warp per row
// ---------------------------------------------------------------------------
__global__ void logsoftmax_kernel(const float* __restrict__ z,
                                  float* __restrict__ out)
{
    int gtid = blockIdx.x * blockDim.x + threadIdx.x;
    int warp = gtid / 32;
    int lane = gtid % 32;
    if (warp >= N_NODES) return;

    const float* zr = z + (size_t)warp * NCLASS;
    float v0 = zr[lane];
    float v1 = (lane < NCLASS - 32) ? zr[lane + 32] : -INFINITY;

    float m = fmaxf(v0, v1);
    #pragma unroll
    for (int o = 16; o > 0; o >>= 1)
        m = fmaxf(m, __shfl_xor_sync(0xFFFFFFFFu, m, o));

    float s = expf(v0 - m) + ((lane < NCLASS - 32) ? expf(v1 - m) : 0.f);
    #pragma unroll
    for (int o = 16; o > 0; o >>= 1)
        s += __shfl_xor_sync(0xFFFFFFFFu, s, o);

    float L = m + logf(s);
    out[(size_t)warp * NCLASS + lane] = v0 - L;
    if (lane < NCLASS - 32)
        out[(size_t)warp * NCLASS + lane + 32] = v1 - L;
}

// ---------------------------------------------------------------------------
extern "C" void kernel_launch(void* const* d_in, const int* in_sizes, int n_in,
                              void* d_out, int out_size)
{
    const float* x    = (const float*)d_in[0];
    const int*   row  = (const int*)  d_in[1];
    const int*   col  = (const int*)  d_in[2];
    const float* vals = (const float*)d_in[3];
    const float* W1   = (const float*)d_in[4];
    const float* b1   = (const float*)d_in[5];
    const float* W2   = (const float*)d_in[6];
    const float* b2   = (const float*)d_in[7];
    float* out = (float*)d_out;

    float *h, *h2, *za, *zb;
    cudaGetSymbolAddress((void**)&h,  g_h);
    cudaGetSymbolAddress((void**)&h2, g_h2);
    cudaGetSymbolAddress((void**)&za, g_za);
    cudaGetSymbolAddress((void**)&zb, g_zb);

    cudaFuncSetAttribute(gemm1_mma_kernel,
                         cudaFuncAttributeMaxDynamicSharedMemorySize, G1_SMEM);

    // CSR build (atomic-free propagation afterwards)
    zero_counts_kernel<<<(N_NODES + 255) / 256, 256>>>();
    histogram_kernel<<<(E_EDGES + 255) / 256, 256>>>(row);
    scan1_kernel<<<NUM_SCAN_BLKS, SCAN_BLK>>>();
    scan2_kernel<<<1, 128>>>();
    scan3_kernel<<<(N_NODES + 255) / 256, 256>>>();
    scatter_kernel<<<(E_EDGES + 255) / 256, 256>>>(row, col, vals);

    // MLP: HMMA GEMM1 (bf16 split), SIMT GEMM2
    prep_w1t_kernel<<<(NHID * NFEAT + 255) / 256, 256>>>(W1);
    dim3 g1((N_NODES + G1_BM - 1) / G1_BM, NHID / G1_BN);
    gemm1_mma_kernel<<<g1, 256, G1_SMEM>>>(x, b1, h);
    gemm2_kernel<<<(N_NODES + 127) / 128, 256>>>(h, W2, b2, h2);

    // APPNP propagation
    const float* zin = h2;
    float* bufs[2] = { za, zb };
    for (int it = 0; it < NLAYERS; it++) {
        float* zout = bufs[it & 1];
        spmm_csr_kernel<<<(N_NODES + 255) / 256, 256>>>(zin, h2, zout);
        zin = zout;
    }

    logsoftmax_kernel<<<(N_NODES * 32 + 255) / 256, 256>>>(zin, out);
}

// round 5
// speedup vs baseline: 1.7073x; 1.0141x over previous
#include <cuda_runtime.h>
#include <cuda_bf16.h>
#include <math.h>
#include <stdint.h>

#define N_NODES 100000
#define E_EDGES 1600000
#define NFEAT   512
#define NHID    256
#define NCLASS  40
#define NLAYERS 10
#define ALPHA   0.1f

#define SCAN_BLK 1024
#define NUM_SCAN_BLKS ((N_NODES + SCAN_BLK - 1) / SCAN_BLK)   // 98

// Scratch (static device globals — allocation-free rule)
__device__ float g_h [N_NODES * NHID];    // relu(x@W1+b1)
__device__ float g_h2[N_NODES * NCLASS];  // h@W2+b2  (z_0)
__device__ float g_za[N_NODES * NCLASS];
__device__ float g_zb[N_NODES * NCLASS];

// W1 transposed + bf16-split: [NHID][NFEAT]
__device__ __nv_bfloat16 g_w1t_hi[NHID * NFEAT];
__device__ __nv_bfloat16 g_w1t_lo[NHID * NFEAT];

// CSR build scratch
__device__ int  g_cnt   [N_NODES];
__device__ int  g_offl  [N_NODES];
__device__ int  g_start [N_NODES + 1];
__device__ int  g_cursor[N_NODES];
__device__ int  g_blk   [NUM_SCAN_BLKS];
__device__ int  g_blkoff[NUM_SCAN_BLKS];
__device__ int2 g_edges [E_EDGES];

// ===========================================================================
// helpers (baseline PTX only: ldmatrix / mma.sync / cp.async)
// ===========================================================================
__device__ __forceinline__ uint32_t smem_u32(const void* p) {
    uint32_t a;
    asm("{ .reg .u64 t; cvta.to.shared.u64 t, %1; cvt.u32.u64 %0, t; }"
        : "=r"(a) : "l"(p));
    return a;
}

__device__ __forceinline__ void ldsm4(uint32_t addr, uint32_t* r) {
    asm volatile("ldmatrix.sync.aligned.m8n8.x4.shared.b16 {%0,%1,%2,%3}, [%4];"
        : "=r"(r[0]), "=r"(r[1]), "=r"(r[2]), "=r"(r[3]) : "r"(addr));
}

__device__ __forceinline__ void mma16816(float* c, const uint32_t* a,
                                         uint32_t b0, uint32_t b1) {
    asm volatile(
        "mma.sync.aligned.m16n8k16.row.col.f32.bf16.bf16.f32 "
        "{%0,%1,%2,%3}, {%4,%5,%6,%7}, {%8,%9}, {%0,%1,%2,%3};"
        : "+f"(c[0]), "+f"(c[1]), "+f"(c[2]), "+f"(c[3])
        : "r"(a[0]), "r"(a[1]), "r"(a[2]), "r"(a[3]), "r"(b0), "r"(b1));
}

__device__ __forceinline__ void cpasync16(uint32_t saddr, const void* gptr) {
    asm volatile("cp.async.cg.shared.global [%0], [%1], 16;"
                 :: "r"(saddr), "l"(gptr) : "memory");
}
#define CP_COMMIT() asm volatile("cp.async.commit_group;" ::: "memory")
#define CP_WAIT0()  asm volatile("cp.async.wait_group 0;" ::: "memory")

__device__ __forceinline__ uint32_t sw128(uint32_t off) {
    return off ^ ((off >> 3) & 0x70);
}

// ===========================================================================
// Prep: W1T bf16 split  (w1t[n][k] = W1[k][n] split into hi/lo)
// ===========================================================================
__global__ void prep_w1t_kernel(const float* __restrict__ W1)
{
    int i = blockIdx.x * blockDim.x + threadIdx.x;
    if (i >= NHID * NFEAT) return;
    int n = i / NFEAT, k = i % NFEAT;
    float v = W1[(size_t)k * NHID + n];
    __nv_bfloat16 h = __float2bfloat16(v);
    g_w1t_hi[i] = h;
    g_w1t_lo[i] = __float2bfloat16(v - __bfloat162float(h));
}

// ===========================================================================
// GEMM1 (mma.sync HMMA): h = relu(x @ W1 + b1), bf16 2-split, fp32 acc
// CTA 128x256 (full NHID in one block), 512 threads / 16 warps (4m x 4n),
// warp tile 32x64. K staged at 32, double buffered.
// SMEM stage: A 128 rows x 128B [hi32|lo32] = 16KB, B 256 rows x 128B = 32KB.
// ===========================================================================
#define G1_BM 128
#define G1_BN 256
#define G1_BK 32
#define G1_STAGES (NFEAT / G1_BK)      // 16
#define G1_A_OFF 0
#define G1_B_OFF 16384
#define G1_STAGE_BYTES 49152
#define G1_SMEM (2 * G1_STAGE_BYTES)   // 98304

__device__ __forceinline__ void split2p(float a, float b, uint32_t& hi, uint32_t& lo) {
    __nv_bfloat16 ah = __float2bfloat16(a);
    __nv_bfloat16 bh = __float2bfloat16(b);
    __nv_bfloat16 al = __float2bfloat16(a - __bfloat162float(ah));
    __nv_bfloat16 bl = __float2bfloat16(b - __bfloat162float(bh));
    hi = (uint32_t)__bfloat16_as_ushort(ah) | ((uint32_t)__bfloat16_as_ushort(bh) << 16);
    lo = (uint32_t)__bfloat16_as_ushort(al) | ((uint32_t)__bfloat16_as_ushort(bl) << 16);
}

__global__ void __launch_bounds__(512, 1) gemm1_mma_kernel(
    const float* __restrict__ A,
    const float* __restrict__ bias,
    float* __restrict__ C)
{
    extern __shared__ char smem[];
    const uint32_t sbase = smem_u32(smem);
    const int tid  = threadIdx.x;
    const int wid  = tid >> 5;
    const int lane = tid & 31;
    const int rowBase = blockIdx.x * G1_BM;

    const int warp_m = wid & 3;        // 0..3
    const int warp_n = wid >> 2;       // 0..3
    const int m0 = warp_m * 32;
    const int n0 = warp_n * 64;

    float acc[2][8][4];
    #pragma unroll
    for (int i = 0; i < 2; i++)
        #pragma unroll
        for (int j = 0; j < 8; j++)
            #pragma unroll
            for (int q = 0; q < 4; q++) acc[i][j][q] = 0.f;

    // A: 512 threads cover 128 rows x 4 k-octets, one 8-float group each
    const int agr = tid >> 2;          // row 0..127
    const int akq = tid & 3;           // k-octet
    // B: 1024 groups (256 rows x 4 octets), 2 per thread
    const int bn0 = tid >> 2;
    const int bn1 = (tid + 512) >> 2;
    const int bkq = tid & 3;

    float a_st[8];

    auto ldgA = [&](int k0) {
        int gr = rowBase + agr;
        if (gr < N_NODES) {
            const float* p = A + (size_t)gr * NFEAT + k0 + akq * 8;
            float4 v0 = *(const float4*)p;
            float4 v1 = *(const float4*)(p + 4);
            a_st[0]=v0.x; a_st[1]=v0.y; a_st[2]=v0.z; a_st[3]=v0.w;
            a_st[4]=v1.x; a_st[5]=v1.y; a_st[6]=v1.z; a_st[7]=v1.w;
        } else {
            #pragma unroll
            for (int q = 0; q < 8; q++) a_st[q] = 0.f;
        }
    };
    auto cpB = [&](int k0, int stage) {
        uint32_t bb = sbase + stage * G1_STAGE_BYTES + G1_B_OFF;
        size_t gi0 = (size_t)bn0 * NFEAT + k0 + bkq * 8;
        size_t gi1 = (size_t)bn1 * NFEAT + k0 + bkq * 8;
        uint32_t off0 = bn0 * 128 + bkq * 16;
        uint32_t off1 = bn1 * 128 + bkq * 16;
        cpasync16(bb + sw128(off0),      g_w1t_hi + gi0);
        cpasync16(bb + sw128(off0 + 64), g_w1t_lo + gi0);
        cpasync16(bb + sw128(off1),      g_w1t_hi + gi1);
        cpasync16(bb + sw128(off1 + 64), g_w1t_lo + gi1);
        CP_COMMIT();
    };
    auto stsA = [&](int stage) {
        uint4 hq, lq;
        split2p(a_st[0], a_st[1], hq.x, lq.x);
        split2p(a_st[2], a_st[3], hq.y, lq.y);
        split2p(a_st[4], a_st[5], hq.z, lq.z);
        split2p(a_st[6], a_st[7], hq.w, lq.w);
        uint32_t offh = agr * 128 + akq * 16;
        char* ab = smem + stage * G1_STAGE_BYTES + G1_A_OFF;
        *(uint4*)(ab + sw128(offh))      = hq;
        *(uint4*)(ab + sw128(offh + 64)) = lq;
    };

    auto compute = [&](int stage) {
        uint32_t ab = sbase + stage * G1_STAGE_BYTES + G1_A_OFF;
        uint32_t bb = sbase + stage * G1_STAGE_BYTES + G1_B_OFF;
        const int q  = lane >> 3;       // 0..3
        const int rr = lane & 7;        // 0..7
        #pragma unroll
        for (int k16 = 0; k16 < 2; k16++) {
            int cb = k16 * 2;
            uint32_t ah[2][4], al[2][4];
            #pragma unroll
            for (int mi = 0; mi < 2; mi++) {
                int row = m0 + mi * 16 + (q & 1) * 8 + rr;
                uint32_t offh = row * 128 + (cb + (q >> 1)) * 16;
                ldsm4(ab + sw128(offh), ah[mi]);
                ldsm4(ab + sw128(offh + 64), al[mi]);
            }
            #pragma unroll
            for (int nj = 0; nj < 4; nj++) {
                uint32_t bh[4], bl[4];
                int row = n0 + nj * 16 + (q & 1) * 8 + rr;
                uint32_t offh = row * 128 + (cb + (q >> 1)) * 16;
                ldsm4(bb + sw128(offh), bh);
                ldsm4(bb + sw128(offh + 64), bl);
                #pragma unroll
                for (int mi = 0; mi < 2; mi++)
                    #pragma unroll
                    for (int hh = 0; hh < 2; hh++) {
                        float* cc = acc[mi][nj * 2 + hh];
                        mma16816(cc, ah[mi], bh[hh], bh[2 + hh]);
                        mma16816(cc, ah[mi], bl[hh], bl[2 + hh]);
                        mma16816(cc, al[mi], bh[hh], bh[2 + hh]);
                    }
            }
        }
    };

    // ---- pipeline ----
    ldgA(0); cpB(0, 0); stsA(0);
    CP_WAIT0();
    __syncthreads();

    for (int s = 0; s < G1_STAGES; s++) {
        if (s + 1 < G1_STAGES) {
            ldgA((s + 1) * G1_BK);
            cpB((s + 1) * G1_BK, (s + 1) & 1);
        }
        compute(s & 1);
        if (s + 1 < G1_STAGES) {
            stsA((s + 1) & 1);
            CP_WAIT0();
            __syncthreads();
        }
    }

    // ---- epilogue: bias + relu ----
    const float bval = bias[0];
    const int g  = lane >> 2;
    const int tq = lane & 3;
    #pragma unroll
    for (int mi = 0; mi < 2; mi++)
        #pragma unroll
        for (int nt = 0; nt < 8; nt++) {
            int row = m0 + mi * 16 + g;
            int col = n0 + nt * 8 + tq * 2;
            int gr0 = rowBase + row;
            int gr1 = gr0 + 8;
            float* cc = acc[mi][nt];
            if (gr0 < N_NODES) {
                float2 o;
                o.x = fmaxf(cc[0] + bval, 0.f);
                o.y = fmaxf(cc[1] + bval, 0.f);
                *(float2*)(C + (size_t)gr0 * NHID + col) = o;
            }
            if (gr1 < N_NODES) {
                float2 o;
                o.x = fmaxf(cc[2] + bval, 0.f);
                o.y = fmaxf(cc[3] + bval, 0.f);
                *(float2*)(C + (size_t)gr1 * NHID + col) = o;
            }
        }
}

// ---------------------------------------------------------------------------
// GEMM2: h2 = h @ W2 + b2   [100000,256] x [256,40]  (SIMT fp32)
// ---------------------------------------------------------------------------
__global__ void __launch_bounds__(256) gemm2_kernel(
    const float* __restrict__ A,
    const float* __restrict__ B,
    const float* __restrict__ bias,
    float* __restrict__ C)
{
    __shared__ float As[32][128];
    __shared__ float Bs[32][40];

    const int tid = threadIdx.x;
    const int rowBase = blockIdx.x * 128;
    const int rg = tid / 8;
    const int cg = tid % 8;

    float acc[4][5];
    #pragma unroll
    for (int i = 0; i < 4; i++)
        #pragma unroll
        for (int j = 0; j < 5; j++) acc[i][j] = 0.f;

    const float bval = bias[0];

    for (int k0 = 0; k0 < NHID; k0 += 32) {
        #pragma unroll
        for (int s = 0; s < 4; s++) {
            int idx = tid + s * 256;
            int r = idx / 8;
            int c4 = (idx % 8) * 4;
            int gr = rowBase + r;
            float4 v = make_float4(0.f, 0.f, 0.f, 0.f);
            if (gr < N_NODES)
                v = *(const float4*)(A + (size_t)gr * NHID + k0 + c4);
            As[c4 + 0][r] = v.x;
            As[c4 + 1][r] = v.y;
            As[c4 + 2][r] = v.z;
            As[c4 + 3][r] = v.w;
        }
        #pragma unroll
        for (int s = 0; s < 5; s++) {
            int idx = tid + s * 256;
            int r = idx / 40, c = idx % 40;
            Bs[r][c] = B[(size_t)(k0 + r) * NCLASS + c];
        }
        __syncthreads();

        #pragma unroll
        for (int k = 0; k < 32; k++) {
            float rm[4], rn[5];
            #pragma unroll
            for (int i = 0; i < 4; i++) rm[i] = As[k][rg * 4 + i];
            #pragma unroll
            for (int j = 0; j < 5; j++) rn[j] = Bs[k][cg * 5 + j];
            #pragma unroll
            for (int i = 0; i < 4; i++)
                #pragma unroll
                for (int j = 0; j < 5; j++)
                    acc[i][j] += rm[i] * rn[j];
        }
        __syncthreads();
    }

    #pragma unroll
    for (int i = 0; i < 4; i++) {
        int gr = rowBase + rg * 4 + i;
        if (gr >= N_NODES) continue;
        #pragma unroll
        for (int j = 0; j < 5; j++)
            C[(size_t)gr * NCLASS + cg * 5 + j] = acc[i][j] + bval;
    }
}

// ---------------------------------------------------------------------------
// CSR build: histogram -> 2-level exclusive scan -> scatter
// ---------------------------------------------------------------------------
__global__ void zero_counts_kernel()
{
    int i = blockIdx.x * blockDim.x + threadIdx.x;
    if (i < N_NODES) g_cnt[i] = 0;
}

__global__ void histogram_kernel(const int* __restrict__ row)
{
    int e = blockIdx.x * blockDim.x + threadIdx.x;
    if (e < E_EDGES) atomicAdd(&g_cnt[row[e]], 1);
}

__global__ void __launch_bounds__(SCAN_BLK) scan1_kernel()
{
    __shared__ int s[SCAN_BLK];
    int gid = blockIdx.x * SCAN_BLK + threadIdx.x;
    int x = (gid < N_NODES) ? g_cnt[gid] : 0;
    s[threadIdx.x] = x;
    __syncthreads();
    #pragma unroll
    for (int d = 1; d < SCAN_BLK; d <<= 1) {
        int t = (threadIdx.x >= d) ? s[threadIdx.x - d] : 0;
        __syncthreads();
        s[threadIdx.x] += t;
        __syncthreads();
    }
    if (gid < N_NODES) g_offl[gid] = s[threadIdx.x] - x;
    if (threadIdx.x == SCAN_BLK - 1) g_blk[blockIdx.x] = s[SCAN_BLK - 1];
}

__global__ void scan2_kernel()
{
    __shared__ int s[128];
    int tid = threadIdx.x;
    int x = (tid < NUM_SCAN_BLKS) ? g_blk[tid] : 0;
    s[tid] = x;
    __syncthreads();
    #pragma unroll
    for (int d = 1; d < 128; d <<= 1) {
        int t = (tid >= d) ? s[tid - d] : 0;
        __syncthreads();
        s[tid] += t;
        __syncthreads();
    }
    if (tid < NUM_SCAN_BLKS) g_blkoff[tid] = s[tid] - x;
}

__global__ void scan3_kernel()
{
    int i = blockIdx.x * blockDim.x + threadIdx.x;
    if (i < N_NODES) {
        int st = g_offl[i] + g_blkoff[i / SCAN_BLK];
        g_start[i]  = st;
        g_cursor[i] = st;
    }
    if (i == 0) g_start[N_NODES] = E_EDGES;
}

__global__ void scatter_kernel(const int* __restrict__ row,
                               const int* __restrict__ col,
                               const float* __restrict__ vals)
{
    int e = blockIdx.x * blockDim.x + threadIdx.x;
    if (e >= E_EDGES) return;
    int r = row[e];
    int pos = atomicAdd(&g_cursor[r], 1);
    int2 ev;
    ev.x = col[e];
    ev.y = __float_as_int((1.0f - ALPHA) * vals[e]);
    g_edges[pos] = ev;
}

// ---------------------------------------------------------------------------
// Pull-mode SpMM + alpha blend (atomic-free)
// ---------------------------------------------------------------------------
__global__ void __launch_bounds__(256) spmm_csr_kernel(
    const float* __restrict__ z,
    const float* __restrict__ h2,
    float* __restrict__ znew)
{
    int r = blockIdx.x * blockDim.x + threadIdx.x;
    if (r >= N_NODES) return;

    int e0 = g_start[r];
    int e1 = g_start[r + 1];

    float4 acc[NCLASS / 4];
    #pragma unroll
    for (int t = 0; t < NCLASS / 4; t++)
        acc[t] = make_float4(0.f, 0.f, 0.f, 0.f);

    for (int e = e0; e < e1; e++) {
        int2 ev = g_edges[e];
        int c = ev.x;
        float v = __int_as_float(ev.y);
        const float4* zp = (const float4*)(z + (size_t)c * NCLASS);
        #pragma unroll
        for (int t = 0; t < NCLASS / 4; t++) {
            float4 a = zp[t];
            acc[t].x += v * a.x;
            acc[t].y += v * a.y;
            acc[t].z += v * a.z;
            acc[t].w += v * a.w;
        }
    }

    const float4* hp = (const float4*)(h2 + (size_t)r * NCLASS);
    float4* op = (float4*)(znew + (size_t)r * NCLASS);
    #pragma unroll
    for (int t = 0; t < NCLASS / 4; t++) {
        float4 hv = hp[t];
        float4 o;
        o.x = acc[t].x + ALPHA * hv.x;
        o.y = acc[t].y + ALPHA * hv.y;
        o.z = acc[t].z + ALPHA * hv.z;
        o.w = acc[t].w + ALPHA * hv.w;
        op[t] = o;
    }
}

// ---------------------------------------------------------------------------
// Row-wise log_softmax over 40 classes: one warp per row
// ---------------------------------------------------------------------------
__global__ void logsoftmax_kernel(const float* __restrict__ z,
                                  float* __restrict__ out)
{
    int gtid = blockIdx.x * blockDim.x + threadIdx.x;
    int warp = gtid / 32;
    int lane = gtid % 32;
    if (warp >= N_NODES) return;

    const float* zr = z + (size_t)warp * NCLASS;
    float v0 = zr[lane];
    float v1 = (lane < NCLASS - 32) ? zr[lane + 32] : -INFINITY;

    float m = fmaxf(v0, v1);
    #pragma unroll
    for (int o = 16; o > 0; o >>= 1)
        m = fmaxf(m, __shfl_xor_sync(0xFFFFFFFFu, m, o));

    float s = expf(v0 - m) + ((lane < NCLASS - 32) ? expf(v1 - m) : 0.f);
    #pragma unroll
    for (int o = 16; o > 0; o >>= 1)
        s += __shfl_xor_sync(0xFFFFFFFFu, s, o);

    float L = m + logf(s);
    out[(size_t)warp * NCLASS + lane] = v0 - L;
    if (lane < NCLASS - 32)
        out[(size_t)warp * NCLASS + lane + 32] = v1 - L;
}

// ---------------------------------------------------------------------------
extern "C" void kernel_launch(void* const* d_in, const int* in_sizes, int n_in,
                              void* d_out, int out_size)
{
    const float* x    = (const float*)d_in[0];
    const int*   row  = (const int*)  d_in[1];
    const int*   col  = (const int*)  d_in[2];
    const float* vals = (const float*)d_in[3];
    const float* W1   = (const float*)d_in[4];
    const float* b1   = (const float*)d_in[5];
    const float* W2   = (const float*)d_in[6];
    const float* b2   = (const float*)d_in[7];
    float* out = (float*)d_out;

    float *h, *h2, *za, *zb;
    cudaGetSymbolAddress((void**)&h,  g_h);
    cudaGetSymbolAddress((void**)&h2, g_h2);
    cudaGetSymbolAddress((void**)&za, g_za);
    cudaGetSymbolAddress((void**)&zb, g_zb);

    cudaFuncSetAttribute(gemm1_mma_kernel,
                         cudaFuncAttributeMaxDynamicSharedMemorySize, G1_SMEM);

    // Launch order arranged so gemm1 is the 6th launch (ncu -s 5 -c 1 profiles it).
    prep_w1t_kernel<<<(NHID * NFEAT + 255) / 256, 256>>>(W1);          // 1
    zero_counts_kernel<<<(N_NODES + 255) / 256, 256>>>();              // 2
    histogram_kernel<<<(E_EDGES + 255) / 256, 256>>>(row);             // 3
    scan1_kernel<<<NUM_SCAN_BLKS, SCAN_BLK>>>();                       // 4
    scan2_kernel<<<1, 128>>>();                                        // 5
    gemm1_mma_kernel<<<(N_NODES + G1_BM - 1) / G1_BM, 512, G1_SMEM>>>(x, b1, h); // 6
    scan3_kernel<<<(N_NODES + 255) / 256, 256>>>();                    // 7
    scatter_kernel<<<(E_EDGES + 255) / 256, 256>>>(row, col, vals);    // 8
    gemm2_kernel<<<(N_NODES + 127) / 128, 256>>>(h, W2, b2, h2);       // 9

    // APPNP propagation
    const float* zin = h2;
    float* bufs[2] = { za, zb };
    for (int it = 0; it < NLAYERS; it++) {
        float* zout = bufs[it & 1];
        spmm_csr_kernel<<<(N_NODES + 255) / 256, 256>>>(zin, h2, zout);
        zin = zout;
    }

    logsoftmax_kernel<<<(N_NODES * 32 + 255) / 256, 256>>>(zin, out);
}

// round 6
// speedup vs baseline: 1.7549x; 1.0279x over previous
#include <cuda_runtime.h>
#include <cuda_bf16.h>
#include <math.h>
#include <stdint.h>

#define N_NODES 100000
#define E_EDGES 1600000
#define NFEAT   512
#define NHID    256
#define NCLASS  40
#define NLAYERS 10
#define ALPHA   0.1f

#define SCAN_BLK 1024
#define NUM_SCAN_BLKS ((N_NODES + SCAN_BLK - 1) / SCAN_BLK)   // 98

// Scratch (static device globals — allocation-free rule)
__device__ float g_h [N_NODES * NHID];    // relu(x@W1+b1)
__device__ float g_h2[N_NODES * NCLASS];  // h@W2+b2  (z_0)
__device__ float g_za[N_NODES * NCLASS];
__device__ float g_zb[N_NODES * NCLASS];

// W1 transposed + bf16-split: [NHID][NFEAT]
__device__ __nv_bfloat16 g_w1t_hi[NHID * NFEAT];
__device__ __nv_bfloat16 g_w1t_lo[NHID * NFEAT];
// W2 transposed + bf16-split: [NCLASS][NHID]
__device__ __nv_bfloat16 g_w2t_hi[NCLASS * NHID];
__device__ __nv_bfloat16 g_w2t_lo[NCLASS * NHID];

// CSR build scratch
__device__ int  g_cnt   [N_NODES];
__device__ int  g_offl  [N_NODES];
__device__ int  g_start [N_NODES + 1];
__device__ int  g_cursor[N_NODES];
__device__ int  g_blk   [NUM_SCAN_BLKS];
__device__ int  g_blkoff[NUM_SCAN_BLKS];
__device__ int2 g_edges [E_EDGES];

// ===========================================================================
// helpers (baseline PTX only: ldmatrix / mma.sync / cp.async)
// ===========================================================================
__device__ __forceinline__ uint32_t smem_u32(const void* p) {
    uint32_t a;
    asm("{ .reg .u64 t; cvta.to.shared.u64 t, %1; cvt.u32.u64 %0, t; }"
        : "=r"(a) : "l"(p));
    return a;
}

__device__ __forceinline__ void ldsm4(uint32_t addr, uint32_t* r) {
    asm volatile("ldmatrix.sync.aligned.m8n8.x4.shared.b16 {%0,%1,%2,%3}, [%4];"
        : "=r"(r[0]), "=r"(r[1]), "=r"(r[2]), "=r"(r[3]) : "r"(addr));
}

__device__ __forceinline__ void mma16816(float* c, const uint32_t* a,
                                         uint32_t b0, uint32_t b1) {
    asm volatile(
        "mma.sync.aligned.m16n8k16.row.col.f32.bf16.bf16.f32 "
        "{%0,%1,%2,%3}, {%4,%5,%6,%7}, {%8,%9}, {%0,%1,%2,%3};"
        : "+f"(c[0]), "+f"(c[1]), "+f"(c[2]), "+f"(c[3])
        : "r"(a[0]), "r"(a[1]), "r"(a[2]), "r"(a[3]), "r"(b0), "r"(b1));
}

__device__ __forceinline__ void cpasync16(uint32_t saddr, const void* gptr) {
    asm volatile("cp.async.cg.shared.global [%0], [%1], 16;"
                 :: "r"(saddr), "l"(gptr) : "memory");
}
#define CP_COMMIT() asm volatile("cp.async.commit_group;" ::: "memory")
#define CP_WAIT0()  asm volatile("cp.async.wait_group 0;" ::: "memory")

__device__ __forceinline__ uint32_t sw128(uint32_t off) {
    return off ^ ((off >> 3) & 0x70);
}

__device__ __forceinline__ void split2p(float a, float b, uint32_t& hi, uint32_t& lo) {
    __nv_bfloat16 ah = __float2bfloat16(a);
    __nv_bfloat16 bh = __float2bfloat16(b);
    __nv_bfloat16 al = __float2bfloat16(a - __bfloat162float(ah));
    __nv_bfloat16 bl = __float2bfloat16(b - __bfloat162float(bh));
    hi = (uint32_t)__bfloat16_as_ushort(ah) | ((uint32_t)__bfloat16_as_ushort(bh) << 16);
    lo = (uint32_t)__bfloat16_as_ushort(al) | ((uint32_t)__bfloat16_as_ushort(bl) << 16);
}

// ===========================================================================
// Prep: W1T / W2T bf16 split
// ===========================================================================
__global__ void prep_w1t_kernel(const float* __restrict__ W1)
{
    int i = blockIdx.x * blockDim.x + threadIdx.x;
    if (i >= NHID * NFEAT) return;
    int n = i / NFEAT, k = i % NFEAT;
    float v = W1[(size_t)k * NHID + n];
    __nv_bfloat16 h = __float2bfloat16(v);
    g_w1t_hi[i] = h;
    g_w1t_lo[i] = __float2bfloat16(v - __bfloat162float(h));
}

__global__ void prep_w2t_kernel(const float* __restrict__ W2)
{
    int i = blockIdx.x * blockDim.x + threadIdx.x;
    if (i >= NCLASS * NHID) return;
    int n = i / NHID, k = i % NHID;
    float v = W2[(size_t)k * NCLASS + n];
    __nv_bfloat16 h = __float2bfloat16(v);
    g_w2t_hi[i] = h;
    g_w2t_lo[i] = __float2bfloat16(v - __bfloat162float(h));
}

// ===========================================================================
// GEMM1 (mma.sync HMMA): h = relu(x @ W1 + b1), bf16 2-split, fp32 acc
// CTA 128x256, 512 threads / 16 warps (4m x 4n), warp tile 32x64.
// K staged at 32, double buffered.
// ===========================================================================
#define G1_BM 128
#define G1_BN 256
#define G1_BK 32
#define G1_STAGES (NFEAT / G1_BK)      // 16
#define G1_A_OFF 0
#define G1_B_OFF 16384
#define G1_STAGE_BYTES 49152
#define G1_SMEM (2 * G1_STAGE_BYTES)   // 98304

__global__ void __launch_bounds__(512, 1) gemm1_mma_kernel(
    const float* __restrict__ A,
    const float* __restrict__ bias,
    float* __restrict__ C)
{
    extern __shared__ char smem[];
    const uint32_t sbase = smem_u32(smem);
    const int tid  = threadIdx.x;
    const int wid  = tid >> 5;
    const int lane = tid & 31;
    const int rowBase = blockIdx.x * G1_BM;

    const int warp_m = wid & 3;
    const int warp_n = wid >> 2;
    const int m0 = warp_m * 32;
    const int n0 = warp_n * 64;

    float acc[2][8][4];
    #pragma unroll
    for (int i = 0; i < 2; i++)
        #pragma unroll
        for (int j = 0; j < 8; j++)
            #pragma unroll
            for (int q = 0; q < 4; q++) acc[i][j][q] = 0.f;

    const int agr = tid >> 2;
    const int akq = tid & 3;
    const int bn0 = tid >> 2;
    const int bn1 = (tid + 512) >> 2;
    const int bkq = tid & 3;

    float a_st[8];

    auto ldgA = [&](int k0) {
        int gr = rowBase + agr;
        if (gr < N_NODES) {
            const float* p = A + (size_t)gr * NFEAT + k0 + akq * 8;
            float4 v0 = *(const float4*)p;
            float4 v1 = *(const float4*)(p + 4);
            a_st[0]=v0.x; a_st[1]=v0.y; a_st[2]=v0.z; a_st[3]=v0.w;
            a_st[4]=v1.x; a_st[5]=v1.y; a_st[6]=v1.z; a_st[7]=v1.w;
        } else {
            #pragma unroll
            for (int q = 0; q < 8; q++) a_st[q] = 0.f;
        }
    };
    auto cpB = [&](int k0, int stage) {
        uint32_t bb = sbase + stage * G1_STAGE_BYTES + G1_B_OFF;
        size_t gi0 = (size_t)bn0 * NFEAT + k0 + bkq * 8;
        size_t gi1 = (size_t)bn1 * NFEAT + k0 + bkq * 8;
        uint32_t off0 = bn0 * 128 + bkq * 16;
        uint32_t off1 = bn1 * 128 + bkq * 16;
        cpasync16(bb + sw128(off0),      g_w1t_hi + gi0);
        cpasync16(bb + sw128(off0 + 64), g_w1t_lo + gi0);
        cpasync16(bb + sw128(off1),      g_w1t_hi + gi1);
        cpasync16(bb + sw128(off1 + 64), g_w1t_lo + gi1);
        CP_COMMIT();
    };
    auto stsA = [&](int stage) {
        uint4 hq, lq;
        split2p(a_st[0], a_st[1], hq.x, lq.x);
        split2p(a_st[2], a_st[3], hq.y, lq.y);
        split2p(a_st[4], a_st[5], hq.z, lq.z);
        split2p(a_st[6], a_st[7], hq.w, lq.w);
        uint32_t offh = agr * 128 + akq * 16;
        char* ab = smem + stage * G1_STAGE_BYTES + G1_A_OFF;
        *(uint4*)(ab + sw128(offh))      = hq;
        *(uint4*)(ab + sw128(offh + 64)) = lq;
    };

    auto compute = [&](int stage) {
        uint32_t ab = sbase + stage * G1_STAGE_BYTES + G1_A_OFF;
        uint32_t bb = sbase + stage * G1_STAGE_BYTES + G1_B_OFF;
        const int q  = lane >> 3;
        const int rr = lane & 7;
        #pragma unroll
        for (int k16 = 0; k16 < 2; k16++) {
            int cb = k16 * 2;
            uint32_t ah[2][4], al[2][4];
            #pragma unroll
            for (int mi = 0; mi < 2; mi++) {
                int row = m0 + mi * 16 + (q & 1) * 8 + rr;
                uint32_t offh = row * 128 + (cb + (q >> 1)) * 16;
                ldsm4(ab + sw128(offh), ah[mi]);
                ldsm4(ab + sw128(offh + 64), al[mi]);
            }
            #pragma unroll
            for (int nj = 0; nj < 4; nj++) {
                uint32_t bh[4], bl[4];
                int row = n0 + nj * 16 + (q & 1) * 8 + rr;
                uint32_t offh = row * 128 + (cb + (q >> 1)) * 16;
                ldsm4(bb + sw128(offh), bh);
                ldsm4(bb + sw128(offh + 64), bl);
                #pragma unroll
                for (int mi = 0; mi < 2; mi++)
                    #pragma unroll
                    for (int hh = 0; hh < 2; hh++) {
                        float* cc = acc[mi][nj * 2 + hh];
                        mma16816(cc, ah[mi], bh[hh], bh[2 + hh]);
                        mma16816(cc, ah[mi], bl[hh], bl[2 + hh]);
                        mma16816(cc, al[mi], bh[hh], bh[2 + hh]);
                    }
            }
        }
    };

    ldgA(0); cpB(0, 0); stsA(0);
    CP_WAIT0();
    __syncthreads();

    for (int s = 0; s < G1_STAGES; s++) {
        if (s + 1 < G1_STAGES) {
            ldgA((s + 1) * G1_BK);
            cpB((s + 1) * G1_BK, (s + 1) & 1);
        }
        compute(s & 1);
        if (s + 1 < G1_STAGES) {
            stsA((s + 1) & 1);
            CP_WAIT0();
            __syncthreads();
        }
    }

    const float bval = bias[0];
    const int g  = lane >> 2;
    const int tq = lane & 3;
    #pragma unroll
    for (int mi = 0; mi < 2; mi++)
        #pragma unroll
        for (int nt = 0; nt < 8; nt++) {
            int row = m0 + mi * 16 + g;
            int col = n0 + nt * 8 + tq * 2;
            int gr0 = rowBase + row;
            int gr1 = gr0 + 8;
            float* cc = acc[mi][nt];
            if (gr0 < N_NODES) {
                float2 o;
                o.x = fmaxf(cc[0] + bval, 0.f);
                o.y = fmaxf(cc[1] + bval, 0.f);
                *(float2*)(C + (size_t)gr0 * NHID + col) = o;
            }
            if (gr1 < N_NODES) {
                float2 o;
                o.x = fmaxf(cc[2] + bval, 0.f);
                o.y = fmaxf(cc[3] + bval, 0.f);
                *(float2*)(C + (size_t)gr1 * NHID + col) = o;
            }
        }
}

// ===========================================================================
// GEMM2 (mma.sync HMMA): h2 = h @ W2 + b2, bf16 2-split, fp32 acc
// CTA 128 rows, 256 threads / 8 warps, warp = 16 rows x 40 cols.
// K = 256 in 8 k32 chunks; W2 tiles fully smem-resident; A double-buffered.
// smem: A stages 2x16384 = 32768; W2 8 chunks x 6144 (48 rows x 128B) = 49152.
// ===========================================================================
#define G2_A_ST   16384
#define G2_W2_OFF 32768
#define G2_W2_CH  6144
#define G2_SMEM   (32768 + 8 * G2_W2_CH)   // 81920

__global__ void __launch_bounds__(256, 1) gemm2_mma_kernel(
    const float* __restrict__ A,      // g_h [N, 256]
    const float* __restrict__ bias,
    float* __restrict__ C)            // g_h2 [N, 40]
{
    extern __shared__ char smem[];
    const uint32_t sbase = smem_u32(smem);
    const int tid  = threadIdx.x;
    const int wid  = tid >> 5;        // 0..7  -> rows wid*16..+16
    const int lane = tid & 31;
    const int rowBase = blockIdx.x * 128;
    const int m0 = wid * 16;

    // async-load all W2 chunk tiles (8 chunks x 40 rows x 8 segs x 16B)
    for (int idx = tid; idx < 8 * 40 * 8; idx += 256) {
        int ch  = idx / 320;
        int rem = idx - ch * 320;
        int n   = rem >> 3;
        int seg = rem & 7;
        const __nv_bfloat16* src =
            (seg < 4 ? g_w2t_hi : g_w2t_lo) + (size_t)n * NHID + ch * 32 + (seg & 3) * 8;
        uint32_t off = n * 128 + (seg < 4 ? (seg & 3) * 16 : 64 + (seg & 3) * 16);
        cpasync16(sbase + G2_W2_OFF + ch * G2_W2_CH + sw128(off), src);
    }
    CP_COMMIT();

    float acc[5][4];
    #pragma unroll
    for (int j = 0; j < 5; j++)
        #pragma unroll
        for (int q = 0; q < 4; q++) acc[j][q] = 0.f;

    float a_st[16];
    auto ldgA = [&](int k0) {
        #pragma unroll
        for (int it = 0; it < 2; it++) {
            int g  = tid + it * 256;
            int r  = g >> 2;
            int oq = g & 3;
            int gr = rowBase + r;
            if (gr < N_NODES) {
                const float* p = A + (size_t)gr * NHID + k0 + oq * 8;
                float4 v0 = *(const float4*)p;
                float4 v1 = *(const float4*)(p + 4);
                a_st[it*8+0]=v0.x; a_st[it*8+1]=v0.y; a_st[it*8+2]=v0.z; a_st[it*8+3]=v0.w;
                a_st[it*8+4]=v1.x; a_st[it*8+5]=v1.y; a_st[it*8+6]=v1.z; a_st[it*8+7]=v1.w;
            } else {
                #pragma unroll
                for (int q = 0; q < 8; q++) a_st[it*8+q] = 0.f;
            }
        }
    };
    auto stsA = [&](int stage) {
        #pragma unroll
        for (int it = 0; it < 2; it++) {
            int g  = tid + it * 256;
            int r  = g >> 2;
            int oq = g & 3;
            uint4 hq, lq;
            split2p(a_st[it*8+0], a_st[it*8+1], hq.x, lq.x);
            split2p(a_st[it*8+2], a_st[it*8+3], hq.y, lq.y);
            split2p(a_st[it*8+4], a_st[it*8+5], hq.z, lq.z);
            split2p(a_st[it*8+6], a_st[it*8+7], hq.w, lq.w);
            uint32_t offh = r * 128 + oq * 16;
            char* ab = smem + stage * G2_A_ST;
            *(uint4*)(ab + sw128(offh))      = hq;
            *(uint4*)(ab + sw128(offh + 64)) = lq;
        }
    };

    auto compute = [&](int stage, int ch) {
        uint32_t ab = sbase + stage * G2_A_ST;
        uint32_t bb = sbase + G2_W2_OFF + ch * G2_W2_CH;
        const int q  = lane >> 3;
        const int rr = lane & 7;
        #pragma unroll
        for (int k16 = 0; k16 < 2; k16++) {
            int cb = k16 * 2;
            uint32_t ah[4], al[4];
            {
                int row = m0 + (q & 1) * 8 + rr;
                uint32_t offh = row * 128 + (cb + (q >> 1)) * 16;
                ldsm4(ab + sw128(offh), ah);
                ldsm4(ab + sw128(offh + 64), al);
            }
            uint32_t bh[3][4], bl[3][4];
            #pragma unroll
            for (int nj = 0; nj < 3; nj++) {
                int row = nj * 16 + (q & 1) * 8 + rr;
                uint32_t offh = row * 128 + (cb + (q >> 1)) * 16;
                ldsm4(bb + sw128(offh), bh[nj]);
                ldsm4(bb + sw128(offh + 64), bl[nj]);
            }
            #pragma unroll
            for (int nt = 0; nt < 5; nt++) {
                int nj = nt >> 1, hh = nt & 1;
                mma16816(acc[nt], ah, bh[nj][hh], bh[nj][2 + hh]);
                mma16816(acc[nt], ah, bl[nj][hh], bl[nj][2 + hh]);
                mma16816(acc[nt], al, bh[nj][hh], bh[nj][2 + hh]);
            }
        }
    };

    ldgA(0); stsA(0);
    CP_WAIT0();
    __syncthreads();

    for (int ch = 0; ch < 8; ch++) {
        if (ch + 1 < 8) ldgA((ch + 1) * 32);
        compute(ch & 1, ch);
        if (ch + 1 < 8) {
            stsA((ch + 1) & 1);
            __syncthreads();
        }
    }

    const float bval = bias[0];
    const int g  = lane >> 2;
    const int tq = lane & 3;
    #pragma unroll
    for (int nt = 0; nt < 5; nt++) {
        int col = nt * 8 + tq * 2;
        int gr0 = rowBase + m0 + g;
        int gr1 = gr0 + 8;
        if (gr0 < N_NODES) {
            float2 o; o.x = acc[nt][0] + bval; o.y = acc[nt][1] + bval;
            *(float2*)(C + (size_t)gr0 * NCLASS + col) = o;
        }
        if (gr1 < N_NODES) {
            float2 o; o.x = acc[nt][2] + bval; o.y = acc[nt][3] + bval;
            *(float2*)(C + (size_t)gr1 * NCLASS + col) = o;
        }
    }
}

// ---------------------------------------------------------------------------
// CSR build: histogram -> 2-level exclusive scan -> scatter
// ---------------------------------------------------------------------------
__global__ void zero_counts_kernel()
{
    int i = blockIdx.x * blockDim.x + threadIdx.x;
    if (i < N_NODES) g_cnt[i] = 0;
}

__global__ void histogram_kernel(const int* __restrict__ row)
{
    int e = blockIdx.x * blockDim.x + threadIdx.x;
    if (e < E_EDGES) atomicAdd(&g_cnt[row[e]], 1);
}

__global__ void __launch_bounds__(SCAN_BLK) scan1_kernel()
{
    __shared__ int s[SCAN_BLK];
    int gid = blockIdx.x * SCAN_BLK + threadIdx.x;
    int x = (gid < N_NODES) ? g_cnt[gid] : 0;
    s[threadIdx.x] = x;
    __syncthreads();
    #pragma unroll
    for (int d = 1; d < SCAN_BLK; d <<= 1) {
        int t = (threadIdx.x >= d) ? s[threadIdx.x - d] : 0;
        __syncthreads();
        s[threadIdx.x] += t;
        __syncthreads();
    }
    if (gid < N_NODES) g_offl[gid] = s[threadIdx.x] - x;
    if (threadIdx.x == SCAN_BLK - 1) g_blk[blockIdx.x] = s[SCAN_BLK - 1];
}

__global__ void scan2_kernel()
{
    __shared__ int s[128];
    int tid = threadIdx.x;
    int x = (tid < NUM_SCAN_BLKS) ? g_blk[tid] : 0;
    s[tid] = x;
    __syncthreads();
    #pragma unroll
    for (int d = 1; d < 128; d <<= 1) {
        int t = (tid >= d) ? s[tid - d] : 0;
        __syncthreads();
        s[tid] += t;
        __syncthreads();
    }
    if (tid < NUM_SCAN_BLKS) g_blkoff[tid] = s[tid] - x;
}

__global__ void scan3_kernel()
{
    int i = blockIdx.x * blockDim.x + threadIdx.x;
    if (i < N_NODES) {
        int st = g_offl[i] + g_blkoff[i / SCAN_BLK];
        g_start[i]  = st;
        g_cursor[i] = st;
    }
    if (i == 0) g_start[N_NODES] = E_EDGES;
}

__global__ void scatter_kernel(const int* __restrict__ row,
                               const int* __restrict__ col,
                               const float* __restrict__ vals)
{
    int e = blockIdx.x * blockDim.x + threadIdx.x;
    if (e >= E_EDGES) return;
    int r = row[e];
    int pos = atomicAdd(&g_cursor[r], 1);
    int2 ev;
    ev.x = col[e];
    ev.y = __float_as_int((1.0f - ALPHA) * vals[e]);
    g_edges[pos] = ev;
}

// ---------------------------------------------------------------------------
// Pull-mode SpMM + alpha blend (atomic-free), edge loop unrolled x2 for MLP
// ---------------------------------------------------------------------------
__global__ void __launch_bounds__(256) spmm_csr_kernel(
    const float* __restrict__ z,
    const float* __restrict__ h2,
    float* __restrict__ znew)
{
    int r = blockIdx.x * blockDim.x + threadIdx.x;
    if (r >= N_NODES) return;

    int e0 = g_start[r];
    int e1 = g_start[r + 1];

    float4 acc[NCLASS / 4];
    #pragma unroll
    for (int t = 0; t < NCLASS / 4; t++)
        acc[t] = make_float4(0.f, 0.f, 0.f, 0.f);

    int e = e0;
    for (; e + 2 <= e1; e += 2) {
        int2 ev0 = g_edges[e];
        int2 ev1 = g_edges[e + 1];
        float v0 = __int_as_float(ev0.y);
        float v1 = __int_as_float(ev1.y);
        const float4* z0 = (const float4*)(z + (size_t)ev0.x * NCLASS);
        const float4* z1 = (const float4*)(z + (size_t)ev1.x * NCLASS);
        #pragma unroll
        for (int t = 0; t < NCLASS / 4; t++) {
            float4 a0 = z0[t];
            float4 a1 = z1[t];
            acc[t].x += v0 * a0.x + v1 * a1.x;
            acc[t].y += v0 * a0.y + v1 * a1.y;
            acc[t].z += v0 * a0.z + v1 * a1.z;
            acc[t].w += v0 * a0.w + v1 * a1.w;
        }
    }
    if (e < e1) {
        int2 ev = g_edges[e];
        float v = __int_as_float(ev.y);
        const float4* zp = (const float4*)(z + (size_t)ev.x * NCLASS);
        #pragma unroll
        for (int t = 0; t < NCLASS / 4; t++) {
            float4 a = zp[t];
            acc[t].x += v * a.x;
            acc[t].y += v * a.y;
            acc[t].z += v * a.z;
            acc[t].w += v * a.w;
        }
    }

    const float4* hp = (const float4*)(h2 + (size_t)r * NCLASS);
    float4* op = (float4*)(znew + (size_t)r * NCLASS);
    #pragma unroll
    for (int t = 0; t < NCLASS / 4; t++) {
        float4 hv = hp[t];
        float4 o;
        o.x = acc[t].x + ALPHA * hv.x;
        o.y = acc[t].y + ALPHA * hv.y;
        o.z = acc[t].z + ALPHA * hv.z;
        o.w = acc[t].w + ALPHA * hv.w;
        op[t] = o;
    }
}

// ---------------------------------------------------------------------------
// Row-wise log_softmax over 40 classes: one warp per row
// ---------------------------------------------------------------------------
__global__ void logsoftmax_kernel(const float* __restrict__ z,
                                  float* __restrict__ out)
{
    int gtid = blockIdx.x * blockDim.x + threadIdx.x;
    int warp = gtid / 32;
    int lane = gtid % 32;
    if (warp >= N_NODES) return;

    const float* zr = z + (size_t)warp * NCLASS;
    float v0 = zr[lane];
    float v1 = (lane < NCLASS - 32) ? zr[lane + 32] : -INFINITY;

    float m = fmaxf(v0, v1);
    #pragma unroll
    for (int o = 16; o > 0; o >>= 1)
        m = fmaxf(m, __shfl_xor_sync(0xFFFFFFFFu, m, o));

    float s = expf(v0 - m) + ((lane < NCLASS - 32) ? expf(v1 - m) : 0.f);
    #pragma unroll
    for (int o = 16; o > 0; o >>= 1)
        s += __shfl_xor_sync(0xFFFFFFFFu, s, o);

    float L = m + logf(s);
    out[(size_t)warp * NCLASS + lane] = v0 - L;
    if (lane < NCLASS - 32)
        out[(size_t)warp * NCLASS + lane + 32] = v1 - L;
}

// ---------------------------------------------------------------------------
extern "C" void kernel_launch(void* const* d_in, const int* in_sizes, int n_in,
                              void* d_out, int out_size)
{
    const float* x    = (const float*)d_in[0];
    const int*   row  = (const int*)  d_in[1];
    const int*   col  = (const int*)  d_in[2];
    const float* vals = (const float*)d_in[3];
    const float* W1   = (const float*)d_in[4];
    const float* b1   = (const float*)d_in[5];
    const float* W2   = (const float*)d_in[6];
    const float* b2   = (const float*)d_in[7];
    float* out = (float*)d_out;

    float *h, *h2, *za, *zb;
    cudaGetSymbolAddress((void**)&h,  g_h);
    cudaGetSymbolAddress((void**)&h2, g_h2);
    cudaGetSymbolAddress((void**)&za, g_za);
    cudaGetSymbolAddress((void**)&zb, g_zb);

    cudaFuncSetAttribute(gemm1_mma_kernel,
                         cudaFuncAttributeMaxDynamicSharedMemorySize, G1_SMEM);
    cudaFuncSetAttribute(gemm2_mma_kernel,
                         cudaFuncAttributeMaxDynamicSharedMemorySize, G2_SMEM);

    // Launch order: gemm1 is our 4th launch (observed: ncu profiles our #4).
    prep_w1t_kernel<<<(NHID * NFEAT + 255) / 256, 256>>>(W1);              // 1
    prep_w2t_kernel<<<(NCLASS * NHID + 255) / 256, 256>>>(W2);             // 2
    zero_counts_kernel<<<(N_NODES + 255) / 256, 256>>>();                  // 3
    gemm1_mma_kernel<<<(N_NODES + G1_BM - 1) / G1_BM, 512, G1_SMEM>>>(x, b1, h); // 4
    histogram_kernel<<<(E_EDGES + 255) / 256, 256>>>(row);                 // 5
    scan1_kernel<<<NUM_SCAN_BLKS, SCAN_BLK>>>();                           // 6
    scan2_kernel<<<1, 128>>>();                                            // 7
    scan3_kernel<<<(N_NODES + 255) / 256, 256>>>();                        // 8
    scatter_kernel<<<(E_EDGES + 255) / 256, 256>>>(row, col, vals);        // 9
    gemm2_mma_kernel<<<(N_NODES + 127) / 128, 256, G2_SMEM>>>(h, b2, h2);  // 10

    // APPNP propagation
    const float* zin = h2;
    float* bufs[2] = { za, zb };
    for (int it = 0; it < NLAYERS; it++) {
        float* zout = bufs[it & 1];
        spmm_csr_kernel<<<(N_NODES + 255) / 256, 256>>>(zin, h2, zout);
        zin = zout;
    }

    logsoftmax_kernel<<<(N_NODES * 32 + 255) / 256, 256>>>(zin, out);
}

// round 7
// speedup vs baseline: 2.7429x; 1.5630x over previous
#include <cuda_runtime.h>
#include <cuda_bf16.h>
#include <math.h>
#include <stdint.h>

#define N_NODES 100000
#define E_EDGES 1600000
#define NFEAT   512
#define NHID    256
#define NCLASS  40
#define NLAYERS 10
#define ALPHA   0.1f

#define SCAN_BLK 1024
#define NUM_SCAN_BLKS ((N_NODES + SCAN_BLK - 1) / SCAN_BLK)   // 98

// Scratch (static device globals — allocation-free rule)
__device__ float g_h [N_NODES * NHID];    // relu(x@W1+b1)
__device__ float g_h2[N_NODES * NCLASS];  // h@W2+b2  (z_0)
__device__ float g_za[N_NODES * NCLASS];
__device__ float g_zb[N_NODES * NCLASS];

// W1 transposed + bf16-split: [NHID][NFEAT]
__device__ __nv_bfloat16 g_w1t_hi[NHID * NFEAT];
__device__ __nv_bfloat16 g_w1t_lo[NHID * NFEAT];
// W2 transposed + bf16-split: [NCLASS][NHID]
__device__ __nv_bfloat16 g_w2t_hi[NCLASS * NHID];
__device__ __nv_bfloat16 g_w2t_lo[NCLASS * NHID];

// CSR build scratch
__device__ int  g_cnt   [N_NODES];
__device__ int  g_offl  [N_NODES];
__device__ int  g_start [N_NODES + 1];
__device__ int  g_cursor[N_NODES];
__device__ int  g_blk   [NUM_SCAN_BLKS];
__device__ int  g_blkoff[NUM_SCAN_BLKS];
__device__ int2 g_edges [E_EDGES];

// ===========================================================================
// helpers (baseline PTX only: ldmatrix / mma.sync / cp.async)
// ===========================================================================
__device__ __forceinline__ uint32_t smem_u32(const void* p) {
    uint32_t a;
    asm("{ .reg .u64 t; cvta.to.shared.u64 t, %1; cvt.u32.u64 %0, t; }"
        : "=r"(a) : "l"(p));
    return a;
}

__device__ __forceinline__ void ldsm4(uint32_t addr, uint32_t* r) {
    asm volatile("ldmatrix.sync.aligned.m8n8.x4.shared.b16 {%0,%1,%2,%3}, [%4];"
        : "=r"(r[0]), "=r"(r[1]), "=r"(r[2]), "=r"(r[3]) : "r"(addr));
}

__device__ __forceinline__ void mma16816(float* c, const uint32_t* a,
                                         uint32_t b0, uint32_t b1) {
    asm volatile(
        "mma.sync.aligned.m16n8k16.row.col.f32.bf16.bf16.f32 "
        "{%0,%1,%2,%3}, {%4,%5,%6,%7}, {%8,%9}, {%0,%1,%2,%3};"
        : "+f"(c[0]), "+f"(c[1]), "+f"(c[2]), "+f"(c[3])
        : "r"(a[0]), "r"(a[1]), "r"(a[2]), "r"(a[3]), "r"(b0), "r"(b1));
}

__device__ __forceinline__ void cpasync16(uint32_t saddr, const void* gptr) {
    asm volatile("cp.async.cg.shared.global [%0], [%1], 16;"
                 :: "r"(saddr), "l"(gptr) : "memory");
}
#define CP_COMMIT() asm volatile("cp.async.commit_group;" ::: "memory")
#define CP_WAIT0()  asm volatile("cp.async.wait_group 0;" ::: "memory")

__device__ __forceinline__ uint32_t sw128(uint32_t off) {
    return off ^ ((off >> 3) & 0x70);
}

__device__ __forceinline__ void split2p(float a, float b, uint32_t& hi, uint32_t& lo) {
    __nv_bfloat16 ah = __float2bfloat16(a);
    __nv_bfloat16 bh = __float2bfloat16(b);
    __nv_bfloat16 al = __float2bfloat16(a - __bfloat162float(ah));
    __nv_bfloat16 bl = __float2bfloat16(b - __bfloat162float(bh));
    hi = (uint32_t)__bfloat16_as_ushort(ah) | ((uint32_t)__bfloat16_as_ushort(bh) << 16);
    lo = (uint32_t)__bfloat16_as_ushort(al) | ((uint32_t)__bfloat16_as_ushort(bl) << 16);
}

// ===========================================================================
// Prep: W1T / W2T bf16 split
// ===========================================================================
__global__ void prep_w1t_kernel(const float* __restrict__ W1)
{
    int i = blockIdx.x * blockDim.x + threadIdx.x;
    if (i >= NHID * NFEAT) return;
    int n = i / NFEAT, k = i % NFEAT;
    float v = W1[(size_t)k * NHID + n];
    __nv_bfloat16 h = __float2bfloat16(v);
    g_w1t_hi[i] = h;
    g_w1t_lo[i] = __float2bfloat16(v - __bfloat162float(h));
}

__global__ void prep_w2t_kernel(const float* __restrict__ W2)
{
    int i = blockIdx.x * blockDim.x + threadIdx.x;
    if (i >= NCLASS * NHID) return;
    int n = i / NHID, k = i % NHID;
    float v = W2[(size_t)k * NCLASS + n];
    __nv_bfloat16 h = __float2bfloat16(v);
    g_w2t_hi[i] = h;
    g_w2t_lo[i] = __float2bfloat16(v - __bfloat162float(h));
}

// ===========================================================================
// GEMM1 (mma.sync HMMA): h = relu(x @ W1 + b1), bf16 2-split, fp32 acc
// CTA 128x256, 512 threads / 16 warps (4m x 4n), warp tile 32x64.
// K staged at 32, double buffered.
// ===========================================================================
#define G1_BM 128
#define G1_BN 256
#define G1_BK 32
#define G1_STAGES (NFEAT / G1_BK)      // 16
#define G1_A_OFF 0
#define G1_B_OFF 16384
#define G1_STAGE_BYTES 49152
#define G1_SMEM (2 * G1_STAGE_BYTES)   // 98304

__global__ void __launch_bounds__(512, 1) gemm1_mma_kernel(
    const float* __restrict__ A,
    const float* __restrict__ bias,
    float* __restrict__ C)
{
    extern __shared__ char smem[];
    const uint32_t sbase = smem_u32(smem);
    const int tid  = threadIdx.x;
    const int wid  = tid >> 5;
    const int lane = tid & 31;
    const int rowBase = blockIdx.x * G1_BM;

    const int warp_m = wid & 3;
    const int warp_n = wid >> 2;
    const int m0 = warp_m * 32;
    const int n0 = warp_n * 64;

    float acc[2][8][4];
    #pragma unroll
    for (int i = 0; i < 2; i++)
        #pragma unroll
        for (int j = 0; j < 8; j++)
            #pragma unroll
            for (int q = 0; q < 4; q++) acc[i][j][q] = 0.f;

    const int agr = tid >> 2;
    const int akq = tid & 3;
    const int bn0 = tid >> 2;
    const int bn1 = (tid + 512) >> 2;
    const int bkq = tid & 3;

    float a_st[8];

    auto ldgA = [&](int k0) {
        int gr = rowBase + agr;
        if (gr < N_NODES) {
            const float* p = A + (size_t)gr * NFEAT + k0 + akq * 8;
            float4 v0 = *(const float4*)p;
            float4 v1 = *(const float4*)(p + 4);
            a_st[0]=v0.x; a_st[1]=v0.y; a_st[2]=v0.z; a_st[3]=v0.w;
            a_st[4]=v1.x; a_st[5]=v1.y; a_st[6]=v1.z; a_st[7]=v1.w;
        } else {
            #pragma unroll
            for (int q = 0; q < 8; q++) a_st[q] = 0.f;
        }
    };
    auto cpB = [&](int k0, int stage) {
        uint32_t bb = sbase + stage * G1_STAGE_BYTES + G1_B_OFF;
        size_t gi0 = (size_t)bn0 * NFEAT + k0 + bkq * 8;
        size_t gi1 = (size_t)bn1 * NFEAT + k0 + bkq * 8;
        uint32_t off0 = bn0 * 128 + bkq * 16;
        uint32_t off1 = bn1 * 128 + bkq * 16;
        cpasync16(bb + sw128(off0),      g_w1t_hi + gi0);
        cpasync16(bb + sw128(off0 + 64), g_w1t_lo + gi0);
        cpasync16(bb + sw128(off1),      g_w1t_hi + gi1);
        cpasync16(bb + sw128(off1 + 64), g_w1t_lo + gi1);
        CP_COMMIT();
    };
    auto stsA = [&](int stage) {
        uint4 hq, lq;
        split2p(a_st[0], a_st[1], hq.x, lq.x);
        split2p(a_st[2], a_st[3], hq.y, lq.y);
        split2p(a_st[4], a_st[5], hq.z, lq.z);
        split2p(a_st[6], a_st[7], hq.w, lq.w);
        uint32_t offh = agr * 128 + akq * 16;
        char* ab = smem + stage * G1_STAGE_BYTES + G1_A_OFF;
        *(uint4*)(ab + sw128(offh))      = hq;
        *(uint4*)(ab + sw128(offh + 64)) = lq;
    };

    auto compute = [&](int stage) {
        uint32_t ab = sbase + stage * G1_STAGE_BYTES + G1_A_OFF;
        uint32_t bb = sbase + stage * G1_STAGE_BYTES + G1_B_OFF;
        const int q  = lane >> 3;
        const int rr = lane & 7;
        #pragma unroll
        for (int k16 = 0; k16 < 2; k16++) {
            int cb = k16 * 2;
            uint32_t ah[2][4], al[2][4];
            #pragma unroll
            for (int mi = 0; mi < 2; mi++) {
                int row = m0 + mi * 16 + (q & 1) * 8 + rr;
                uint32_t offh = row * 128 + (cb + (q >> 1)) * 16;
                ldsm4(ab + sw128(offh), ah[mi]);
                ldsm4(ab + sw128(offh + 64), al[mi]);
            }
            #pragma unroll
            for (int nj = 0; nj < 4; nj++) {
                uint32_t bh[4], bl[4];
                int row = n0 + nj * 16 + (q & 1) * 8 + rr;
                uint32_t offh = row * 128 + (cb + (q >> 1)) * 16;
                ldsm4(bb + sw128(offh), bh);
                ldsm4(bb + sw128(offh + 64), bl);
                #pragma unroll
                for (int mi = 0; mi < 2; mi++)
                    #pragma unroll
                    for (int hh = 0; hh < 2; hh++) {
                        float* cc = acc[mi][nj * 2 + hh];
                        mma16816(cc, ah[mi], bh[hh], bh[2 + hh]);
                        mma16816(cc, ah[mi], bl[hh], bl[2 + hh]);
                        mma16816(cc, al[mi], bh[hh], bh[2 + hh]);
                    }
            }
        }
    };

    ldgA(0); cpB(0, 0); stsA(0);
    CP_WAIT0();
    __syncthreads();

    for (int s = 0; s < G1_STAGES; s++) {
        if (s + 1 < G1_STAGES) {
            ldgA((s + 1) * G1_BK);
            cpB((s + 1) * G1_BK, (s + 1) & 1);
        }
        compute(s & 1);
        if (s + 1 < G1_STAGES) {
            stsA((s + 1) & 1);
            CP_WAIT0();
            __syncthreads();
        }
    }

    const float bval = bias[0];
    const int g  = lane >> 2;
    const int tq = lane & 3;
    #pragma unroll
    for (int mi = 0; mi < 2; mi++)
        #pragma unroll
        for (int nt = 0; nt < 8; nt++) {
            int row = m0 + mi * 16 + g;
            int col = n0 + nt * 8 + tq * 2;
            int gr0 = rowBase + row;
            int gr1 = gr0 + 8;
            float* cc = acc[mi][nt];
            if (gr0 < N_NODES) {
                float2 o;
                o.x = fmaxf(cc[0] + bval, 0.f);
                o.y = fmaxf(cc[1] + bval, 0.f);
                *(float2*)(C + (size_t)gr0 * NHID + col) = o;
            }
            if (gr1 < N_NODES) {
                float2 o;
                o.x = fmaxf(cc[2] + bval, 0.f);
                o.y = fmaxf(cc[3] + bval, 0.f);
                *(float2*)(C + (size_t)gr1 * NHID + col) = o;
            }
        }
}

// ===========================================================================
// GEMM2 (mma.sync HMMA): h2 = h @ W2 + b2, bf16 2-split, fp32 acc
// ===========================================================================
#define G2_A_ST   16384
#define G2_W2_OFF 32768
#define G2_W2_CH  6144
#define G2_SMEM   (32768 + 8 * G2_W2_CH)   // 81920

__global__ void __launch_bounds__(256, 1) gemm2_mma_kernel(
    const float* __restrict__ A,      // g_h [N, 256]
    const float* __restrict__ bias,
    float* __restrict__ C)            // g_h2 [N, 40]
{
    extern __shared__ char smem[];
    const uint32_t sbase = smem_u32(smem);
    const int tid  = threadIdx.x;
    const int wid  = tid >> 5;
    const int lane = tid & 31;
    const int rowBase = blockIdx.x * 128;
    const int m0 = wid * 16;

    for (int idx = tid; idx < 8 * 40 * 8; idx += 256) {
        int ch  = idx / 320;
        int rem = idx - ch * 320;
        int n   = rem >> 3;
        int seg = rem & 7;
        const __nv_bfloat16* src =
            (seg < 4 ? g_w2t_hi : g_w2t_lo) + (size_t)n * NHID + ch * 32 + (seg & 3) * 8;
        uint32_t off = n * 128 + (seg < 4 ? (seg & 3) * 16 : 64 + (seg & 3) * 16);
        cpasync16(sbase + G2_W2_OFF + ch * G2_W2_CH + sw128(off), src);
    }
    CP_COMMIT();

    float acc[5][4];
    #pragma unroll
    for (int j = 0; j < 5; j++)
        #pragma unroll
        for (int q = 0; q < 4; q++) acc[j][q] = 0.f;

    float a_st[16];
    auto ldgA = [&](int k0) {
        #pragma unroll
        for (int it = 0; it < 2; it++) {
            int g  = tid + it * 256;
            int r  = g >> 2;
            int oq = g & 3;
            int gr = rowBase + r;
            if (gr < N_NODES) {
                const float* p = A + (size_t)gr * NHID + k0 + oq * 8;
                float4 v0 = *(const float4*)p;
                float4 v1 = *(const float4*)(p + 4);
                a_st[it*8+0]=v0.x; a_st[it*8+1]=v0.y; a_st[it*8+2]=v0.z; a_st[it*8+3]=v0.w;
                a_st[it*8+4]=v1.x; a_st[it*8+5]=v1.y; a_st[it*8+6]=v1.z; a_st[it*8+7]=v1.w;
            } else {
                #pragma unroll
                for (int q = 0; q < 8; q++) a_st[it*8+q] = 0.f;
            }
        }
    };
    auto stsA = [&](int stage) {
        #pragma unroll
        for (int it = 0; it < 2; it++) {
            int g  = tid + it * 256;
            int r  = g >> 2;
            int oq = g & 3;
            uint4 hq, lq;
            split2p(a_st[it*8+0], a_st[it*8+1], hq.x, lq.x);
            split2p(a_st[it*8+2], a_st[it*8+3], hq.y, lq.y);
            split2p(a_st[it*8+4], a_st[it*8+5], hq.z, lq.z);
            split2p(a_st[it*8+6], a_st[it*8+7], hq.w, lq.w);
            uint32_t offh = r * 128 + oq * 16;
            char* ab = smem + stage * G2_A_ST;
            *(uint4*)(ab + sw128(offh))      = hq;
            *(uint4*)(ab + sw128(offh + 64)) = lq;
        }
    };

    auto compute = [&](int stage, int ch) {
        uint32_t ab = sbase + stage * G2_A_ST;
        uint32_t bb = sbase + G2_W2_OFF + ch * G2_W2_CH;
        const int q  = lane >> 3;
        const int rr = lane & 7;
        #pragma unroll
        for (int k16 = 0; k16 < 2; k16++) {
            int cb = k16 * 2;
            uint32_t ah[4], al[4];
            {
                int row = m0 + (q & 1) * 8 + rr;
                uint32_t offh = row * 128 + (cb + (q >> 1)) * 16;
                ldsm4(ab + sw128(offh), ah);
                ldsm4(ab + sw128(offh + 64), al);
            }
            uint32_t bh[3][4], bl[3][4];
            #pragma unroll
            for (int nj = 0; nj < 3; nj++) {
                int row = nj * 16 + (q & 1) * 8 + rr;
                uint32_t offh = row * 128 + (cb + (q >> 1)) * 16;
                ldsm4(bb + sw128(offh), bh[nj]);
                ldsm4(bb + sw128(offh + 64), bl[nj]);
            }
            #pragma unroll
            for (int nt = 0; nt < 5; nt++) {
                int nj = nt >> 1, hh = nt & 1;
                mma16816(acc[nt], ah, bh[nj][hh], bh[nj][2 + hh]);
                mma16816(acc[nt], ah, bl[nj][hh], bl[nj][2 + hh]);
                mma16816(acc[nt], al, bh[nj][hh], bh[nj][2 + hh]);
            }
        }
    };

    ldgA(0); stsA(0);
    CP_WAIT0();
    __syncthreads();

    for (int ch = 0; ch < 8; ch++) {
        if (ch + 1 < 8) ldgA((ch + 1) * 32);
        compute(ch & 1, ch);
        if (ch + 1 < 8) {
            stsA((ch + 1) & 1);
            __syncthreads();
        }
    }

    const float bval = bias[0];
    const int g  = lane >> 2;
    const int tq = lane & 3;
    #pragma unroll
    for (int nt = 0; nt < 5; nt++) {
        int col = nt * 8 + tq * 2;
        int gr0 = rowBase + m0 + g;
        int gr1 = gr0 + 8;
        if (gr0 < N_NODES) {
            float2 o; o.x = acc[nt][0] + bval; o.y = acc[nt][1] + bval;
            *(float2*)(C + (size_t)gr0 * NCLASS + col) = o;
        }
        if (gr1 < N_NODES) {
            float2 o; o.x = acc[nt][2] + bval; o.y = acc[nt][3] + bval;
            *(float2*)(C + (size_t)gr1 * NCLASS + col) = o;
        }
    }
}

// ---------------------------------------------------------------------------
// CSR build: histogram -> 2-level exclusive scan -> scatter
// ---------------------------------------------------------------------------
__global__ void zero_counts_kernel()
{
    int i = blockIdx.x * blockDim.x + threadIdx.x;
    if (i < N_NODES) g_cnt[i] = 0;
}

__global__ void histogram_kernel(const int* __restrict__ row)
{
    int e = blockIdx.x * blockDim.x + threadIdx.x;
    if (e < E_EDGES) atomicAdd(&g_cnt[row[e]], 1);
}

__global__ void __launch_bounds__(SCAN_BLK) scan1_kernel()
{
    __shared__ int s[SCAN_BLK];
    int gid = blockIdx.x * SCAN_BLK + threadIdx.x;
    int x = (gid < N_NODES) ? g_cnt[gid] : 0;
    s[threadIdx.x] = x;
    __syncthreads();
    #pragma unroll
    for (int d = 1; d < SCAN_BLK; d <<= 1) {
        int t = (threadIdx.x >= d) ? s[threadIdx.x - d] : 0;
        __syncthreads();
        s[threadIdx.x] += t;
        __syncthreads();
    }
    if (gid < N_NODES) g_offl[gid] = s[threadIdx.x] - x;
    if (threadIdx.x == SCAN_BLK - 1) g_blk[blockIdx.x] = s[SCAN_BLK - 1];
}

__global__ void scan2_kernel()
{
    __shared__ int s[128];
    int tid = threadIdx.x;
    int x = (tid < NUM_SCAN_BLKS) ? g_blk[tid] : 0;
    s[tid] = x;
    __syncthreads();
    #pragma unroll
    for (int d = 1; d < 128; d <<= 1) {
        int t = (tid >= d) ? s[tid - d] : 0;
        __syncthreads();
        s[tid] += t;
        __syncthreads();
    }
    if (tid < NUM_SCAN_BLKS) g_blkoff[tid] = s[tid] - x;
}

__global__ void scan3_kernel()
{
    int i = blockIdx.x * blockDim.x + threadIdx.x;
    if (i < N_NODES) {
        int st = g_offl[i] + g_blkoff[i / SCAN_BLK];
        g_start[i]  = st;
        g_cursor[i] = st;
    }
    if (i == 0) g_start[N_NODES] = E_EDGES;
}

__global__ void scatter_kernel(const int* __restrict__ row,
                               const int* __restrict__ col,
                               const float* __restrict__ vals)
{
    int e = blockIdx.x * blockDim.x + threadIdx.x;
    if (e >= E_EDGES) return;
    int r = row[e];
    int pos = atomicAdd(&g_cursor[r], 1);
    int2 ev;
    ev.x = col[e];
    ev.y = __float_as_int((1.0f - ALPHA) * vals[e]);
    g_edges[pos] = ev;
}

// ---------------------------------------------------------------------------
// Pull-mode SpMM v2: 10 threads per row, one float4 segment per thread.
// Lanes t..t+9 read 160 contiguous bytes of the same z row -> coalesced
// gathers (2-3 lines per warp-LDG instead of 32).
// ---------------------------------------------------------------------------
#define SPMM_TPB 320

__global__ void __launch_bounds__(SPMM_TPB) spmm_csr_kernel(
    const float* __restrict__ z,
    const float* __restrict__ h2,
    float* __restrict__ znew)
{
    int t = blockIdx.x * SPMM_TPB + threadIdx.x;
    int r   = t / 10;
    int seg = t - r * 10;
    if (r >= N_NODES) return;

    int e0 = g_start[r];
    int e1 = g_start[r + 1];

    float4 acc = make_float4(0.f, 0.f, 0.f, 0.f);

    int e = e0;
    for (; e + 2 <= e1; e += 2) {
        int2 ev0 = __ldg(&g_edges[e]);
        int2 ev1 = __ldg(&g_edges[e + 1]);
        float v0 = __int_as_float(ev0.y);
        float v1 = __int_as_float(ev1.y);
        float4 a0 = __ldg((const float4*)(z + (size_t)ev0.x * NCLASS) + seg);
        float4 a1 = __ldg((const float4*)(z + (size_t)ev1.x * NCLASS) + seg);
        acc.x += v0 * a0.x + v1 * a1.x;
        acc.y += v0 * a0.y + v1 * a1.y;
        acc.z += v0 * a0.z + v1 * a1.z;
        acc.w += v0 * a0.w + v1 * a1.w;
    }
    if (e < e1) {
        int2 ev = __ldg(&g_edges[e]);
        float v = __int_as_float(ev.y);
        float4 a = __ldg((const float4*)(z + (size_t)ev.x * NCLASS) + seg);
        acc.x += v * a.x;
        acc.y += v * a.y;
        acc.z += v * a.z;
        acc.w += v * a.w;
    }

    float4 hv = __ldg((const float4*)(h2 + (size_t)r * NCLASS) + seg);
    float4 o;
    o.x = acc.x + ALPHA * hv.x;
    o.y = acc.y + ALPHA * hv.y;
    o.z = acc.z + ALPHA * hv.z;
    o.w = acc.w + ALPHA * hv.w;
    ((float4*)(znew + (size_t)r * NCLASS))[seg] = o;
}

// ---------------------------------------------------------------------------
// Row-wise log_softmax over 40 classes: one warp per row
// ---------------------------------------------------------------------------
__global__ void logsoftmax_kernel(const float* __restrict__ z,
                                  float* __restrict__ out)
{
    int gtid = blockIdx.x * blockDim.x + threadIdx.x;
    int warp = gtid / 32;
    int lane = gtid % 32;
    if (warp >= N_NODES) return;

    const float* zr = z + (size_t)warp * NCLASS;
    float v0 = zr[lane];
    float v1 = (lane < NCLASS - 32) ? zr[lane + 32] : -INFINITY;

    float m = fmaxf(v0, v1);
    #pragma unroll
    for (int o = 16; o > 0; o >>= 1)
        m = fmaxf(m, __shfl_xor_sync(0xFFFFFFFFu, m, o));

    float s = expf(v0 - m) + ((lane < NCLASS - 32) ? expf(v1 - m) : 0.f);
    #pragma unroll
    for (int o = 16; o > 0; o >>= 1)
        s += __shfl_xor_sync(0xFFFFFFFFu, s, o);

    float L = m + logf(s);
    out[(size_t)warp * NCLASS + lane] = v0 - L;
    if (lane < NCLASS - 32)
        out[(size_t)warp * NCLASS + lane + 32] = v1 - L;
}

// ---------------------------------------------------------------------------
extern "C" void kernel_launch(void* const* d_in, const int* in_sizes, int n_in,
                              void* d_out, int out_size)
{
    const float* x    = (const float*)d_in[0];
    const int*   row  = (const int*)  d_in[1];
    const int*   col  = (const int*)  d_in[2];
    const float* vals = (const float*)d_in[3];
    const float* W1   = (const float*)d_in[4];
    const float* b1   = (const float*)d_in[5];
    const float* W2   = (const float*)d_in[6];
    const float* b2   = (const float*)d_in[7];
    float* out = (float*)d_out;

    float *h, *h2, *za, *zb;
    cudaGetSymbolAddress((void**)&h,  g_h);
    cudaGetSymbolAddress((void**)&h2, g_h2);
    cudaGetSymbolAddress((void**)&za, g_za);
    cudaGetSymbolAddress((void**)&zb, g_zb);

    cudaFuncSetAttribute(gemm1_mma_kernel,
                         cudaFuncAttributeMaxDynamicSharedMemorySize, G1_SMEM);
    cudaFuncSetAttribute(gemm2_mma_kernel,
                         cudaFuncAttributeMaxDynamicSharedMemorySize, G2_SMEM);

    // Launch order: gemm2 is our 4th launch (observed: ncu profiles our #4).
    prep_w1t_kernel<<<(NHID * NFEAT + 255) / 256, 256>>>(W1);              // 1
    prep_w2t_kernel<<<(NCLASS * NHID + 255) / 256, 256>>>(W2);             // 2
    gemm1_mma_kernel<<<(N_NODES + G1_BM - 1) / G1_BM, 512, G1_SMEM>>>(x, b1, h); // 3
    gemm2_mma_kernel<<<(N_NODES + 127) / 128, 256, G2_SMEM>>>(h, b2, h2);  // 4
    zero_counts_kernel<<<(N_NODES + 255) / 256, 256>>>();                  // 5
    histogram_kernel<<<(E_EDGES + 255) / 256, 256>>>(row);                 // 6
    scan1_kernel<<<NUM_SCAN_BLKS, SCAN_BLK>>>();                           // 7
    scan2_kernel<<<1, 128>>>();                                            // 8
    scan3_kernel<<<(N_NODES + 255) / 256, 256>>>();                        // 9
    scatter_kernel<<<(E_EDGES + 255) / 256, 256>>>(row, col, vals);        // 10

    // APPNP propagation
    const int spmm_grid = (N_NODES * 10 + SPMM_TPB - 1) / SPMM_TPB;
    const float* zin = h2;
    float* bufs[2] = { za, zb };
    for (int it = 0; it < NLAYERS; it++) {
        float* zout = bufs[it & 1];
        spmm_csr_kernel<<<spmm_grid, SPMM_TPB>>>(zin, h2, zout);
        zin = zout;
    }

    logsoftmax_kernel<<<(N_NODES * 32 + 255) / 256, 256>>>(zin, out);
}

// round 8
// speedup vs baseline: 2.8813x; 1.0504x over previous
#include <cuda_runtime.h>
#include <cuda_bf16.h>
#include <math.h>
#include <stdint.h>

#define N_NODES 100000
#define E_EDGES 1600000
#define NFEAT   512
#define NHID    256
#define NCLASS  40
#define NLAYERS 10
#define ALPHA   0.1f

#define SCAN_BLK 1024
#define NUM_SCAN_BLKS ((N_NODES + SCAN_BLK - 1) / SCAN_BLK)   // 98

// Scratch (static device globals — allocation-free rule)
__device__ float g_h [N_NODES * NHID];    // relu(x@W1+b1)
__device__ float g_h2[N_NODES * NCLASS];  // h@W2+b2  (z_0)
__device__ float g_za[N_NODES * NCLASS];
__device__ float g_zb[N_NODES * NCLASS];

// W1 transposed + bf16-split: [NHID][NFEAT]
__device__ __nv_bfloat16 g_w1t_hi[NHID * NFEAT];
__device__ __nv_bfloat16 g_w1t_lo[NHID * NFEAT];
// W2 transposed + bf16-split: [NCLASS][NHID]
__device__ __nv_bfloat16 g_w2t_hi[NCLASS * NHID];
__device__ __nv_bfloat16 g_w2t_lo[NCLASS * NHID];

// CSR build scratch
__device__ int  g_cnt   [N_NODES];
__device__ int  g_offl  [N_NODES];
__device__ int  g_start [N_NODES + 1];
__device__ int  g_cursor[N_NODES];
__device__ int  g_blk   [NUM_SCAN_BLKS];
__device__ int  g_blkoff[NUM_SCAN_BLKS];
__device__ int2 g_edges [E_EDGES];

// ===========================================================================
// helpers (baseline PTX only: ldmatrix / mma.sync / cp.async)
// ===========================================================================
__device__ __forceinline__ uint32_t smem_u32(const void* p) {
    uint32_t a;
    asm("{ .reg .u64 t; cvta.to.shared.u64 t, %1; cvt.u32.u64 %0, t; }"
        : "=r"(a) : "l"(p));
    return a;
}

__device__ __forceinline__ void ldsm4(uint32_t addr, uint32_t* r) {
    asm volatile("ldmatrix.sync.aligned.m8n8.x4.shared.b16 {%0,%1,%2,%3}, [%4];"
        : "=r"(r[0]), "=r"(r[1]), "=r"(r[2]), "=r"(r[3]) : "r"(addr));
}

__device__ __forceinline__ void mma16816(float* c, const uint32_t* a,
                                         uint32_t b0, uint32_t b1) {
    asm volatile(
        "mma.sync.aligned.m16n8k16.row.col.f32.bf16.bf16.f32 "
        "{%0,%1,%2,%3}, {%4,%5,%6,%7}, {%8,%9}, {%0,%1,%2,%3};"
        : "+f"(c[0]), "+f"(c[1]), "+f"(c[2]), "+f"(c[3])
        : "r"(a[0]), "r"(a[1]), "r"(a[2]), "r"(a[3]), "r"(b0), "r"(b1));
}

__device__ __forceinline__ void cpasync16(uint32_t saddr, const void* gptr) {
    asm volatile("cp.async.cg.shared.global [%0], [%1], 16;"
                 :: "r"(saddr), "l"(gptr) : "memory");
}
#define CP_COMMIT() asm volatile("cp.async.commit_group;" ::: "memory")
#define CP_WAIT0()  asm volatile("cp.async.wait_group 0;" ::: "memory")

__device__ __forceinline__ uint32_t sw128(uint32_t off) {
    return off ^ ((off >> 3) & 0x70);
}

__device__ __forceinline__ void split2p(float a, float b, uint32_t& hi, uint32_t& lo) {
    __nv_bfloat16 ah = __float2bfloat16(a);
    __nv_bfloat16 bh = __float2bfloat16(b);
    __nv_bfloat16 al = __float2bfloat16(a - __bfloat162float(ah));
    __nv_bfloat16 bl = __float2bfloat16(b - __bfloat162float(bh));
    hi = (uint32_t)__bfloat16_as_ushort(ah) | ((uint32_t)__bfloat16_as_ushort(bh) << 16);
    lo = (uint32_t)__bfloat16_as_ushort(al) | ((uint32_t)__bfloat16_as_ushort(bl) << 16);
}

// ===========================================================================
// Prep: W1T / W2T bf16 split
// ===========================================================================
__global__ void prep_w1t_kernel(const float* __restrict__ W1)
{
    int i = blockIdx.x * blockDim.x + threadIdx.x;
    if (i >= NHID * NFEAT) return;
    int n = i / NFEAT, k = i % NFEAT;
    float v = W1[(size_t)k * NHID + n];
    __nv_bfloat16 h = __float2bfloat16(v);
    g_w1t_hi[i] = h;
    g_w1t_lo[i] = __float2bfloat16(v - __bfloat162float(h));
}

__global__ void prep_w2t_kernel(const float* __restrict__ W2)
{
    int i = blockIdx.x * blockDim.x + threadIdx.x;
    if (i >= NCLASS * NHID) return;
    int n = i / NHID, k = i % NHID;
    float v = W2[(size_t)k * NCLASS + n];
    __nv_bfloat16 h = __float2bfloat16(v);
    g_w2t_hi[i] = h;
    g_w2t_lo[i] = __float2bfloat16(v - __bfloat162float(h));
}

// ===========================================================================
// GEMM1 (mma.sync HMMA): h = relu(x @ W1 + b1), bf16 2-split, fp32 acc
// CTA 64x256, 256 threads / 8 warps (2m x 4n), warp tile 32x64.
// K staged at 32, double buffered. 2 CTAs/SM (smem 80KB, regs capped 128).
// ===========================================================================
#define G1_BM 64
#define G1_BN 256
#define G1_BK 32
#define G1_STAGES (NFEAT / G1_BK)      // 16
#define G1_A_OFF 0
#define G1_B_OFF 8192
#define G1_STAGE_BYTES 40960           // 8KB A + 32KB B
#define G1_SMEM (2 * G1_STAGE_BYTES)   // 81920

__global__ void __launch_bounds__(256, 2) gemm1_mma_kernel(
    const float* __restrict__ A,
    const float* __restrict__ bias,
    float* __restrict__ C)
{
    extern __shared__ char smem[];
    const uint32_t sbase = smem_u32(smem);
    const int tid  = threadIdx.x;
    const int wid  = tid >> 5;
    const int lane = tid & 31;
    const int rowBase = blockIdx.x * G1_BM;

    const int warp_m = wid & 1;        // 0..1
    const int warp_n = wid >> 1;       // 0..3
    const int m0 = warp_m * 32;
    const int n0 = warp_n * 64;

    float acc[2][8][4];
    #pragma unroll
    for (int i = 0; i < 2; i++)
        #pragma unroll
        for (int j = 0; j < 8; j++)
            #pragma unroll
            for (int q = 0; q < 4; q++) acc[i][j][q] = 0.f;

    // A: 256 threads cover 64 rows x 4 k-octets
    const int agr = tid >> 2;          // row 0..63
    const int akq = tid & 3;           // k-octet
    const int bkq = tid & 3;

    float a_st[8];

    auto ldgA = [&](int k0) {
        int gr = rowBase + agr;
        if (gr < N_NODES) {
            const float* p = A + (size_t)gr * NFEAT + k0 + akq * 8;
            float4 v0 = *(const float4*)p;
            float4 v1 = *(const float4*)(p + 4);
            a_st[0]=v0.x; a_st[1]=v0.y; a_st[2]=v0.z; a_st[3]=v0.w;
            a_st[4]=v1.x; a_st[5]=v1.y; a_st[6]=v1.z; a_st[7]=v1.w;
        } else {
            #pragma unroll
            for (int q = 0; q < 8; q++) a_st[q] = 0.f;
        }
    };
    auto cpB = [&](int k0, int stage) {
        uint32_t bb = sbase + stage * G1_STAGE_BYTES + G1_B_OFF;
        #pragma unroll
        for (int it = 0; it < 4; it++) {
            int n = (tid >> 2) + it * 64;          // 0..255
            size_t gi = (size_t)n * NFEAT + k0 + bkq * 8;
            uint32_t off = n * 128 + bkq * 16;
            cpasync16(bb + sw128(off),      g_w1t_hi + gi);
            cpasync16(bb + sw128(off + 64), g_w1t_lo + gi);
        }
        CP_COMMIT();
    };
    auto stsA = [&](int stage) {
        uint4 hq, lq;
        split2p(a_st[0], a_st[1], hq.x, lq.x);
        split2p(a_st[2], a_st[3], hq.y, lq.y);
        split2p(a_st[4], a_st[5], hq.z, lq.z);
        split2p(a_st[6], a_st[7], hq.w, lq.w);
        uint32_t offh = agr * 128 + akq * 16;
        char* ab = smem + stage * G1_STAGE_BYTES + G1_A_OFF;
        *(uint4*)(ab + sw128(offh))      = hq;
        *(uint4*)(ab + sw128(offh + 64)) = lq;
    };

    auto compute = [&](int stage) {
        uint32_t ab = sbase + stage * G1_STAGE_BYTES + G1_A_OFF;
        uint32_t bb = sbase + stage * G1_STAGE_BYTES + G1_B_OFF;
        const int q  = lane >> 3;
        const int rr = lane & 7;
        #pragma unroll
        for (int k16 = 0; k16 < 2; k16++) {
            int cb = k16 * 2;
            uint32_t ah[2][4], al[2][4];
            #pragma unroll
            for (int mi = 0; mi < 2; mi++) {
                int row = m0 + mi * 16 + (q & 1) * 8 + rr;
                uint32_t offh = row * 128 + (cb + (q >> 1)) * 16;
                ldsm4(ab + sw128(offh), ah[mi]);
                ldsm4(ab + sw128(offh + 64), al[mi]);
            }
            #pragma unroll
            for (int nj = 0; nj < 4; nj++) {
                uint32_t bh[4], bl[4];
                int row = n0 + nj * 16 + (q & 1) * 8 + rr;
                uint32_t offh = row * 128 + (cb + (q >> 1)) * 16;
                ldsm4(bb + sw128(offh), bh);
                ldsm4(bb + sw128(offh + 64), bl);
                #pragma unroll
                for (int mi = 0; mi < 2; mi++)
                    #pragma unroll
                    for (int hh = 0; hh < 2; hh++) {
                        float* cc = acc[mi][nj * 2 + hh];
                        mma16816(cc, ah[mi], bh[hh], bh[2 + hh]);
                        mma16816(cc, ah[mi], bl[hh], bl[2 + hh]);
                        mma16816(cc, al[mi], bh[hh], bh[2 + hh]);
                    }
            }
        }
    };

    ldgA(0); cpB(0, 0); stsA(0);
    CP_WAIT0();
    __syncthreads();

    for (int s = 0; s < G1_STAGES; s++) {
        if (s + 1 < G1_STAGES) {
            ldgA((s + 1) * G1_BK);
            cpB((s + 1) * G1_BK, (s + 1) & 1);
        }
        compute(s & 1);
        if (s + 1 < G1_STAGES) {
            stsA((s + 1) & 1);
            CP_WAIT0();
            __syncthreads();
        }
    }

    const float bval = bias[0];
    const int g  = lane >> 2;
    const int tq = lane & 3;
    #pragma unroll
    for (int mi = 0; mi < 2; mi++)
        #pragma unroll
        for (int nt = 0; nt < 8; nt++) {
            int row = m0 + mi * 16 + g;
            int col = n0 + nt * 8 + tq * 2;
            int gr0 = rowBase + row;
            int gr1 = gr0 + 8;
            float* cc = acc[mi][nt];
            if (gr0 < N_NODES) {
                float2 o;
                o.x = fmaxf(cc[0] + bval, 0.f);
                o.y = fmaxf(cc[1] + bval, 0.f);
                *(float2*)(C + (size_t)gr0 * NHID + col) = o;
            }
            if (gr1 < N_NODES) {
                float2 o;
                o.x = fmaxf(cc[2] + bval, 0.f);
                o.y = fmaxf(cc[3] + bval, 0.f);
                *(float2*)(C + (size_t)gr1 * NHID + col) = o;
            }
        }
}

// ===========================================================================
// GEMM2 (mma.sync HMMA): h2 = h @ W2 + b2, bf16 2-split, fp32 acc
// ===========================================================================
#define G2_A_ST   16384
#define G2_W2_OFF 32768
#define G2_W2_CH  6144
#define G2_SMEM   (32768 + 8 * G2_W2_CH)   // 81920

__global__ void __launch_bounds__(256, 1) gemm2_mma_kernel(
    const float* __restrict__ A,      // g_h [N, 256]
    const float* __restrict__ bias,
    float* __restrict__ C)            // g_h2 [N, 40]
{
    extern __shared__ char smem[];
    const uint32_t sbase = smem_u32(smem);
    const int tid  = threadIdx.x;
    const int wid  = tid >> 5;
    const int lane = tid & 31;
    const int rowBase = blockIdx.x * 128;
    const int m0 = wid * 16;

    for (int idx = tid; idx < 8 * 40 * 8; idx += 256) {
        int ch  = idx / 320;
        int rem = idx - ch * 320;
        int n   = rem >> 3;
        int seg = rem & 7;
        const __nv_bfloat16* src =
            (seg < 4 ? g_w2t_hi : g_w2t_lo) + (size_t)n * NHID + ch * 32 + (seg & 3) * 8;
        uint32_t off = n * 128 + (seg < 4 ? (seg & 3) * 16 : 64 + (seg & 3) * 16);
        cpasync16(sbase + G2_W2_OFF + ch * G2_W2_CH + sw128(off), src);
    }
    CP_COMMIT();

    float acc[5][4];
    #pragma unroll
    for (int j = 0; j < 5; j++)
        #pragma unroll
        for (int q = 0; q < 4; q++) acc[j][q] = 0.f;

    float a_st[16];
    auto ldgA = [&](int k0) {
        #pragma unroll
        for (int it = 0; it < 2; it++) {
            int g  = tid + it * 256;
            int r  = g >> 2;
            int oq = g & 3;
            int gr = rowBase + r;
            if (gr < N_NODES) {
                const float* p = A + (size_t)gr * NHID + k0 + oq * 8;
                float4 v0 = *(const float4*)p;
                float4 v1 = *(const float4*)(p + 4);
                a_st[it*8+0]=v0.x; a_st[it*8+1]=v0.y; a_st[it*8+2]=v0.z; a_st[it*8+3]=v0.w;
                a_st[it*8+4]=v1.x; a_st[it*8+5]=v1.y; a_st[it*8+6]=v1.z; a_st[it*8+7]=v1.w;
            } else {
                #pragma unroll
                for (int q = 0; q < 8; q++) a_st[it*8+q] = 0.f;
            }
        }
    };
    auto stsA = [&](int stage) {
        #pragma unroll
        for (int it = 0; it < 2; it++) {
            int g  = tid + it * 256;
            int r  = g >> 2;
            int oq = g & 3;
            uint4 hq, lq;
            split2p(a_st[it*8+0], a_st[it*8+1], hq.x, lq.x);
            split2p(a_st[it*8+2], a_st[it*8+3], hq.y, lq.y);
            split2p(a_st[it*8+4], a_st[it*8+5], hq.z, lq.z);
            split2p(a_st[it*8+6], a_st[it*8+7], hq.w, lq.w);
            uint32_t offh = r * 128 + oq * 16;
            char* ab = smem + stage * G2_A_ST;
            *(uint4*)(ab + sw128(offh))      = hq;
            *(uint4*)(ab + sw128(offh + 64)) = lq;
        }
    };

    auto compute = [&](int stage, int ch) {
        uint32_t ab = sbase + stage * G2_A_ST;
        uint32_t bb = sbase + G2_W2_OFF + ch * G2_W2_CH;
        const int q  = lane >> 3;
        const int rr = lane & 7;
        #pragma unroll
        for (int k16 = 0; k16 < 2; k16++) {
            int cb = k16 * 2;
            uint32_t ah[4], al[4];
            {
                int row = m0 + (q & 1) * 8 + rr;
                uint32_t offh = row * 128 + (cb + (q >> 1)) * 16;
                ldsm4(ab + sw128(offh), ah);
                ldsm4(ab + sw128(offh + 64), al);
            }
            uint32_t bh[3][4], bl[3][4];
            #pragma unroll
            for (int nj = 0; nj < 3; nj++) {
                int row = nj * 16 + (q & 1) * 8 + rr;
                uint32_t offh = row * 128 + (cb + (q >> 1)) * 16;
                ldsm4(bb + sw128(offh), bh[nj]);
                ldsm4(bb + sw128(offh + 64), bl[nj]);
            }
            #pragma unroll
            for (int nt = 0; nt < 5; nt++) {
                int nj = nt >> 1, hh = nt & 1;
                mma16816(acc[nt], ah, bh[nj][hh], bh[nj][2 + hh]);
                mma16816(acc[nt], ah, bl[nj][hh], bl[nj][2 + hh]);
                mma16816(acc[nt], al, bh[nj][hh], bh[nj][2 + hh]);
            }
        }
    };

    ldgA(0); stsA(0);
    CP_WAIT0();
    __syncthreads();

    for (int ch = 0; ch < 8; ch++) {
        if (ch + 1 < 8) ldgA((ch + 1) * 32);
        compute(ch & 1, ch);
        if (ch + 1 < 8) {
            stsA((ch + 1) & 1);
            __syncthreads();
        }
    }

    const float bval = bias[0];
    const int g  = lane >> 2;
    const int tq = lane & 3;
    #pragma unroll
    for (int nt = 0; nt < 5; nt++) {
        int col = nt * 8 + tq * 2;
        int gr0 = rowBase + m0 + g;
        int gr1 = gr0 + 8;
        if (gr0 < N_NODES) {
            float2 o; o.x = acc[nt][0] + bval; o.y = acc[nt][1] + bval;
            *(float2*)(C + (size_t)gr0 * NCLASS + col) = o;
        }
        if (gr1 < N_NODES) {
            float2 o; o.x = acc[nt][2] + bval; o.y = acc[nt][3] + bval;
            *(float2*)(C + (size_t)gr1 * NCLASS + col) = o;
        }
    }
}

// ---------------------------------------------------------------------------
// CSR build: histogram -> 2-level exclusive scan -> scatter
// ---------------------------------------------------------------------------
__global__ void zero_counts_kernel()
{
    int i = blockIdx.x * blockDim.x + threadIdx.x;
    if (i < N_NODES) g_cnt[i] = 0;
}

__global__ void histogram_kernel(const int* __restrict__ row)
{
    int e = blockIdx.x * blockDim.x + threadIdx.x;
    if (e < E_EDGES) atomicAdd(&g_cnt[row[e]], 1);
}

__global__ void __launch_bounds__(SCAN_BLK) scan1_kernel()
{
    __shared__ int s[SCAN_BLK];
    int gid = blockIdx.x * SCAN_BLK + threadIdx.x;
    int x = (gid < N_NODES) ? g_cnt[gid] : 0;
    s[threadIdx.x] = x;
    __syncthreads();
    #pragma unroll
    for (int d = 1; d < SCAN_BLK; d <<= 1) {
        int t = (threadIdx.x >= d) ? s[threadIdx.x - d] : 0;
        __syncthreads();
        s[threadIdx.x] += t;
        __syncthreads();
    }
    if (gid < N_NODES) g_offl[gid] = s[threadIdx.x] - x;
    if (threadIdx.x == SCAN_BLK - 1) g_blk[blockIdx.x] = s[SCAN_BLK - 1];
}

__global__ void scan2_kernel()
{
    __shared__ int s[128];
    int tid = threadIdx.x;
    int x = (tid < NUM_SCAN_BLKS) ? g_blk[tid] : 0;
    s[tid] = x;
    __syncthreads();
    #pragma unroll
    for (int d = 1; d < 128; d <<= 1) {
        int t = (tid >= d) ? s[tid - d] : 0;
        __syncthreads();
        s[tid] += t;
        __syncthreads();
    }
    if (tid < NUM_SCAN_BLKS) g_blkoff[tid] = s[tid] - x;
}

__global__ void scan3_kernel()
{
    int i = blockIdx.x * blockDim.x + threadIdx.x;
    if (i < N_NODES) {
        int st = g_offl[i] + g_blkoff[i / SCAN_BLK];
        g_start[i]  = st;
        g_cursor[i] = st;
    }
    if (i == 0) g_start[N_NODES] = E_EDGES;
}

__global__ void scatter_kernel(const int* __restrict__ row,
                               const int* __restrict__ col,
                               const float* __restrict__ vals)
{
    int e = blockIdx.x * blockDim.x + threadIdx.x;
    if (e >= E_EDGES) return;
    int r = row[e];
    int pos = atomicAdd(&g_cursor[r], 1);
    int2 ev;
    ev.x = col[e];
    ev.y = __float_as_int((1.0f - ALPHA) * vals[e]);
    g_edges[pos] = ev;
}

// ---------------------------------------------------------------------------
// Pull-mode SpMM: 10 threads per row, one float4 segment per thread.
// ---------------------------------------------------------------------------
#define SPMM_TPB 320

__global__ void __launch_bounds__(SPMM_TPB) spmm_csr_kernel(
    const float* __restrict__ z,
    const float* __restrict__ h2,
    float* __restrict__ znew)
{
    int t = blockIdx.x * SPMM_TPB + threadIdx.x;
    int r   = t / 10;
    int seg = t - r * 10;
    if (r >= N_NODES) return;

    int e0 = g_start[r];
    int e1 = g_start[r + 1];

    float4 acc = make_float4(0.f, 0.f, 0.f, 0.f);

    int e = e0;
    for (; e + 2 <= e1; e += 2) {
        int2 ev0 = __ldg(&g_edges[e]);
        int2 ev1 = __ldg(&g_edges[e + 1]);
        float v0 = __int_as_float(ev0.y);
        float v1 = __int_as_float(ev1.y);
        float4 a0 = __ldg((const float4*)(z + (size_t)ev0.x * NCLASS) + seg);
        float4 a1 = __ldg((const float4*)(z + (size_t)ev1.x * NCLASS) + seg);
        acc.x += v0 * a0.x + v1 * a1.x;
        acc.y += v0 * a0.y + v1 * a1.y;
        acc.z += v0 * a0.z + v1 * a1.z;
        acc.w += v0 * a0.w + v1 * a1.w;
    }
    if (e < e1) {
        int2 ev = __ldg(&g_edges[e]);
        float v = __int_as_float(ev.y);
        float4 a = __ldg((const float4*)(z + (size_t)ev.x * NCLASS) + seg);
        acc.x += v * a.x;
        acc.y += v * a.y;
        acc.z += v * a.z;
        acc.w += v * a.w;
    }

    float4 hv = __ldg((const float4*)(h2 + (size_t)r * NCLASS) + seg);
    float4 o;
    o.x = acc.x + ALPHA * hv.x;
    o.y = acc.y + ALPHA * hv.y;
    o.z = acc.z + ALPHA * hv.z;
    o.w = acc.w + ALPHA * hv.w;
    ((float4*)(znew + (size_t)r * NCLASS))[seg] = o;
}

// ---------------------------------------------------------------------------
// Row-wise log_softmax over 40 classes: one warp per row
// ---------------------------------------------------------------------------
__global__ void logsoftmax_kernel(const float* __restrict__ z,
                                  float* __restrict__ out)
{
    int gtid = blockIdx.x * blockDim.x + threadIdx.x;
    int warp = gtid / 32;
    int lane = gtid % 32;
    if (warp >= N_NODES) return;

    const float* zr = z + (size_t)warp * NCLASS;
    float v0 = zr[lane];
    float v1 = (lane < NCLASS - 32) ? zr[lane + 32] : -INFINITY;

    float m = fmaxf(v0, v1);
    #pragma unroll
    for (int o = 16; o > 0; o >>= 1)
        m = fmaxf(m, __shfl_xor_sync(0xFFFFFFFFu, m, o));

    float s = expf(v0 - m) + ((lane < NCLASS - 32) ? expf(v1 - m) : 0.f);
    #pragma unroll
    for (int o = 16; o > 0; o >>= 1)
        s += __shfl_xor_sync(0xFFFFFFFFu, s, o);

    float L = m + logf(s);
    out[(size_t)warp * NCLASS + lane] = v0 - L;
    if (lane < NCLASS - 32)
        out[(size_t)warp * NCLASS + lane + 32] = v1 - L;
}

// ---------------------------------------------------------------------------
extern "C" void kernel_launch(void* const* d_in, const int* in_sizes, int n_in,
                              void* d_out, int out_size)
{
    const float* x    = (const float*)d_in[0];
    const int*   row  = (const int*)  d_in[1];
    const int*   col  = (const int*)  d_in[2];
    const float* vals = (const float*)d_in[3];
    const float* W1   = (const float*)d_in[4];
    const float* b1   = (const float*)d_in[5];
    const float* W2   = (const float*)d_in[6];
    const float* b2   = (const float*)d_in[7];
    float* out = (float*)d_out;

    float *h, *h2, *za, *zb;
    cudaGetSymbolAddress((void**)&h,  g_h);
    cudaGetSymbolAddress((void**)&h2, g_h2);
    cudaGetSymbolAddress((void**)&za, g_za);
    cudaGetSymbolAddress((void**)&zb, g_zb);

    cudaFuncSetAttribute(gemm1_mma_kernel,
                         cudaFuncAttributeMaxDynamicSharedMemorySize, G1_SMEM);
    cudaFuncSetAttribute(gemm2_mma_kernel,
                         cudaFuncAttributeMaxDynamicSharedMemorySize, G2_SMEM);

    // Launch order: gemm1 is our 4th launch (ncu profiles our #4).
    prep_w1t_kernel<<<(NHID * NFEAT + 255) / 256, 256>>>(W1);              // 1
    prep_w2t_kernel<<<(NCLASS * NHID + 255) / 256, 256>>>(W2);             // 2
    zero_counts_kernel<<<(N_NODES + 255) / 256, 256>>>();                  // 3
    gemm1_mma_kernel<<<(N_NODES + G1_BM - 1) / G1_BM, 256, G1_SMEM>>>(x, b1, h); // 4
    histogram_kernel<<<(E_EDGES + 255) / 256, 256>>>(row);                 // 5
    scan1_kernel<<<NUM_SCAN_BLKS, SCAN_BLK>>>();                           // 6
    scan2_kernel<<<1, 128>>>();                                            // 7
    scan3_kernel<<<(N_NODES + 255) / 256, 256>>>();                        // 8
    scatter_kernel<<<(E_EDGES + 255) / 256, 256>>>(row, col, vals);        // 9
    gemm2_mma_kernel<<<(N_NODES + 127) / 128, 256, G2_SMEM>>>(h, b2, h2);  // 10

    // APPNP propagation
    const int spmm_grid = (N_NODES * 10 + SPMM_TPB - 1) / SPMM_TPB;
    const float* zin = h2;
    float* bufs[2] = { za, zb };
    for (int it = 0; it < NLAYERS; it++) {
        float* zout = bufs[it & 1];
        spmm_csr_kernel<<<spmm_grid, SPMM_TPB>>>(zin, h2, zout);
        zin = zout;
    }

    logsoftmax_kernel<<<(N_NODES * 32 + 255) / 256, 256>>>(zin, out);
}

// round 9
// speedup vs baseline: 3.3341x; 1.1572x over previous
#include <cuda_runtime.h>
#include <cuda_fp16.h>
#include <math.h>
#include <stdint.h>

#define N_NODES 100000
#define E_EDGES 1600000
#define NFEAT   512
#define NHID    256
#define NCLASS  40
#define NLAYERS 10
#define ALPHA   0.1f

#define SCAN_BLK 1024
#define NUM_SCAN_BLKS ((N_NODES + SCAN_BLK - 1) / SCAN_BLK)   // 98

// Scratch (static device globals — allocation-free rule)
__device__ float g_h [N_NODES * NHID];    // relu(x@W1+b1)
__device__ float g_h2[N_NODES * NCLASS];  // h@W2+b2  (z_0)
__device__ float g_za[N_NODES * NCLASS];
__device__ float g_zb[N_NODES * NCLASS];

// W1 transposed, fp16: [NHID][NFEAT]
__device__ __half g_w1t[NHID * NFEAT];
// W2 transposed, fp16: [NCLASS][NHID]
__device__ __half g_w2t[NCLASS * NHID];

// CSR build scratch
__device__ int  g_cnt   [N_NODES];
__device__ int  g_offl  [N_NODES];
__device__ int  g_start [N_NODES + 1];
__device__ int  g_cursor[N_NODES];
__device__ int  g_blk   [NUM_SCAN_BLKS];
__device__ int  g_blkoff[NUM_SCAN_BLKS];
__device__ int2 g_edges [E_EDGES];

// ===========================================================================
// helpers (baseline PTX only: ldmatrix / mma.sync / cp.async)
// ===========================================================================
__device__ __forceinline__ uint32_t smem_u32(const void* p) {
    uint32_t a;
    asm("{ .reg .u64 t; cvta.to.shared.u64 t, %1; cvt.u32.u64 %0, t; }"
        : "=r"(a) : "l"(p));
    return a;
}

__device__ __forceinline__ void ldsm4(uint32_t addr, uint32_t* r) {
    asm volatile("ldmatrix.sync.aligned.m8n8.x4.shared.b16 {%0,%1,%2,%3}, [%4];"
        : "=r"(r[0]), "=r"(r[1]), "=r"(r[2]), "=r"(r[3]) : "r"(addr));
}

// fp16 MMA, fp32 accumulate
__device__ __forceinline__ void mma16816(float* c, const uint32_t* a,
                                         uint32_t b0, uint32_t b1) {
    asm volatile(
        "mma.sync.aligned.m16n8k16.row.col.f32.f16.f16.f32 "
        "{%0,%1,%2,%3}, {%4,%5,%6,%7}, {%8,%9}, {%0,%1,%2,%3};"
        : "+f"(c[0]), "+f"(c[1]), "+f"(c[2]), "+f"(c[3])
        : "r"(a[0]), "r"(a[1]), "r"(a[2]), "r"(a[3]), "r"(b0), "r"(b1));
}

__device__ __forceinline__ void cpasync16(uint32_t saddr, const void* gptr) {
    asm volatile("cp.async.cg.shared.global [%0], [%1], 16;"
                 :: "r"(saddr), "l"(gptr) : "memory");
}
#define CP_COMMIT() asm volatile("cp.async.commit_group;" ::: "memory")
#define CP_WAIT0()  asm volatile("cp.async.wait_group 0;" ::: "memory")

__device__ __forceinline__ uint32_t sw128(uint32_t off) {
    return off ^ ((off >> 3) & 0x70);
}

// fp16 hi/lo split of two floats, packed
__device__ __forceinline__ void split2h(float a, float b, uint32_t& hi, uint32_t& lo) {
    __half ah = __float2half(a);
    __half bh = __float2half(b);
    __half al = __float2half(a - __half2float(ah));
    __half bl = __float2half(b - __half2float(bh));
    hi = (uint32_t)__half_as_ushort(ah) | ((uint32_t)__half_as_ushort(bh) << 16);
    lo = (uint32_t)__half_as_ushort(al) | ((uint32_t)__half_as_ushort(bl) << 16);
}

// ===========================================================================
// Prep: W1T / W2T fp16
// ===========================================================================
__global__ void prep_w1t_kernel(const float* __restrict__ W1)
{
    int i = blockIdx.x * blockDim.x + threadIdx.x;
    if (i >= NHID * NFEAT) return;
    int n = i / NFEAT, k = i % NFEAT;
    g_w1t[i] = __float2half(W1[(size_t)k * NHID + n]);
}

__global__ void prep_w2t_kernel(const float* __restrict__ W2)
{
    int i = blockIdx.x * blockDim.x + threadIdx.x;
    if (i >= NCLASS * NHID) return;
    int n = i / NHID, k = i % NHID;
    g_w2t[i] = __float2half(W2[(size_t)k * NCLASS + n]);
}

// ===========================================================================
// GEMM1 (mma.sync fp16, A split hi/lo, B single): h = relu(x @ W1 + b1)
// CTA 64x256, 256 threads / 8 warps (2m x 4n), warp tile 32x64.
// K staged at 32, double buffered, 2 CTAs/SM.
// SMEM stage: A 64 rows x 128B [hi32|lo32] = 8KB; B 256 rows x 128B
// (only first 64B of each row used: k32 fp16) = 32KB.
// ===========================================================================
#define G1_BM 64
#define G1_BN 256
#define G1_BK 32
#define G1_STAGES (NFEAT / G1_BK)      // 16
#define G1_A_OFF 0
#define G1_B_OFF 8192
#define G1_STAGE_BYTES 40960
#define G1_SMEM (2 * G1_STAGE_BYTES)   // 81920

__global__ void __launch_bounds__(256, 2) gemm1_mma_kernel(
    const float* __restrict__ A,
    const float* __restrict__ bias,
    float* __restrict__ C)
{
    extern __shared__ char smem[];
    const uint32_t sbase = smem_u32(smem);
    const int tid  = threadIdx.x;
    const int lane = tid & 31;
    const int wid  = tid >> 5;
    const int rowBase = blockIdx.x * G1_BM;

    const int warp_m = wid & 1;        // 0..1
    const int warp_n = wid >> 1;       // 0..3
    const int m0 = warp_m * 32;
    const int n0 = warp_n * 64;

    float acc[2][8][4];
    #pragma unroll
    for (int i = 0; i < 2; i++)
        #pragma unroll
        for (int j = 0; j < 8; j++)
            #pragma unroll
            for (int q = 0; q < 4; q++) acc[i][j][q] = 0.f;

    const int agr = tid >> 2;          // row 0..63
    const int akq = tid & 3;           // k-octet
    const int bkq = tid & 3;

    float a_st[8];

    auto ldgA = [&](int k0) {
        int gr = rowBase + agr;
        if (gr < N_NODES) {
            const float* p = A + (size_t)gr * NFEAT + k0 + akq * 8;
            float4 v0 = *(const float4*)p;
            float4 v1 = *(const float4*)(p + 4);
            a_st[0]=v0.x; a_st[1]=v0.y; a_st[2]=v0.z; a_st[3]=v0.w;
            a_st[4]=v1.x; a_st[5]=v1.y; a_st[6]=v1.z; a_st[7]=v1.w;
        } else {
            #pragma unroll
            for (int q = 0; q < 8; q++) a_st[q] = 0.f;
        }
    };
    auto cpB = [&](int k0, int stage) {
        uint32_t bb = sbase + stage * G1_STAGE_BYTES + G1_B_OFF;
        #pragma unroll
        for (int it = 0; it < 4; it++) {
            int n = (tid >> 2) + it * 64;          // 0..255
            size_t gi = (size_t)n * NFEAT + k0 + bkq * 8;
            uint32_t off = n * 128 + bkq * 16;
            cpasync16(bb + sw128(off), g_w1t + gi);
        }
        CP_COMMIT();
    };
    auto stsA = [&](int stage) {
        uint4 hq, lq;
        split2h(a_st[0], a_st[1], hq.x, lq.x);
        split2h(a_st[2], a_st[3], hq.y, lq.y);
        split2h(a_st[4], a_st[5], hq.z, lq.z);
        split2h(a_st[6], a_st[7], hq.w, lq.w);
        uint32_t offh = agr * 128 + akq * 16;
        char* ab = smem + stage * G1_STAGE_BYTES + G1_A_OFF;
        *(uint4*)(ab + sw128(offh))      = hq;
        *(uint4*)(ab + sw128(offh + 64)) = lq;
    };

    auto compute = [&](int stage) {
        uint32_t ab = sbase + stage * G1_STAGE_BYTES + G1_A_OFF;
        uint32_t bb = sbase + stage * G1_STAGE_BYTES + G1_B_OFF;
        const int q  = lane >> 3;
        const int rr = lane & 7;
        #pragma unroll
        for (int k16 = 0; k16 < 2; k16++) {
            int cb = k16 * 2;
            uint32_t ah[2][4], al[2][4];
            #pragma unroll
            for (int mi = 0; mi < 2; mi++) {
                int row = m0 + mi * 16 + (q & 1) * 8 + rr;
                uint32_t offh = row * 128 + (cb + (q >> 1)) * 16;
                ldsm4(ab + sw128(offh), ah[mi]);
                ldsm4(ab + sw128(offh + 64), al[mi]);
            }
            #pragma unroll
            for (int nj = 0; nj < 4; nj++) {
                uint32_t bh[4];
                int row = n0 + nj * 16 + (q & 1) * 8 + rr;
                uint32_t offh = row * 128 + (cb + (q >> 1)) * 16;
                ldsm4(bb + sw128(offh), bh);
                #pragma unroll
                for (int mi = 0; mi < 2; mi++)
                    #pragma unroll
                    for (int hh = 0; hh < 2; hh++) {
                        float* cc = acc[mi][nj * 2 + hh];
                        mma16816(cc, ah[mi], bh[hh], bh[2 + hh]);
                        mma16816(cc, al[mi], bh[hh], bh[2 + hh]);
                    }
            }
        }
    };

    ldgA(0); cpB(0, 0); stsA(0);
    CP_WAIT0();
    __syncthreads();

    for (int s = 0; s < G1_STAGES; s++) {
        if (s + 1 < G1_STAGES) {
            ldgA((s + 1) * G1_BK);
            cpB((s + 1) * G1_BK, (s + 1) & 1);
        }
        compute(s & 1);
        if (s + 1 < G1_STAGES) {
            stsA((s + 1) & 1);
            CP_WAIT0();
            __syncthreads();
        }
    }

    const float bval = bias[0];
    const int g  = lane >> 2;
    const int tq = lane & 3;
    #pragma unroll
    for (int mi = 0; mi < 2; mi++)
        #pragma unroll
        for (int nt = 0; nt < 8; nt++) {
            int row = m0 + mi * 16 + g;
            int col = n0 + nt * 8 + tq * 2;
            int gr0 = rowBase + row;
            int gr1 = gr0 + 8;
            float* cc = acc[mi][nt];
            if (gr0 < N_NODES) {
                float2 o;
                o.x = fmaxf(cc[0] + bval, 0.f);
                o.y = fmaxf(cc[1] + bval, 0.f);
                *(float2*)(C + (size_t)gr0 * NHID + col) = o;
            }
            if (gr1 < N_NODES) {
                float2 o;
                o.x = fmaxf(cc[2] + bval, 0.f);
                o.y = fmaxf(cc[3] + bval, 0.f);
                *(float2*)(C + (size_t)gr1 * NHID + col) = o;
            }
        }
}

// ===========================================================================
// GEMM2 (mma.sync fp16, A split hi/lo, W2 single): h2 = h @ W2 + b2
// ===========================================================================
#define G2_A_ST   16384
#define G2_W2_OFF 32768
#define G2_W2_CH  6144
#define G2_SMEM   (32768 + 8 * G2_W2_CH)   // 81920

__global__ void __launch_bounds__(256, 1) gemm2_mma_kernel(
    const float* __restrict__ A,      // g_h [N, 256]
    const float* __restrict__ bias,
    float* __restrict__ C)            // g_h2 [N, 40]
{
    extern __shared__ char smem[];
    const uint32_t sbase = smem_u32(smem);
    const int tid  = threadIdx.x;
    const int wid  = tid >> 5;
    const int lane = tid & 31;
    const int rowBase = blockIdx.x * 128;
    const int m0 = wid * 16;

    // async-load W2 chunk tiles (8 chunks x 40 rows x 4 segs x 16B; hi only)
    for (int idx = tid; idx < 8 * 40 * 4; idx += 256) {
        int ch  = idx / 160;
        int rem = idx - ch * 160;
        int n   = rem >> 2;
        int seg = rem & 3;
        const __half* src = g_w2t + (size_t)n * NHID + ch * 32 + seg * 8;
        uint32_t off = n * 128 + seg * 16;
        cpasync16(sbase + G2_W2_OFF + ch * G2_W2_CH + sw128(off), src);
    }
    CP_COMMIT();

    float acc[5][4];
    #pragma unroll
    for (int j = 0; j < 5; j++)
        #pragma unroll
        for (int q = 0; q < 4; q++) acc[j][q] = 0.f;

    float a_st[16];
    auto ldgA = [&](int k0) {
        #pragma unroll
        for (int it = 0; it < 2; it++) {
            int g  = tid + it * 256;
            int r  = g >> 2;
            int oq = g & 3;
            int gr = rowBase + r;
            if (gr < N_NODES) {
                const float* p = A + (size_t)gr * NHID + k0 + oq * 8;
                float4 v0 = *(const float4*)p;
                float4 v1 = *(const float4*)(p + 4);
                a_st[it*8+0]=v0.x; a_st[it*8+1]=v0.y; a_st[it*8+2]=v0.z; a_st[it*8+3]=v0.w;
                a_st[it*8+4]=v1.x; a_st[it*8+5]=v1.y; a_st[it*8+6]=v1.z; a_st[it*8+7]=v1.w;
            } else {
                #pragma unroll
                for (int q = 0; q < 8; q++) a_st[it*8+q] = 0.f;
            }
        }
    };
    auto stsA = [&](int stage) {
        #pragma unroll
        for (int it = 0; it < 2; it++) {
            int g  = tid + it * 256;
            int r  = g >> 2;
            int oq = g & 3;
            uint4 hq, lq;
            split2h(a_st[it*8+0], a_st[it*8+1], hq.x, lq.x);
            split2h(a_st[it*8+2], a_st[it*8+3], hq.y, lq.y);
            split2h(a_st[it*8+4], a_st[it*8+5], hq.z, lq.z);
            split2h(a_st[it*8+6], a_st[it*8+7], hq.w, lq.w);
            uint32_t offh = r * 128 + oq * 16;
            char* ab = smem + stage * G2_A_ST;
            *(uint4*)(ab + sw128(offh))      = hq;
            *(uint4*)(ab + sw128(offh + 64)) = lq;
        }
    };

    auto compute = [&](int stage, int ch) {
        uint32_t ab = sbase + stage * G2_A_ST;
        uint32_t bb = sbase + G2_W2_OFF + ch * G2_W2_CH;
        const int q  = lane >> 3;
        const int rr = lane & 7;
        #pragma unroll
        for (int k16 = 0; k16 < 2; k16++) {
            int cb = k16 * 2;
            uint32_t ah[4], al[4];
            {
                int row = m0 + (q & 1) * 8 + rr;
                uint32_t offh = row * 128 + (cb + (q >> 1)) * 16;
                ldsm4(ab + sw128(offh), ah);
                ldsm4(ab + sw128(offh + 64), al);
            }
            uint32_t bh[3][4];
            #pragma unroll
            for (int nj = 0; nj < 3; nj++) {
                int row = nj * 16 + (q & 1) * 8 + rr;
                uint32_t offh = row * 128 + (cb + (q >> 1)) * 16;
                ldsm4(bb + sw128(offh), bh[nj]);
            }
            #pragma unroll
            for (int nt = 0; nt < 5; nt++) {
                int nj = nt >> 1, hh = nt & 1;
                mma16816(acc[nt], ah, bh[nj][hh], bh[nj][2 + hh]);
                mma16816(acc[nt], al, bh[nj][hh], bh[nj][2 + hh]);
            }
        }
    };

    ldgA(0); stsA(0);
    CP_WAIT0();
    __syncthreads();

    for (int ch = 0; ch < 8; ch++) {
        if (ch + 1 < 8) ldgA((ch + 1) * 32);
        compute(ch & 1, ch);
        if (ch + 1 < 8) {
            stsA((ch + 1) & 1);
            __syncthreads();
        }
    }

    const float bval = bias[0];
    const int g  = lane >> 2;
    const int tq = lane & 3;
    #pragma unroll
    for (int nt = 0; nt < 5; nt++) {
        int col = nt * 8 + tq * 2;
        int gr0 = rowBase + m0 + g;
        int gr1 = gr0 + 8;
        if (gr0 < N_NODES) {
            float2 o; o.x = acc[nt][0] + bval; o.y = acc[nt][1] + bval;
            *(float2*)(C + (size_t)gr0 * NCLASS + col) = o;
        }
        if (gr1 < N_NODES) {
            float2 o; o.x = acc[nt][2] + bval; o.y = acc[nt][3] + bval;
            *(float2*)(C + (size_t)gr1 * NCLASS + col) = o;
        }
    }
}

// ---------------------------------------------------------------------------
// CSR build: histogram -> 2-level exclusive scan -> scatter
// ---------------------------------------------------------------------------
__global__ void zero_counts_kernel()
{
    int i = blockIdx.x * blockDim.x + threadIdx.x;
    if (i < N_NODES) g_cnt[i] = 0;
}

__global__ void histogram_kernel(const int* __restrict__ row)
{
    int e = blockIdx.x * blockDim.x + threadIdx.x;
    if (e < E_EDGES) atomicAdd(&g_cnt[row[e]], 1);
}

__global__ void __launch_bounds__(SCAN_BLK) scan1_kernel()
{
    __shared__ int s[SCAN_BLK];
    int gid = blockIdx.x * SCAN_BLK + threadIdx.x;
    int x = (gid < N_NODES) ? g_cnt[gid] : 0;
    s[threadIdx.x] = x;
    __syncthreads();
    #pragma unroll
    for (int d = 1; d < SCAN_BLK; d <<= 1) {
        int t = (threadIdx.x >= d) ? s[threadIdx.x - d] : 0;
        __syncthreads();
        s[threadIdx.x] += t;
        __syncthreads();
    }
    if (gid < N_NODES) g_offl[gid] = s[threadIdx.x] - x;
    if (threadIdx.x == SCAN_BLK - 1) g_blk[blockIdx.x] = s[SCAN_BLK - 1];
}

__global__ void scan2_kernel()
{
    __shared__ int s[128];
    int tid = threadIdx.x;
    int x = (tid < NUM_SCAN_BLKS) ? g_blk[tid] : 0;
    s[tid] = x;
    __syncthreads();
    #pragma unroll
    for (int d = 1; d < 128; d <<= 1) {
        int t = (tid >= d) ? s[tid - d] : 0;
        __syncthreads();
        s[tid] += t;
        __syncthreads();
    }
    if (tid < NUM_SCAN_BLKS) g_blkoff[tid] = s[tid] - x;
}

__global__ void scan3_kernel()
{
    int i = blockIdx.x * blockDim.x + threadIdx.x;
    if (i < N_NODES) {
        int st = g_offl[i] + g_blkoff[i / SCAN_BLK];
        g_start[i]  = st;
        g_cursor[i] = st;
    }
    if (i == 0) g_start[N_NODES] = E_EDGES;
}

__global__ void scatter_kernel(const int* __restrict__ row,
                               const int* __restrict__ col,
                               const float* __restrict__ vals)
{
    int e = blockIdx.x * blockDim.x + threadIdx.x;
    if (e >= E_EDGES) return;
    int r = row[e];
    int pos = atomicAdd(&g_cursor[r], 1);
    int2 ev;
    ev.x = col[e];
    ev.y = __float_as_int((1.0f - ALPHA) * vals[e]);
    g_edges[pos] = ev;
}

// ---------------------------------------------------------------------------
// Pull-mode SpMM: 10 threads per row, one float4 segment per thread.
// ---------------------------------------------------------------------------
#define SPMM_TPB 320

__global__ void __launch_bounds__(SPMM_TPB) spmm_csr_kernel(
    const float* __restrict__ z,
    const float* __restrict__ h2,
    float* __restrict__ znew)
{
    int t = blockIdx.x * SPMM_TPB + threadIdx.x;
    int r   = t / 10;
    int seg = t - r * 10;
    if (r >= N_NODES) return;

    int e0 = g_start[r];
    int e1 = g_start[r + 1];

    float4 acc = make_float4(0.f, 0.f, 0.f, 0.f);

    int e = e0;
    for (; e + 2 <= e1; e += 2) {
        int2 ev0 = __ldg(&g_edges[e]);
        int2 ev1 = __ldg(&g_edges[e + 1]);
        float v0 = __int_as_float(ev0.y);
        float v1 = __int_as_float(ev1.y);
        float4 a0 = __ldg((const float4*)(z + (size_t)ev0.x * NCLASS) + seg);
        float4 a1 = __ldg((const float4*)(z + (size_t)ev1.x * NCLASS) + seg);
        acc.x += v0 * a0.x + v1 * a1.x;
        acc.y += v0 * a0.y + v1 * a1.y;
        acc.z += v0 * a0.z + v1 * a1.z;
        acc.w += v0 * a0.w + v1 * a1.w;
    }
    if (e < e1) {
        int2 ev = __ldg(&g_edges[e]);
        float v = __int_as_float(ev.y);
        float4 a = __ldg((const float4*)(z + (size_t)ev.x * NCLASS) + seg);
        acc.x += v * a.x;
        acc.y += v * a.y;
        acc.z += v * a.z;
        acc.w += v * a.w;
    }

    float4 hv = __ldg((const float4*)(h2 + (size_t)r * NCLASS) + seg);
    float4 o;
    o.x = acc.x + ALPHA * hv.x;
    o.y = acc.y + ALPHA * hv.y;
    o.z = acc.z + ALPHA * hv.z;
    o.w = acc.w + ALPHA * hv.w;
    ((float4*)(znew + (size_t)r * NCLASS))[seg] = o;
}

// ---------------------------------------------------------------------------
// Row-wise log_softmax over 40 classes: one warp per row
// ---------------------------------------------------------------------------
__global__ void logsoftmax_kernel(const float* __restrict__ z,
                                  float* __restrict__ out)
{
    int gtid = blockIdx.x * blockDim.x + threadIdx.x;
    int warp = gtid / 32;
    int lane = gtid % 32;
    if (warp >= N_NODES) return;

    const float* zr = z + (size_t)warp * NCLASS;
    float v0 = zr[lane];
    float v1 = (lane < NCLASS - 32) ? zr[lane + 32] : -INFINITY;

    float m = fmaxf(v0, v1);
    #pragma unroll
    for (int o = 16; o > 0; o >>= 1)
        m = fmaxf(m, __shfl_xor_sync(0xFFFFFFFFu, m, o));

    float s = expf(v0 - m) + ((lane < NCLASS - 32) ? expf(v1 - m) : 0.f);
    #pragma unroll
    for (int o = 16; o > 0; o >>= 1)
        s += __shfl_xor_sync(0xFFFFFFFFu, s, o);

    float L = m + logf(s);
    out[(size_t)warp * NCLASS + lane] = v0 - L;
    if (lane < NCLASS - 32)
        out[(size_t)warp * NCLASS + lane + 32] = v1 - L;
}

// ---------------------------------------------------------------------------
extern "C" void kernel_launch(void* const* d_in, const int* in_sizes, int n_in,
                              void* d_out, int out_size)
{
    const float* x    = (const float*)d_in[0];
    const int*   row  = (const int*)  d_in[1];
    const int*   col  = (const int*)  d_in[2];
    const float* vals = (const float*)d_in[3];
    const float* W1   = (const float*)d_in[4];
    const float* b1   = (const float*)d_in[5];
    const float* W2   = (const float*)d_in[6];
    const float* b2   = (const float*)d_in[7];
    float* out = (float*)d_out;

    float *h, *h2, *za, *zb;
    cudaGetSymbolAddress((void**)&h,  g_h);
    cudaGetSymbolAddress((void**)&h2, g_h2);
    cudaGetSymbolAddress((void**)&za, g_za);
    cudaGetSymbolAddress((void**)&zb, g_zb);

    cudaFuncSetAttribute(gemm1_mma_kernel,
                         cudaFuncAttributeMaxDynamicSharedMemorySize, G1_SMEM);
    cudaFuncSetAttribute(gemm2_mma_kernel,
                         cudaFuncAttributeMaxDynamicSharedMemorySize, G2_SMEM);

    // Launch order: gemm1 is our 4th launch (ncu profiles our #4).
    prep_w1t_kernel<<<(NHID * NFEAT + 255) / 256, 256>>>(W1);              // 1
    prep_w2t_kernel<<<(NCLASS * NHID + 255) / 256, 256>>>(W2);             // 2
    zero_counts_kernel<<<(N_NODES + 255) / 256, 256>>>();                  // 3
    gemm1_mma_kernel<<<(N_NODES + G1_BM - 1) / G1_BM, 256, G1_SMEM>>>(x, b1, h); // 4
    histogram_kernel<<<(E_EDGES + 255) / 256, 256>>>(row);                 // 5
    scan1_kernel<<<NUM_SCAN_BLKS, SCAN_BLK>>>();                           // 6
    scan2_kernel<<<1, 128>>>();                                            // 7
    scan3_kernel<<<(N_NODES + 255) / 256, 256>>>();                        // 8
    scatter_kernel<<<(E_EDGES + 255) / 256, 256>>>(row, col, vals);        // 9
    gemm2_mma_kernel<<<(N_NODES + 127) / 128, 256, G2_SMEM>>>(h, b2, h2);  // 10

    // APPNP propagation
    const int spmm_grid = (N_NODES * 10 + SPMM_TPB - 1) / SPMM_TPB;
    const float* zin = h2;
    float* bufs[2] = { za, zb };
    for (int it = 0; it < NLAYERS; it++) {
        float* zout = bufs[it & 1];
        spmm_csr_kernel<<<spmm_grid, SPMM_TPB>>>(zin, h2, zout);
        zin = zout;
    }

    logsoftmax_kernel<<<(N_NODES * 32 + 255) / 256, 256>>>(zin, out);
}

// round 10
// speedup vs baseline: 3.7138x; 1.1139x over previous
#include <cuda_runtime.h>
#include <cuda_fp16.h>
#include <math.h>
#include <stdint.h>

#define N_NODES 100000
#define E_EDGES 1600000
#define NFEAT   512
#define NHID    256
#define NCLASS  40
#define NLAYERS 10
#define ALPHA   0.1f

#define SCAN_BLK 1024
#define NUM_SCAN_BLKS ((N_NODES + SCAN_BLK - 1) / SCAN_BLK)   // 98

// Scratch (static device globals — allocation-free rule)
__device__ float g_h [N_NODES * NHID];    // relu(x@W1+b1)
__device__ float g_h2[N_NODES * NCLASS];  // h@W2+b2  (z_0)
__device__ float g_za[N_NODES * NCLASS];
__device__ float g_zb[N_NODES * NCLASS];

// W1 transposed, fp16: [NHID][NFEAT]
__device__ __half g_w1t[NHID * NFEAT];
// W2 transposed, fp16: [NCLASS][NHID]
__device__ __half g_w2t[NCLASS * NHID];

// CSR build scratch
__device__ int  g_cnt   [N_NODES];
__device__ int  g_offl  [N_NODES];
__device__ int  g_start [N_NODES + 1];
__device__ int  g_cursor[N_NODES];
__device__ int  g_blk   [NUM_SCAN_BLKS];
__device__ int  g_blkoff[NUM_SCAN_BLKS];
__device__ int2 g_edges [E_EDGES];

// ===========================================================================
// helpers (baseline PTX only: ldmatrix / mma.sync / cp.async)
// ===========================================================================
__device__ __forceinline__ uint32_t smem_u32(const void* p) {
    uint32_t a;
    asm("{ .reg .u64 t; cvta.to.shared.u64 t, %1; cvt.u32.u64 %0, t; }"
        : "=r"(a) : "l"(p));
    return a;
}

__device__ __forceinline__ void ldsm4(uint32_t addr, uint32_t* r) {
    asm volatile("ldmatrix.sync.aligned.m8n8.x4.shared.b16 {%0,%1,%2,%3}, [%4];"
        : "=r"(r[0]), "=r"(r[1]), "=r"(r[2]), "=r"(r[3]) : "r"(addr));
}

// fp16 MMA, fp32 accumulate
__device__ __forceinline__ void mma16816(float* c, const uint32_t* a,
                                         uint32_t b0, uint32_t b1) {
    asm volatile(
        "mma.sync.aligned.m16n8k16.row.col.f32.f16.f16.f32 "
        "{%0,%1,%2,%3}, {%4,%5,%6,%7}, {%8,%9}, {%0,%1,%2,%3};"
        : "+f"(c[0]), "+f"(c[1]), "+f"(c[2]), "+f"(c[3])
        : "r"(a[0]), "r"(a[1]), "r"(a[2]), "r"(a[3]), "r"(b0), "r"(b1));
}

__device__ __forceinline__ void cpasync16(uint32_t saddr, const void* gptr) {
    asm volatile("cp.async.cg.shared.global [%0], [%1], 16;"
                 :: "r"(saddr), "l"(gptr) : "memory");
}
#define CP_COMMIT() asm volatile("cp.async.commit_group;" ::: "memory")
#define CP_WAIT0()  asm volatile("cp.async.wait_group 0;" ::: "memory")

__device__ __forceinline__ uint32_t sw128(uint32_t off) {
    return off ^ ((off >> 3) & 0x70);
}

__device__ __forceinline__ uint32_t pack2h(float a, float b) {
    __half2 h = __floats2half2_rn(a, b);
    return *(uint32_t*)&h;
}

// ===========================================================================
// Prep: W1T / W2T fp16
// ===========================================================================
__global__ void prep_w1t_kernel(const float* __restrict__ W1)
{
    int i = blockIdx.x * blockDim.x + threadIdx.x;
    if (i >= NHID * NFEAT) return;
    int n = i / NFEAT, k = i % NFEAT;
    g_w1t[i] = __float2half(W1[(size_t)k * NHID + n]);
}

__global__ void prep_w2t_kernel(const float* __restrict__ W2)
{
    int i = blockIdx.x * blockDim.x + threadIdx.x;
    if (i >= NCLASS * NHID) return;
    int n = i / NHID, k = i % NHID;
    g_w2t[i] = __float2half(W2[(size_t)k * NCLASS + n]);
}

// ===========================================================================
// GEMM1 (mma.sync fp16 x fp16): h = relu(x @ W1 + b1)
// CTA 64x256, 256 threads / 8 warps (2m x 4n), warp tile 32x64.
// K staged at 32, double buffered, 2 CTAs/SM.
// ===========================================================================
#define G1_BM 64
#define G1_BN 256
#define G1_BK 32
#define G1_STAGES (NFEAT / G1_BK)      // 16
#define G1_A_OFF 0
#define G1_B_OFF 8192
#define G1_STAGE_BYTES 40960
#define G1_SMEM (2 * G1_STAGE_BYTES)   // 81920

__global__ void __launch_bounds__(256, 2) gemm1_mma_kernel(
    const float* __restrict__ A,
    const float* __restrict__ bias,
    float* __restrict__ C)
{
    extern __shared__ char smem[];
    const uint32_t sbase = smem_u32(smem);
    const int tid  = threadIdx.x;
    const int lane = tid & 31;
    const int wid  = tid >> 5;
    const int rowBase = blockIdx.x * G1_BM;

    const int warp_m = wid & 1;        // 0..1
    const int warp_n = wid >> 1;       // 0..3
    const int m0 = warp_m * 32;
    const int n0 = warp_n * 64;

    float acc[2][8][4];
    #pragma unroll
    for (int i = 0; i < 2; i++)
        #pragma unroll
        for (int j = 0; j < 8; j++)
            #pragma unroll
            for (int q = 0; q < 4; q++) acc[i][j][q] = 0.f;

    const int agr = tid >> 2;          // row 0..63
    const int akq = tid & 3;           // k-octet
    const int bkq = tid & 3;

    float a_st[8];

    auto ldgA = [&](int k0) {
        int gr = rowBase + agr;
        if (gr < N_NODES) {
            const float* p = A + (size_t)gr * NFEAT + k0 + akq * 8;
            float4 v0 = *(const float4*)p;
            float4 v1 = *(const float4*)(p + 4);
            a_st[0]=v0.x; a_st[1]=v0.y; a_st[2]=v0.z; a_st[3]=v0.w;
            a_st[4]=v1.x; a_st[5]=v1.y; a_st[6]=v1.z; a_st[7]=v1.w;
        } else {
            #pragma unroll
            for (int q = 0; q < 8; q++) a_st[q] = 0.f;
        }
    };
    auto cpB = [&](int k0, int stage) {
        uint32_t bb = sbase + stage * G1_STAGE_BYTES + G1_B_OFF;
        #pragma unroll
        for (int it = 0; it < 4; it++) {
            int n = (tid >> 2) + it * 64;          // 0..255
            size_t gi = (size_t)n * NFEAT + k0 + bkq * 8;
            uint32_t off = n * 128 + bkq * 16;
            cpasync16(bb + sw128(off), g_w1t + gi);
        }
        CP_COMMIT();
    };
    auto stsA = [&](int stage) {
        uint4 hq;
        hq.x = pack2h(a_st[0], a_st[1]);
        hq.y = pack2h(a_st[2], a_st[3]);
        hq.z = pack2h(a_st[4], a_st[5]);
        hq.w = pack2h(a_st[6], a_st[7]);
        uint32_t offh = agr * 128 + akq * 16;
        char* ab = smem + stage * G1_STAGE_BYTES + G1_A_OFF;
        *(uint4*)(ab + sw128(offh)) = hq;
    };

    auto compute = [&](int stage) {
        uint32_t ab = sbase + stage * G1_STAGE_BYTES + G1_A_OFF;
        uint32_t bb = sbase + stage * G1_STAGE_BYTES + G1_B_OFF;
        const int q  = lane >> 3;
        const int rr = lane & 7;
        #pragma unroll
        for (int k16 = 0; k16 < 2; k16++) {
            int cb = k16 * 2;
            uint32_t ah[2][4];
            #pragma unroll
            for (int mi = 0; mi < 2; mi++) {
                int row = m0 + mi * 16 + (q & 1) * 8 + rr;
                uint32_t offh = row * 128 + (cb + (q >> 1)) * 16;
                ldsm4(ab + sw128(offh), ah[mi]);
            }
            #pragma unroll
            for (int nj = 0; nj < 4; nj++) {
                uint32_t bh[4];
                int row = n0 + nj * 16 + (q & 1) * 8 + rr;
                uint32_t offh = row * 128 + (cb + (q >> 1)) * 16;
                ldsm4(bb + sw128(offh), bh);
                #pragma unroll
                for (int mi = 0; mi < 2; mi++)
                    #pragma unroll
                    for (int hh = 0; hh < 2; hh++) {
                        float* cc = acc[mi][nj * 2 + hh];
                        mma16816(cc, ah[mi], bh[hh], bh[2 + hh]);
                    }
            }
        }
    };

    ldgA(0); cpB(0, 0); stsA(0);
    CP_WAIT0();
    __syncthreads();

    for (int s = 0; s < G1_STAGES; s++) {
        if (s + 1 < G1_STAGES) {
            ldgA((s + 1) * G1_BK);
            cpB((s + 1) * G1_BK, (s + 1) & 1);
        }
        compute(s & 1);
        if (s + 1 < G1_STAGES) {
            stsA((s + 1) & 1);
            CP_WAIT0();
            __syncthreads();
        }
    }

    const float bval = bias[0];
    const int g  = lane >> 2;
    const int tq = lane & 3;
    #pragma unroll
    for (int mi = 0; mi < 2; mi++)
        #pragma unroll
        for (int nt = 0; nt < 8; nt++) {
            int row = m0 + mi * 16 + g;
            int col = n0 + nt * 8 + tq * 2;
            int gr0 = rowBase + row;
            int gr1 = gr0 + 8;
            float* cc = acc[mi][nt];
            if (gr0 < N_NODES) {
                float2 o;
                o.x = fmaxf(cc[0] + bval, 0.f);
                o.y = fmaxf(cc[1] + bval, 0.f);
                *(float2*)(C + (size_t)gr0 * NHID + col) = o;
            }
            if (gr1 < N_NODES) {
                float2 o;
                o.x = fmaxf(cc[2] + bval, 0.f);
                o.y = fmaxf(cc[3] + bval, 0.f);
                *(float2*)(C + (size_t)gr1 * NHID + col) = o;
            }
        }
}

// ===========================================================================
// GEMM2 (mma.sync fp16 x fp16): h2 = h @ W2 + b2
// ===========================================================================
#define G2_A_ST   16384
#define G2_W2_OFF 32768
#define G2_W2_CH  6144
#define G2_SMEM   (32768 + 8 * G2_W2_CH)   // 81920

__global__ void __launch_bounds__(256, 1) gemm2_mma_kernel(
    const float* __restrict__ A,      // g_h [N, 256]
    const float* __restrict__ bias,
    float* __restrict__ C)            // g_h2 [N, 40]
{
    extern __shared__ char smem[];
    const uint32_t sbase = smem_u32(smem);
    const int tid  = threadIdx.x;
    const int wid  = tid >> 5;
    const int lane = tid & 31;
    const int rowBase = blockIdx.x * 128;
    const int m0 = wid * 16;

    // async-load W2 chunk tiles (8 chunks x 40 rows x 4 segs x 16B)
    for (int idx = tid; idx < 8 * 40 * 4; idx += 256) {
        int ch  = idx / 160;
        int rem = idx - ch * 160;
        int n   = rem >> 2;
        int seg = rem & 3;
        const __half* src = g_w2t + (size_t)n * NHID + ch * 32 + seg * 8;
        uint32_t off = n * 128 + seg * 16;
        cpasync16(sbase + G2_W2_OFF + ch * G2_W2_CH + sw128(off), src);
    }
    CP_COMMIT();

    float acc[5][4];
    #pragma unroll
    for (int j = 0; j < 5; j++)
        #pragma unroll
        for (int q = 0; q < 4; q++) acc[j][q] = 0.f;

    float a_st[16];
    auto ldgA = [&](int k0) {
        #pragma unroll
        for (int it = 0; it < 2; it++) {
            int g  = tid + it * 256;
            int r  = g >> 2;
            int oq = g & 3;
            int gr = rowBase + r;
            if (gr < N_NODES) {
                const float* p = A + (size_t)gr * NHID + k0 + oq * 8;
                float4 v0 = *(const float4*)p;
                float4 v1 = *(const float4*)(p + 4);
                a_st[it*8+0]=v0.x; a_st[it*8+1]=v0.y; a_st[it*8+2]=v0.z; a_st[it*8+3]=v0.w;
                a_st[it*8+4]=v1.x; a_st[it*8+5]=v1.y; a_st[it*8+6]=v1.z; a_st[it*8+7]=v1.w;
            } else {
                #pragma unroll
                for (int q = 0; q < 8; q++) a_st[it*8+q] = 0.f;
            }
        }
    };
    auto stsA = [&](int stage) {
        #pragma unroll
        for (int it = 0; it < 2; it++) {
            int g  = tid + it * 256;
            int r  = g >> 2;
            int oq = g & 3;
            uint4 hq;
            hq.x = pack2h(a_st[it*8+0], a_st[it*8+1]);
            hq.y = pack2h(a_st[it*8+2], a_st[it*8+3]);
            hq.z = pack2h(a_st[it*8+4], a_st[it*8+5]);
            hq.w = pack2h(a_st[it*8+6], a_st[it*8+7]);
            uint32_t offh = r * 128 + oq * 16;
            char* ab = smem + stage * G2_A_ST;
            *(uint4*)(ab + sw128(offh)) = hq;
        }
    };

    auto compute = [&](int stage, int ch) {
        uint32_t ab = sbase + stage * G2_A_ST;
        uint32_t bb = sbase + G2_W2_OFF + ch * G2_W2_CH;
        const int q  = lane >> 3;
        const int rr = lane & 7;
        #pragma unroll
        for (int k16 = 0; k16 < 2; k16++) {
            int cb = k16 * 2;
            uint32_t ah[4];
            {
                int row = m0 + (q & 1) * 8 + rr;
                uint32_t offh = row * 128 + (cb + (q >> 1)) * 16;
                ldsm4(ab + sw128(offh), ah);
            }
            uint32_t bh[3][4];
            #pragma unroll
            for (int nj = 0; nj < 3; nj++) {
                int row = nj * 16 + (q & 1) * 8 + rr;
                uint32_t offh = row * 128 + (cb + (q >> 1)) * 16;
                ldsm4(bb + sw128(offh), bh[nj]);
            }
            #pragma unroll
            for (int nt = 0; nt < 5; nt++) {
                int nj = nt >> 1, hh = nt & 1;
                mma16816(acc[nt], ah, bh[nj][hh], bh[nj][2 + hh]);
            }
        }
    };

    ldgA(0); stsA(0);
    CP_WAIT0();
    __syncthreads();

    for (int ch = 0; ch < 8; ch++) {
        if (ch + 1 < 8) ldgA((ch + 1) * 32);
        compute(ch & 1, ch);
        if (ch + 1 < 8) {
            stsA((ch + 1) & 1);
            __syncthreads();
        }
    }

    const float bval = bias[0];
    const int g  = lane >> 2;
    const int tq = lane & 3;
    #pragma unroll
    for (int nt = 0; nt < 5; nt++) {
        int col = nt * 8 + tq * 2;
        int gr0 = rowBase + m0 + g;
        int gr1 = gr0 + 8;
        if (gr0 < N_NODES) {
            float2 o; o.x = acc[nt][0] + bval; o.y = acc[nt][1] + bval;
            *(float2*)(C + (size_t)gr0 * NCLASS + col) = o;
        }
        if (gr1 < N_NODES) {
            float2 o; o.x = acc[nt][2] + bval; o.y = acc[nt][3] + bval;
            *(float2*)(C + (size_t)gr1 * NCLASS + col) = o;
        }
    }
}

// ---------------------------------------------------------------------------
// CSR build: histogram -> 2-level exclusive scan -> scatter
// ---------------------------------------------------------------------------
__global__ void zero_counts_kernel()
{
    int i = blockIdx.x * blockDim.x + threadIdx.x;
    if (i < N_NODES) g_cnt[i] = 0;
}

__global__ void histogram_kernel(const int* __restrict__ row)
{
    int e = blockIdx.x * blockDim.x + threadIdx.x;
    if (e < E_EDGES) atomicAdd(&g_cnt[row[e]], 1);
}

__global__ void __launch_bounds__(SCAN_BLK) scan1_kernel()
{
    __shared__ int s[SCAN_BLK];
    int gid = blockIdx.x * SCAN_BLK + threadIdx.x;
    int x = (gid < N_NODES) ? g_cnt[gid] : 0;
    s[threadIdx.x] = x;
    __syncthreads();
    #pragma unroll
    for (int d = 1; d < SCAN_BLK; d <<= 1) {
        int t = (threadIdx.x >= d) ? s[threadIdx.x - d] : 0;
        __syncthreads();
        s[threadIdx.x] += t;
        __syncthreads();
    }
    if (gid < N_NODES) g_offl[gid] = s[threadIdx.x] - x;
    if (threadIdx.x == SCAN_BLK - 1) g_blk[blockIdx.x] = s[SCAN_BLK - 1];
}

__global__ void scan2_kernel()
{
    __shared__ int s[128];
    int tid = threadIdx.x;
    int x = (tid < NUM_SCAN_BLKS) ? g_blk[tid] : 0;
    s[tid] = x;
    __syncthreads();
    #pragma unroll
    for (int d = 1; d < 128; d <<= 1) {
        int t = (tid >= d) ? s[tid - d] : 0;
        __syncthreads();
        s[tid] += t;
        __syncthreads();
    }
    if (tid < NUM_SCAN_BLKS) g_blkoff[tid] = s[tid] - x;
}

__global__ void scan3_kernel()
{
    int i = blockIdx.x * blockDim.x + threadIdx.x;
    if (i < N_NODES) {
        int st = g_offl[i] + g_blkoff[i / SCAN_BLK];
        g_start[i]  = st;
        g_cursor[i] = st;
    }
    if (i == 0) g_start[N_NODES] = E_EDGES;
}

__global__ void scatter_kernel(const int* __restrict__ row,
                               const int* __restrict__ col,
                               const float* __restrict__ vals)
{
    int e = blockIdx.x * blockDim.x + threadIdx.x;
    if (e >= E_EDGES) return;
    int r = row[e];
    int pos = atomicAdd(&g_cursor[r], 1);
    int2 ev;
    ev.x = col[e];
    ev.y = __float_as_int((1.0f - ALPHA) * vals[e]);
    g_edges[pos] = ev;
}

// ---------------------------------------------------------------------------
// Pull-mode SpMM: 10 threads per row, one float4 segment per thread.
// ---------------------------------------------------------------------------
#define SPMM_TPB 320

__global__ void __launch_bounds__(SPMM_TPB) spmm_csr_kernel(
    const float* __restrict__ z,
    const float* __restrict__ h2,
    float* __restrict__ znew)
{
    int t = blockIdx.x * SPMM_TPB + threadIdx.x;
    int r   = t / 10;
    int seg = t - r * 10;
    if (r >= N_NODES) return;

    int e0 = g_start[r];
    int e1 = g_start[r + 1];

    float4 acc = make_float4(0.f, 0.f, 0.f, 0.f);

    int e = e0;
    for (; e + 2 <= e1; e += 2) {
        int2 ev0 = __ldg(&g_edges[e]);
        int2 ev1 = __ldg(&g_edges[e + 1]);
        float v0 = __int_as_float(ev0.y);
        float v1 = __int_as_float(ev1.y);
        float4 a0 = __ldg((const float4*)(z + (size_t)ev0.x * NCLASS) + seg);
        float4 a1 = __ldg((const float4*)(z + (size_t)ev1.x * NCLASS) + seg);
        acc.x += v0 * a0.x + v1 * a1.x;
        acc.y += v0 * a0.y + v1 * a1.y;
        acc.z += v0 * a0.z + v1 * a1.z;
        acc.w += v0 * a0.w + v1 * a1.w;
    }
    if (e < e1) {
        int2 ev = __ldg(&g_edges[e]);
        float v = __int_as_float(ev.y);
        float4 a = __ldg((const float4*)(z + (size_t)ev.x * NCLASS) + seg);
        acc.x += v * a.x;
        acc.y += v * a.y;
        acc.z += v * a.z;
        acc.w += v * a.w;
    }

    float4 hv = __ldg((const float4*)(h2 + (size_t)r * NCLASS) + seg);
    float4 o;
    o.x = acc.x + ALPHA * hv.x;
    o.y = acc.y + ALPHA * hv.y;
    o.z = acc.z + ALPHA * hv.z;
    o.w = acc.w + ALPHA * hv.w;
    ((float4*)(znew + (size_t)r * NCLASS))[seg] = o;
}

// ---------------------------------------------------------------------------
// Row-wise log_softmax over 40 classes: one warp per row
// ---------------------------------------------------------------------------
__global__ void logsoftmax_kernel(const float* __restrict__ z,
                                  float* __restrict__ out)
{
    int gtid = blockIdx.x * blockDim.x + threadIdx.x;
    int warp = gtid / 32;
    int lane = gtid % 32;
    if (warp >= N_NODES) return;

    const float* zr = z + (size_t)warp * NCLASS;
    float v0 = zr[lane];
    float v1 = (lane < NCLASS - 32) ? zr[lane + 32] : -INFINITY;

    float m = fmaxf(v0, v1);
    #pragma unroll
    for (int o = 16; o > 0; o >>= 1)
        m = fmaxf(m, __shfl_xor_sync(0xFFFFFFFFu, m, o));

    float s = expf(v0 - m) + ((lane < NCLASS - 32) ? expf(v1 - m) : 0.f);
    #pragma unroll
    for (int o = 16; o > 0; o >>= 1)
        s += __shfl_xor_sync(0xFFFFFFFFu, s, o);

    float L = m + logf(s);
    out[(size_t)warp * NCLASS + lane] = v0 - L;
    if (lane < NCLASS - 32)
        out[(size_t)warp * NCLASS + lane + 32] = v1 - L;
}

// ---------------------------------------------------------------------------
extern "C" void kernel_launch(void* const* d_in, const int* in_sizes, int n_in,
                              void* d_out, int out_size)
{
    const float* x    = (const float*)d_in[0];
    const int*   row  = (const int*)  d_in[1];
    const int*   col  = (const int*)  d_in[2];
    const float* vals = (const float*)d_in[3];
    const float* W1   = (const float*)d_in[4];
    const float* b1   = (const float*)d_in[5];
    const float* W2   = (const float*)d_in[6];
    const float* b2   = (const float*)d_in[7];
    float* out = (float*)d_out;

    float *h, *h2, *za, *zb;
    cudaGetSymbolAddress((void**)&h,  g_h);
    cudaGetSymbolAddress((void**)&h2, g_h2);
    cudaGetSymbolAddress((void**)&za, g_za);
    cudaGetSymbolAddress((void**)&zb, g_zb);

    cudaFuncSetAttribute(gemm1_mma_kernel,
                         cudaFuncAttributeMaxDynamicSharedMemorySize, G1_SMEM);
    cudaFuncSetAttribute(gemm2_mma_kernel,
                         cudaFuncAttributeMaxDynamicSharedMemorySize, G2_SMEM);

    // Launch order: gemm1 is our 4th launch (ncu profiles our #4).
    prep_w1t_kernel<<<(NHID * NFEAT + 255) / 256, 256>>>(W1);              // 1
    prep_w2t_kernel<<<(NCLASS * NHID + 255) / 256, 256>>>(W2);             // 2
    zero_counts_kernel<<<(N_NODES + 255) / 256, 256>>>();                  // 3
    gemm1_mma_kernel<<<(N_NODES + G1_BM - 1) / G1_BM, 256, G1_SMEM>>>(x, b1, h); // 4
    histogram_kernel<<<(E_EDGES + 255) / 256, 256>>>(row);                 // 5
    scan1_kernel<<<NUM_SCAN_BLKS, SCAN_BLK>>>();                           // 6
    scan2_kernel<<<1, 128>>>();                                            // 7
    scan3_kernel<<<(N_NODES + 255) / 256, 256>>>();                        // 8
    scatter_kernel<<<(E_EDGES + 255) / 256, 256>>>(row, col, vals);        // 9
    gemm2_mma_kernel<<<(N_NODES + 127) / 128, 256, G2_SMEM>>>(h, b2, h2);  // 10

    // APPNP propagation
    const int spmm_grid = (N_NODES * 10 + SPMM_TPB - 1) / SPMM_TPB;
    const float* zin = h2;
    float* bufs[2] = { za, zb };
    for (int it = 0; it < NLAYERS; it++) {
        float* zout = bufs[it & 1];
        spmm_csr_kernel<<<spmm_grid, SPMM_TPB>>>(zin, h2, zout);
        zin = zout;
    }

    logsoftmax_kernel<<<(N_NODES * 32 + 255) / 256, 256>>>(zin, out);
}

// round 11
// speedup vs baseline: 3.8548x; 1.0380x over previous
#include <cuda_runtime.h>
#include <cuda_fp16.h>
#include <math.h>
#include <stdint.h>

#define N_NODES 100000
#define E_EDGES 1600000
#define NFEAT   512
#define NHID    256
#define NCLASS  40
#define NLAYERS 10
#define ALPHA   0.1f

#define SCAN_BLK 1024
#define NUM_SCAN_BLKS ((N_NODES + SCAN_BLK - 1) / SCAN_BLK)   // 98

// Scratch (static device globals — allocation-free rule)
__device__ __half g_hh[N_NODES * NHID];   // fp16 relu(x@W1+b1)
__device__ float g_h2[N_NODES * NCLASS];  // h@W2+b2  (z_0)
__device__ float g_za[N_NODES * NCLASS];
__device__ float g_zb[N_NODES * NCLASS];

// W1 transposed, fp16: [NHID][NFEAT]
__device__ __half g_w1t[NHID * NFEAT];
// W2 transposed, fp16: [NCLASS][NHID]
__device__ __half g_w2t[NCLASS * NHID];

// CSR build scratch
__device__ int  g_cnt   [N_NODES];
__device__ int  g_offl  [N_NODES];
__device__ int  g_start [N_NODES + 1];
__device__ int  g_cursor[N_NODES];
__device__ int  g_blk   [NUM_SCAN_BLKS];
__device__ int  g_blkoff[NUM_SCAN_BLKS];
__device__ int2 g_edges [E_EDGES];

// ===========================================================================
// helpers (baseline PTX only: ldmatrix / mma.sync / cp.async)
// ===========================================================================
__device__ __forceinline__ uint32_t smem_u32(const void* p) {
    uint32_t a;
    asm("{ .reg .u64 t; cvta.to.shared.u64 t, %1; cvt.u32.u64 %0, t; }"
        : "=r"(a) : "l"(p));
    return a;
}

__device__ __forceinline__ void ldsm4(uint32_t addr, uint32_t* r) {
    asm volatile("ldmatrix.sync.aligned.m8n8.x4.shared.b16 {%0,%1,%2,%3}, [%4];"
        : "=r"(r[0]), "=r"(r[1]), "=r"(r[2]), "=r"(r[3]) : "r"(addr));
}

// fp16 MMA, fp32 accumulate
__device__ __forceinline__ void mma16816(float* c, const uint32_t* a,
                                         uint32_t b0, uint32_t b1) {
    asm volatile(
        "mma.sync.aligned.m16n8k16.row.col.f32.f16.f16.f32 "
        "{%0,%1,%2,%3}, {%4,%5,%6,%7}, {%8,%9}, {%0,%1,%2,%3};"
        : "+f"(c[0]), "+f"(c[1]), "+f"(c[2]), "+f"(c[3])
        : "r"(a[0]), "r"(a[1]), "r"(a[2]), "r"(a[3]), "r"(b0), "r"(b1));
}

__device__ __forceinline__ void cpasync16(uint32_t saddr, const void* gptr) {
    asm volatile("cp.async.cg.shared.global [%0], [%1], 16;"
                 :: "r"(saddr), "l"(gptr) : "memory");
}
#define CP_COMMIT() asm volatile("cp.async.commit_group;" ::: "memory")
#define CP_WAIT0()  asm volatile("cp.async.wait_group 0;" ::: "memory")

__device__ __forceinline__ uint32_t sw128(uint32_t off) {
    return off ^ ((off >> 3) & 0x70);
}

__device__ __forceinline__ uint32_t pack2h(float a, float b) {
    __half2 h = __floats2half2_rn(a, b);
    return *(uint32_t*)&h;
}

// ===========================================================================
// Prep: W1T / W2T fp16
// ===========================================================================
__global__ void prep_w1t_kernel(const float* __restrict__ W1)
{
    int i = blockIdx.x * blockDim.x + threadIdx.x;
    if (i >= NHID * NFEAT) return;
    int n = i / NFEAT, k = i % NFEAT;
    g_w1t[i] = __float2half(W1[(size_t)k * NHID + n]);
}

__global__ void prep_w2t_kernel(const float* __restrict__ W2)
{
    int i = blockIdx.x * blockDim.x + threadIdx.x;
    if (i >= NCLASS * NHID) return;
    int n = i / NHID, k = i % NHID;
    g_w2t[i] = __float2half(W2[(size_t)k * NCLASS + n]);
}

// ===========================================================================
// GEMM1 (mma.sync fp16 x fp16): h = relu(x @ W1 + b1), output fp16
// CTA 64x256, 256 threads / 8 warps (2m x 4n), warp tile 32x64.
// K staged at 64 (full 128B smem rows), double buffered, 2 CTAs/SM.
// ===========================================================================
#define G1_BM 64
#define G1_BN 256
#define G1_BK 64
#define G1_STAGES (NFEAT / G1_BK)      // 8
#define G1_A_OFF 0
#define G1_B_OFF 8192
#define G1_STAGE_BYTES 40960           // 8KB A + 32KB B
#define G1_SMEM (2 * G1_STAGE_BYTES)   // 81920

__global__ void __launch_bounds__(256, 2) gemm1_mma_kernel(
    const float* __restrict__ A,
    const float* __restrict__ bias,
    __half* __restrict__ C)
{
    extern __shared__ char smem[];
    const uint32_t sbase = smem_u32(smem);
    const int tid  = threadIdx.x;
    const int lane = tid & 31;
    const int wid  = tid >> 5;
    const int rowBase = blockIdx.x * G1_BM;

    const int warp_m = wid & 1;        // 0..1
    const int warp_n = wid >> 1;       // 0..3
    const int m0 = warp_m * 32;
    const int n0 = warp_n * 64;

    float acc[2][8][4];
    #pragma unroll
    for (int i = 0; i < 2; i++)
        #pragma unroll
        for (int j = 0; j < 8; j++)
            #pragma unroll
            for (int q = 0; q < 4; q++) acc[i][j][q] = 0.f;

    const int agr = tid >> 2;          // row 0..63
    const int aoq = tid & 3;           // 16-float group within k64

    float a_st[16];

    auto ldgA = [&](int k0) {
        int gr = rowBase + agr;
        if (gr < N_NODES) {
            const float* p = A + (size_t)gr * NFEAT + k0 + aoq * 16;
            #pragma unroll
            for (int v = 0; v < 4; v++) {
                float4 t = *(const float4*)(p + v * 4);
                a_st[v*4+0]=t.x; a_st[v*4+1]=t.y; a_st[v*4+2]=t.z; a_st[v*4+3]=t.w;
            }
        } else {
            #pragma unroll
            for (int q = 0; q < 16; q++) a_st[q] = 0.f;
        }
    };
    auto cpB = [&](int k0, int stage) {
        uint32_t bb = sbase + stage * G1_STAGE_BYTES + G1_B_OFF;
        #pragma unroll
        for (int it = 0; it < 8; it++) {
            int s = tid + it * 256;            // 0..2047
            int n   = s >> 3;                  // 0..255
            int seg = s & 7;
            size_t gi = (size_t)n * NFEAT + k0 + seg * 8;
            uint32_t off = n * 128 + seg * 16;
            cpasync16(bb + sw128(off), g_w1t + gi);
        }
        CP_COMMIT();
    };
    auto stsA = [&](int stage) {
        uint4 q0, q1;
        q0.x = pack2h(a_st[0],  a_st[1]);
        q0.y = pack2h(a_st[2],  a_st[3]);
        q0.z = pack2h(a_st[4],  a_st[5]);
        q0.w = pack2h(a_st[6],  a_st[7]);
        q1.x = pack2h(a_st[8],  a_st[9]);
        q1.y = pack2h(a_st[10], a_st[11]);
        q1.z = pack2h(a_st[12], a_st[13]);
        q1.w = pack2h(a_st[14], a_st[15]);
        uint32_t offh = agr * 128 + aoq * 32;
        char* ab = smem + stage * G1_STAGE_BYTES + G1_A_OFF;
        *(uint4*)(ab + sw128(offh))      = q0;
        *(uint4*)(ab + sw128(offh + 16)) = q1;
    };

    auto compute = [&](int stage) {
        uint32_t ab = sbase + stage * G1_STAGE_BYTES + G1_A_OFF;
        uint32_t bb = sbase + stage * G1_STAGE_BYTES + G1_B_OFF;
        const int q  = lane >> 3;
        const int rr = lane & 7;
        #pragma unroll
        for (int k16 = 0; k16 < 4; k16++) {
            int cb = k16 * 2;
            uint32_t ah[2][4];
            #pragma unroll
            for (int mi = 0; mi < 2; mi++) {
                int row = m0 + mi * 16 + (q & 1) * 8 + rr;
                uint32_t offh = row * 128 + (cb + (q >> 1)) * 16;
                ldsm4(ab + sw128(offh), ah[mi]);
            }
            #pragma unroll
            for (int nj = 0; nj < 4; nj++) {
                uint32_t bh[4];
                int row = n0 + nj * 16 + (q & 1) * 8 + rr;
                uint32_t offh = row * 128 + (cb + (q >> 1)) * 16;
                ldsm4(bb + sw128(offh), bh);
                #pragma unroll
                for (int mi = 0; mi < 2; mi++)
                    #pragma unroll
                    for (int hh = 0; hh < 2; hh++) {
                        float* cc = acc[mi][nj * 2 + hh];
                        mma16816(cc, ah[mi], bh[hh], bh[2 + hh]);
                    }
            }
        }
    };

    ldgA(0); cpB(0, 0); stsA(0);
    CP_WAIT0();
    __syncthreads();

    for (int s = 0; s < G1_STAGES; s++) {
        if (s + 1 < G1_STAGES) {
            ldgA((s + 1) * G1_BK);
            cpB((s + 1) * G1_BK, (s + 1) & 1);
        }
        compute(s & 1);
        if (s + 1 < G1_STAGES) {
            stsA((s + 1) & 1);
            CP_WAIT0();
            __syncthreads();
        }
    }

    const float bval = bias[0];
    const int g  = lane >> 2;
    const int tq = lane & 3;
    #pragma unroll
    for (int mi = 0; mi < 2; mi++)
        #pragma unroll
        for (int nt = 0; nt < 8; nt++) {
            int row = m0 + mi * 16 + g;
            int col = n0 + nt * 8 + tq * 2;
            int gr0 = rowBase + row;
            int gr1 = gr0 + 8;
            float* cc = acc[mi][nt];
            if (gr0 < N_NODES) {
                uint32_t o = pack2h(fmaxf(cc[0] + bval, 0.f),
                                    fmaxf(cc[1] + bval, 0.f));
                *(uint32_t*)(C + (size_t)gr0 * NHID + col) = o;
            }
            if (gr1 < N_NODES) {
                uint32_t o = pack2h(fmaxf(cc[2] + bval, 0.f),
                                    fmaxf(cc[3] + bval, 0.f));
                *(uint32_t*)(C + (size_t)gr1 * NHID + col) = o;
            }
        }
}

// ===========================================================================
// GEMM2 (mma.sync fp16 x fp16): h2 = h @ W2 + b2
// A (fp16 h) loaded directly via cp.async. CTA 128 rows, 8 warps x 16 rows.
// K = 256 in 4 k64 chunks; W2 chunks smem-resident; A double-buffered.
// ===========================================================================
#define G2_A_ST   16384                 // 128 rows x 128B
#define G2_W2_OFF 32768
#define G2_W2_CH  6144                  // 48 rows x 128B (40 used, pad for ldsm)
#define G2_SMEM   (32768 + 4 * G2_W2_CH)   // 57344

__global__ void __launch_bounds__(256, 1) gemm2_mma_kernel(
    const __half* __restrict__ A,     // g_hh [N, 256]
    const float* __restrict__ bias,
    float* __restrict__ C)            // g_h2 [N, 40]
{
    extern __shared__ char smem[];
    const uint32_t sbase = smem_u32(smem);
    const int tid  = threadIdx.x;
    const int wid  = tid >> 5;
    const int lane = tid & 31;
    const int rowBase = blockIdx.x * 128;
    const int m0 = wid * 16;

    // async-load W2 chunk tiles (4 chunks x 40 rows x 8 segs x 16B)
    for (int idx = tid; idx < 4 * 40 * 8; idx += 256) {
        int ch  = idx / 320;
        int rem = idx - ch * 320;
        int n   = rem >> 3;
        int seg = rem & 7;
        const __half* src = g_w2t + (size_t)n * NHID + ch * 64 + seg * 8;
        uint32_t off = n * 128 + seg * 16;
        cpasync16(sbase + G2_W2_OFF + ch * G2_W2_CH + sw128(off), src);
    }
    CP_COMMIT();

    float acc[5][4];
    #pragma unroll
    for (int j = 0; j < 5; j++)
        #pragma unroll
        for (int q = 0; q < 4; q++) acc[j][q] = 0.f;

    auto cpA = [&](int k0, int stage) {
        uint32_t ab = sbase + stage * G2_A_ST;
        #pragma unroll
        for (int it = 0; it < 4; it++) {
            int s = tid + it * 256;          // 0..1023
            int r   = s >> 3;                // 0..127
            int seg = s & 7;
            int gr = rowBase + r;
            if (gr >= N_NODES) gr = N_NODES - 1;   // clamp (rows unwritten anyway)
            const __half* src = A + (size_t)gr * NHID + k0 + seg * 8;
            uint32_t off = r * 128 + seg * 16;
            cpasync16(ab + sw128(off), src);
        }
        CP_COMMIT();
    };

    auto compute = [&](int stage, int ch) {
        uint32_t ab = sbase + stage * G2_A_ST;
        uint32_t bb = sbase + G2_W2_OFF + ch * G2_W2_CH;
        const int q  = lane >> 3;
        const int rr = lane & 7;
        #pragma unroll
        for (int k16 = 0; k16 < 4; k16++) {
            int cb = k16 * 2;
            uint32_t ah[4];
            {
                int row = m0 + (q & 1) * 8 + rr;
                uint32_t offh = row * 128 + (cb + (q >> 1)) * 16;
                ldsm4(ab + sw128(offh), ah);
            }
            uint32_t bh[3][4];
            #pragma unroll
            for (int nj = 0; nj < 3; nj++) {
                int row = nj * 16 + (q & 1) * 8 + rr;
                uint32_t offh = row * 128 + (cb + (q >> 1)) * 16;
                ldsm4(bb + sw128(offh), bh[nj]);
            }
            #pragma unroll
            for (int nt = 0; nt < 5; nt++) {
                int nj = nt >> 1, hh = nt & 1;
                mma16816(acc[nt], ah, bh[nj][hh], bh[nj][2 + hh]);
            }
        }
    };

    cpA(0, 0);
    CP_WAIT0();        // waits W2 tiles + first A stage
    __syncthreads();

    for (int ch = 0; ch < 4; ch++) {
        if (ch + 1 < 4) cpA((ch + 1) * 64, (ch + 1) & 1);
        compute(ch & 1, ch);
        if (ch + 1 < 4) {
            CP_WAIT0();
            __syncthreads();
        }
    }

    const float bval = bias[0];
    const int g  = lane >> 2;
    const int tq = lane & 3;
    #pragma unroll
    for (int nt = 0; nt < 5; nt++) {
        int col = nt * 8 + tq * 2;
        int gr0 = rowBase + m0 + g;
        int gr1 = gr0 + 8;
        if (gr0 < N_NODES) {
            float2 o; o.x = acc[nt][0] + bval; o.y = acc[nt][1] + bval;
            *(float2*)(C + (size_t)gr0 * NCLASS + col) = o;
        }
        if (gr1 < N_NODES) {
            float2 o; o.x = acc[nt][2] + bval; o.y = acc[nt][3] + bval;
            *(float2*)(C + (size_t)gr1 * NCLASS + col) = o;
        }
    }
}

// ---------------------------------------------------------------------------
// CSR build: histogram -> 2-level exclusive scan -> scatter
// ---------------------------------------------------------------------------
__global__ void zero_counts_kernel()
{
    int i = blockIdx.x * blockDim.x + threadIdx.x;
    if (i < N_NODES) g_cnt[i] = 0;
}

__global__ void histogram_kernel(const int* __restrict__ row)
{
    int e = blockIdx.x * blockDim.x + threadIdx.x;
    if (e < E_EDGES) atomicAdd(&g_cnt[row[e]], 1);
}

__global__ void __launch_bounds__(SCAN_BLK) scan1_kernel()
{
    __shared__ int s[SCAN_BLK];
    int gid = blockIdx.x * SCAN_BLK + threadIdx.x;
    int x = (gid < N_NODES) ? g_cnt[gid] : 0;
    s[threadIdx.x] = x;
    __syncthreads();
    #pragma unroll
    for (int d = 1; d < SCAN_BLK; d <<= 1) {
        int t = (threadIdx.x >= d) ? s[threadIdx.x - d] : 0;
        __syncthreads();
        s[threadIdx.x] += t;
        __syncthreads();
    }
    if (gid < N_NODES) g_offl[gid] = s[threadIdx.x] - x;
    if (threadIdx.x == SCAN_BLK - 1) g_blk[blockIdx.x] = s[SCAN_BLK - 1];
}

__global__ void scan2_kernel()
{
    __shared__ int s[128];
    int tid = threadIdx.x;
    int x = (tid < NUM_SCAN_BLKS) ? g_blk[tid] : 0;
    s[tid] = x;
    __syncthreads();
    #pragma unroll
    for (int d = 1; d < 128; d <<= 1) {
        int t = (tid >= d) ? s[tid - d] : 0;
        __syncthreads();
        s[tid] += t;
        __syncthreads();
    }
    if (tid < NUM_SCAN_BLKS) g_blkoff[tid] = s[tid] - x;
}

__global__ void scan3_kernel()
{
    int i = blockIdx.x * blockDim.x + threadIdx.x;
    if (i < N_NODES) {
        int st = g_offl[i] + g_blkoff[i / SCAN_BLK];
        g_start[i]  = st;
        g_cursor[i] = st;
    }
    if (i == 0) g_start[N_NODES] = E_EDGES;
}

__global__ void scatter_kernel(const int* __restrict__ row,
                               const int* __restrict__ col,
                               const float* __restrict__ vals)
{
    int e = blockIdx.x * blockDim.x + threadIdx.x;
    if (e >= E_EDGES) return;
    int r = row[e];
    int pos = atomicAdd(&g_cursor[r], 1);
    int2 ev;
    ev.x = col[e];
    ev.y = __float_as_int((1.0f - ALPHA) * vals[e]);
    g_edges[pos] = ev;
}

// ---------------------------------------------------------------------------
// Pull-mode SpMM: 10 threads per row, one float4 segment per thread.
// ---------------------------------------------------------------------------
#define SPMM_TPB 320

__global__ void __launch_bounds__(SPMM_TPB) spmm_csr_kernel(
    const float* __restrict__ z,
    const float* __restrict__ h2,
    float* __restrict__ znew)
{
    int t = blockIdx.x * SPMM_TPB + threadIdx.x;
    int r   = t / 10;
    int seg = t - r * 10;
    if (r >= N_NODES) return;

    int e0 = g_start[r];
    int e1 = g_start[r + 1];

    float4 acc = make_float4(0.f, 0.f, 0.f, 0.f);

    int e = e0;
    for (; e + 2 <= e1; e += 2) {
        int2 ev0 = __ldg(&g_edges[e]);
        int2 ev1 = __ldg(&g_edges[e + 1]);
        float v0 = __int_as_float(ev0.y);
        float v1 = __int_as_float(ev1.y);
        float4 a0 = __ldg((const float4*)(z + (size_t)ev0.x * NCLASS) + seg);
        float4 a1 = __ldg((const float4*)(z + (size_t)ev1.x * NCLASS) + seg);
        acc.x += v0 * a0.x + v1 * a1.x;
        acc.y += v0 * a0.y + v1 * a1.y;
        acc.z += v0 * a0.z + v1 * a1.z;
        acc.w += v0 * a0.w + v1 * a1.w;
    }
    if (e < e1) {
        int2 ev = __ldg(&g_edges[e]);
        float v = __int_as_float(ev.y);
        float4 a = __ldg((const float4*)(z + (size_t)ev.x * NCLASS) + seg);
        acc.x += v * a.x;
        acc.y += v * a.y;
        acc.z += v * a.z;
        acc.w += v * a.w;
    }

    float4 hv = __ldg((const float4*)(h2 + (size_t)r * NCLASS) + seg);
    float4 o;
    o.x = acc.x + ALPHA * hv.x;
    o.y = acc.y + ALPHA * hv.y;
    o.z = acc.z + ALPHA * hv.z;
    o.w = acc.w + ALPHA * hv.w;
    ((float4*)(znew + (size_t)r * NCLASS))[seg] = o;
}

// ---------------------------------------------------------------------------
// Row-wise log_softmax over 40 classes: one warp per row
// ---------------------------------------------------------------------------
__global__ void logsoftmax_kernel(const float* __restrict__ z,
                                  float* __restrict__ out)
{
    int gtid = blockIdx.x * blockDim.x + threadIdx.x;
    int warp = gtid / 32;
    int lane = gtid % 32;
    if (warp >= N_NODES) return;

    const float* zr = z + (size_t)warp * NCLASS;
    float v0 = zr[lane];
    float v1 = (lane < NCLASS - 32) ? zr[lane + 32] : -INFINITY;

    float m = fmaxf(v0, v1);
    #pragma unroll
    for (int o = 16; o > 0; o >>= 1)
        m = fmaxf(m, __shfl_xor_sync(0xFFFFFFFFu, m, o));

    float s = expf(v0 - m) + ((lane < NCLASS - 32) ? expf(v1 - m) : 0.f);
    #pragma unroll
    for (int o = 16; o > 0; o >>= 1)
        s += __shfl_xor_sync(0xFFFFFFFFu, s, o);

    float L = m + logf(s);
    out[(size_t)warp * NCLASS + lane] = v0 - L;
    if (lane < NCLASS - 32)
        out[(size_t)warp * NCLASS + lane + 32] = v1 - L;
}

// ---------------------------------------------------------------------------
extern "C" void kernel_launch(void* const* d_in, const int* in_sizes, int n_in,
                              void* d_out, int out_size)
{
    const float* x    = (const float*)d_in[0];
    const int*   row  = (const int*)  d_in[1];
    const int*   col  = (const int*)  d_in[2];
    const float* vals = (const float*)d_in[3];
    const float* W1   = (const float*)d_in[4];
    const float* b1   = (const float*)d_in[5];
    const float* W2   = (const float*)d_in[6];
    const float* b2   = (const float*)d_in[7];
    float* out = (float*)d_out;

    __half* hh;
    float *h2, *za, *zb;
    cudaGetSymbolAddress((void**)&hh, g_hh);
    cudaGetSymbolAddress((void**)&h2, g_h2);
    cudaGetSymbolAddress((void**)&za, g_za);
    cudaGetSymbolAddress((void**)&zb, g_zb);

    cudaFuncSetAttribute(gemm1_mma_kernel,
                         cudaFuncAttributeMaxDynamicSharedMemorySize, G1_SMEM);
    cudaFuncSetAttribute(gemm2_mma_kernel,
                         cudaFuncAttributeMaxDynamicSharedMemorySize, G2_SMEM);

    // Launch order: gemm1 is our 4th launch (ncu profiles our #4).
    prep_w1t_kernel<<<(NHID * NFEAT + 255) / 256, 256>>>(W1);              // 1
    prep_w2t_kernel<<<(NCLASS * NHID + 255) / 256, 256>>>(W2);             // 2
    zero_counts_kernel<<<(N_NODES + 255) / 256, 256>>>();                  // 3
    gemm1_mma_kernel<<<(N_NODES + G1_BM - 1) / G1_BM, 256, G1_SMEM>>>(x, b1, hh); // 4
    histogram_kernel<<<(E_EDGES + 255) / 256, 256>>>(row);                 // 5
    scan1_kernel<<<NUM_SCAN_BLKS, SCAN_BLK>>>();                           // 6
    scan2_kernel<<<1, 128>>>();                                            // 7
    scan3_kernel<<<(N_NODES + 255) / 256, 256>>>();                        // 8
    scatter_kernel<<<(E_EDGES + 255) / 256, 256>>>(row, col, vals);        // 9
    gemm2_mma_kernel<<<(N_NODES + 127) / 128, 256, G2_SMEM>>>(hh, b2, h2); // 10

    // APPNP propagation
    const int spmm_grid = (N_NODES * 10 + SPMM_TPB - 1) / SPMM_TPB;
    const float* zin = h2;
    float* bufs[2] = { za, zb };
    for (int it = 0; it < NLAYERS; it++) {
        float* zout = bufs[it & 1];
        spmm_csr_kernel<<<spmm_grid, SPMM_TPB>>>(zin, h2, zout);
        zin = zout;
    }

    logsoftmax_kernel<<<(N_NODES * 32 + 255) / 256, 256>>>(zin, out);
}